// round 5
// baseline (speedup 1.0000x reference)
#include <cuda_runtime.h>
#include <cuda_bf16.h>
#include <math.h>
#include <stdint.h>

#define NN 4096
#define BB 64
#define DIN 64
#define DH 64
#define CC 128              // DIN + DH
#define EE 16
#define XGPITCH (BB * CC)   // 8192

// ================= device scratch (no runtime allocs) ==========================
__device__ __nv_bfloat16 g_Shi[(size_t)NN * NN];     // 32 MB supports hi (A operand)
__device__ __nv_bfloat16 g_Slo[(size_t)NN * NN];     // 32 MB supports lo
__device__ __nv_bfloat16 g_BXhi[(size_t)NN * NN];    // 32 MB x^T hi    [j=b*64+c][m]
__device__ __nv_bfloat16 g_BXlo[(size_t)NN * NN];    // 32 MB x^T lo
__device__ __nv_bfloat16 g_BShi[(size_t)NN * NN];    // 32 MB state^T / (z*state)^T hi
__device__ __nv_bfloat16 g_BSlo[(size_t)NN * NN];    // 32 MB
__device__ float g_XG[(size_t)NN * XGPITCH];         // 128 MB [n][b][128]
__device__ float g_W[(size_t)NN * CC * CC];          // 256 MB per-node weights
__device__ float g_BIAS[(size_t)NN * CC];            // 2 MB
__device__ float g_ZR[(size_t)NN * XGPITCH];         // 128 MB z_r [n][b*128+j]

// ================= PTX helpers (sm_80-level only; NO tcgen05) ====================
__device__ __forceinline__ uint32_t smem_u32(const void* p) {
    uint32_t a;
    asm("{ .reg .u64 t; cvta.to.shared.u64 t, %1; cvt.u32.u64 %0, t; }" : "=r"(a) : "l"(p));
    return a;
}
__device__ __forceinline__ void cpa16(uint32_t dst, const void* src) {
    asm volatile("cp.async.cg.shared.global [%0], [%1], 16;" :: "r"(dst), "l"(src));
}
#define CP_COMMIT() asm volatile("cp.async.commit_group;" ::: "memory")
#define CP_WAIT1()  asm volatile("cp.async.wait_group 1;" ::: "memory")

#define LDSM4(r0, r1, r2, r3, addr) \
    asm volatile("ldmatrix.sync.aligned.m8n8.x4.shared.b16 {%0,%1,%2,%3}, [%4];" \
        : "=r"(r0), "=r"(r1), "=r"(r2), "=r"(r3) : "r"(addr))

#define MMA_BF16(c, a, b) \
    asm volatile("mma.sync.aligned.m16n8k16.row.col.f32.bf16.bf16.f32 " \
        "{%0,%1,%2,%3}, {%4,%5,%6,%7}, {%8,%9}, {%0,%1,%2,%3};" \
        : "+f"((c)[0]), "+f"((c)[1]), "+f"((c)[2]), "+f"((c)[3]) \
        : "r"((a)[0]), "r"((a)[1]), "r"((a)[2]), "r"((a)[3]), \
          "r"((b)[0]), "r"((b)[1]))

// ================ supports = softmax(relu(NE @ NE^T)) -> bf16 hi/lo ==============
__global__ __launch_bounds__(256) void k_supports(const float* __restrict__ ne) {
    int n = blockIdx.x, tid = threadIdx.x;
    __shared__ float e[EE];
    __shared__ float redm[8], reds[8];
    if (tid < EE) e[tid] = ne[n * EE + tid];
    __syncthreads();

    float vals[16];
    float mx = 0.0f;
    #pragma unroll
    for (int j = 0; j < 16; j++) {
        int m = tid + j * 256;
        const float4* p = reinterpret_cast<const float4*>(ne + m * EE);
        float4 v0 = p[0], v1 = p[1], v2 = p[2], v3 = p[3];
        float d = e[0]*v0.x + e[1]*v0.y + e[2]*v0.z + e[3]*v0.w
                + e[4]*v1.x + e[5]*v1.y + e[6]*v1.z + e[7]*v1.w
                + e[8]*v2.x + e[9]*v2.y + e[10]*v2.z + e[11]*v2.w
                + e[12]*v3.x + e[13]*v3.y + e[14]*v3.z + e[15]*v3.w;
        d = fmaxf(d, 0.0f);
        vals[j] = d;
        mx = fmaxf(mx, d);
    }
    #pragma unroll
    for (int o = 16; o > 0; o >>= 1) mx = fmaxf(mx, __shfl_xor_sync(0xffffffffu, mx, o));
    if ((tid & 31) == 0) redm[tid >> 5] = mx;
    __syncthreads();
    mx = redm[0];
    #pragma unroll
    for (int w = 1; w < 8; w++) mx = fmaxf(mx, redm[w]);

    float s = 0.0f;
    #pragma unroll
    for (int j = 0; j < 16; j++) { vals[j] = __expf(vals[j] - mx); s += vals[j]; }
    #pragma unroll
    for (int o = 16; o > 0; o >>= 1) s += __shfl_xor_sync(0xffffffffu, s, o);
    if ((tid & 31) == 0) reds[tid >> 5] = s;
    __syncthreads();
    s = 0.0f;
    #pragma unroll
    for (int w = 0; w < 8; w++) s += reds[w];
    float inv = 1.0f / s;
    #pragma unroll
    for (int j = 0; j < 16; j++) {
        float v = vals[j] * inv;
        __nv_bfloat16 h = __float2bfloat16(v);
        size_t o = (size_t)n * NN + tid + j * 256;
        g_Shi[o] = h;
        g_Slo[o] = __float2bfloat16(v - __bfloat162float(h));
    }
}

// ================ per-node weights / bias ========================================
__global__ __launch_bounds__(256) void k_mkweights(const float* __restrict__ ne,
                                                   const float* __restrict__ wp,
                                                   int IO) {
    int io = blockIdx.x * 256 + threadIdx.x;
    float wv[EE];
    #pragma unroll
    for (int d = 0; d < EE; d++) wv[d] = wp[(size_t)d * IO + io];
    __shared__ float sne[128 * EE];
    for (int n0 = 0; n0 < NN; n0 += 128) {
        __syncthreads();
        for (int t = threadIdx.x; t < 128 * EE; t += 256) sne[t] = ne[n0 * EE + t];
        __syncthreads();
        for (int nn = 0; nn < 128; nn++) {
            float v = 0.0f;
            #pragma unroll
            for (int d = 0; d < EE; d++) v += sne[nn * EE + d] * wv[d];
            g_W[(size_t)(n0 + nn) * IO + io] = v;
        }
    }
}

__global__ void k_bias(const float* __restrict__ ne, const float* __restrict__ bp, int O) {
    int n = blockIdx.x, o = threadIdx.x;
    float v = 0.0f;
    #pragma unroll
    for (int d = 0; d < EE; d++) v += ne[n * EE + d] * bp[d * O + o];
    g_BIAS[n * O + o] = v;
}

// ================ transpose + hi/lo split: B operand build =======================
__global__ __launch_bounds__(256) void k_trans(const float* __restrict__ src,
                                               __nv_bfloat16* __restrict__ dhi,
                                               __nv_bfloat16* __restrict__ dlo,
                                               int zmul) {
    __shared__ float tile[64][68];
    int b = blockIdx.y, m0 = blockIdx.x * 64, tid = threadIdx.x;
    #pragma unroll
    for (int i = 0; i < 4; i++) {
        int id = i * 256 + tid;
        int r = id >> 4, c4 = id & 15;
        float4 v = *reinterpret_cast<const float4*>(
            src + ((size_t)b * NN + m0 + r) * 64 + c4 * 4);
        if (zmul) {
            float4 z = *reinterpret_cast<const float4*>(
                g_ZR + (size_t)(m0 + r) * XGPITCH + b * CC + c4 * 4);
            v.x *= z.x; v.y *= z.y; v.z *= z.z; v.w *= z.w;
        }
        *reinterpret_cast<float4*>(&tile[r][c4 * 4]) = v;
    }
    __syncthreads();
    int c = tid >> 2, mg = (tid & 3) * 16;
    uint32_t hi[8], lo[8];
    #pragma unroll
    for (int p = 0; p < 8; p++) {
        float v0 = tile[mg + 2 * p][c], v1 = tile[mg + 2 * p + 1][c];
        __nv_bfloat16 h0 = __float2bfloat16(v0);
        __nv_bfloat16 h1 = __float2bfloat16(v1);
        float l0 = v0 - __bfloat162float(h0);
        float l1 = v1 - __bfloat162float(h1);
        __nv_bfloat162 hp; hp.x = h0; hp.y = h1;
        __nv_bfloat162 lp = __floats2bfloat162_rn(l0, l1);
        hi[p] = *reinterpret_cast<uint32_t*>(&hp);
        lo[p] = *reinterpret_cast<uint32_t*>(&lp);
    }
    size_t o = (size_t)(b * 64 + c) * NN + m0 + mg;
    *reinterpret_cast<uint4*>(dhi + o)     = make_uint4(hi[0], hi[1], hi[2], hi[3]);
    *reinterpret_cast<uint4*>(dhi + o + 8) = make_uint4(hi[4], hi[5], hi[6], hi[7]);
    *reinterpret_cast<uint4*>(dlo + o)     = make_uint4(lo[0], lo[1], lo[2], lo[3]);
    *reinterpret_cast<uint4*>(dlo + o + 8) = make_uint4(lo[4], lo[5], lo[6], lo[7]);
}

// ================ big GEMM via mma.sync bf16, split-precision (3 terms) ==========
// CTA tile 128(M) x 256(N), K-chunk 64, 2-stage double buffer.
// 8 warps: 2(M) x 4(N), warptile 64x64.
#define OFF_ALO 16384
#define OFF_BHI 32768
#define OFF_BLO 65536
#define STAGE_BYTES 98304            // A hi/lo 32K + B hi/lo 64K
#define GEMM_SMEM (2 * STAGE_BYTES)  // 192 KB

__device__ __forceinline__ void load_stage(uint32_t base, int kt, int tid,
        const __nv_bfloat16* Ah, const __nv_bfloat16* Al,
        const __nv_bfloat16* Bh, const __nv_bfloat16* Bl) {
    #pragma unroll
    for (int i = 0; i < 4; i++) {               // A: 128 rows x 128 B
        int id = i * 256 + tid;
        int r = id >> 3, c = id & 7;
        uint32_t off = (uint32_t)(r * 128 + c * 16) ^ (uint32_t)((r & 7) << 4);
        size_t g = (size_t)r * NN + kt * 64 + c * 8;
        cpa16(base + off,           Ah + g);
        cpa16(base + OFF_ALO + off, Al + g);
    }
    #pragma unroll
    for (int i = 0; i < 8; i++) {               // B: 256 rows x 128 B
        int id = i * 256 + tid;
        int r = id >> 3, c = id & 7;
        uint32_t off = (uint32_t)(r * 128 + c * 16) ^ (uint32_t)((r & 7) << 4);
        size_t g = (size_t)r * NN + kt * 64 + c * 8;
        cpa16(base + OFF_BHI + off, Bh + g);
        cpa16(base + OFF_BLO + off, Bl + g);
    }
    CP_COMMIT();
}

__global__ __launch_bounds__(256, 1) void k_hgemm(
        const __nv_bfloat16* __restrict__ Bhi,
        const __nv_bfloat16* __restrict__ Blo,
        int coff) {
    extern __shared__ char dsm[];
    uint32_t sb = smem_u32(dsm);
    int tid = threadIdx.x, lane = tid & 31, wid = tid >> 5;
    int bn = blockIdx.x, bm = blockIdx.y;

    const __nv_bfloat16* Ah = g_Shi + (size_t)(bm * 128) * NN;
    const __nv_bfloat16* Al = g_Slo + (size_t)(bm * 128) * NN;
    const __nv_bfloat16* Bh = Bhi + (size_t)(bn * 256) * NN;
    const __nv_bfloat16* Bl = Blo + (size_t)(bn * 256) * NN;

    int warp_m = (wid >> 2) * 64;    // 2 warps in M
    int warp_n = (wid & 3) * 64;     // 4 warps in N
    float acc[4][8][4] = {};         // [mt16][nt8][frag]

    load_stage(sb, 0, tid, Ah, Al, Bh, Bl);
    load_stage(sb + STAGE_BYTES, 1, tid, Ah, Al, Bh, Bl);

    const int NKT = NN / 64;         // 64
    int lrowA = lane & 15, lgrp = lane >> 4;

    for (int kt = 0; kt < NKT; kt++) {
        CP_WAIT1();
        __syncthreads();

        uint32_t base = sb + (kt & 1) * STAGE_BYTES;
        #pragma unroll
        for (int k16 = 0; k16 < 4; k16++) {
            uint32_t ahi[4][4], alo[4][4];
            #pragma unroll
            for (int mt = 0; mt < 4; mt++) {
                int r = warp_m + mt * 16 + lrowA;
                uint32_t off = (uint32_t)(r * 128 + (k16 * 2 + lgrp) * 16)
                             ^ (uint32_t)((r & 7) << 4);
                LDSM4(ahi[mt][0], ahi[mt][1], ahi[mt][2], ahi[mt][3], base + off);
                LDSM4(alo[mt][0], alo[mt][1], alo[mt][2], alo[mt][3], base + OFF_ALO + off);
            }
            #pragma unroll
            for (int ng = 0; ng < 4; ng++) {
                int r = warp_n + ng * 16 + lrowA;
                uint32_t off = (uint32_t)(r * 128 + (k16 * 2 + lgrp) * 16)
                             ^ (uint32_t)((r & 7) << 4);
                uint32_t t0, t1, t2, t3;
                uint32_t bh0[2], bh1[2], bl0[2], bl1[2];
                LDSM4(t0, t1, t2, t3, base + OFF_BHI + off);
                bh0[0] = t0; bh0[1] = t2; bh1[0] = t1; bh1[1] = t3;
                LDSM4(t0, t1, t2, t3, base + OFF_BLO + off);
                bl0[0] = t0; bl0[1] = t2; bl1[0] = t1; bl1[1] = t3;
                #pragma unroll
                for (int mt = 0; mt < 4; mt++) {
                    MMA_BF16(acc[mt][ng * 2], ahi[mt], bh0);
                    MMA_BF16(acc[mt][ng * 2], ahi[mt], bl0);
                    MMA_BF16(acc[mt][ng * 2], alo[mt], bh0);
                    MMA_BF16(acc[mt][ng * 2 + 1], ahi[mt], bh1);
                    MMA_BF16(acc[mt][ng * 2 + 1], ahi[mt], bl1);
                    MMA_BF16(acc[mt][ng * 2 + 1], alo[mt], bh1);
                }
            }
        }
        __syncthreads();
        if (kt + 2 < NKT)
            load_stage(sb + (kt & 1) * STAGE_BYTES, kt + 2, tid, Ah, Al, Bh, Bl);
        else
            CP_COMMIT();             // keep group counting uniform
    }

    // epilogue: C fragment (row = lane>>2 [+8], col = 2*(lane&3) [+1])
    int row0 = bm * 128 + warp_m + (lane >> 2);
    #pragma unroll
    for (int mt = 0; mt < 4; mt++) {
        #pragma unroll
        for (int nt = 0; nt < 8; nt++) {
            int j = bn * 256 + warp_n + nt * 8 + (lane & 3) * 2;
            int b = j >> 6, c = j & 63;
            float* p = g_XG + (size_t)(row0 + mt * 16) * XGPITCH + b * CC + coff + c;
            *reinterpret_cast<float2*>(p) = make_float2(acc[mt][nt][0], acc[mt][nt][1]);
            *reinterpret_cast<float2*>(p + (size_t)8 * XGPITCH) =
                make_float2(acc[mt][nt][2], acc[mt][nt][3]);
        }
    }
}

// ================ per-node gate GEMM + sigmoid ===================================
__global__ __launch_bounds__(256) void k_node_gate() {
    int n = blockIdx.x, tid = threadIdx.x;
    __shared__ float Xs[BB][132];
    __shared__ float Ws[16][132];

    #pragma unroll
    for (int p = 0; p < 8; p++) {
        int f = tid + p * 256;
        int b = f >> 5, i4 = (f & 31) << 2;
        *reinterpret_cast<float4*>(&Xs[b][i4]) =
            *reinterpret_cast<const float4*>(g_XG + (size_t)n * XGPITCH + b * CC + i4);
    }

    int tb = (tid >> 4) << 2;
    int tj = (tid & 15) << 3;
    float acc[4][8] = {};

    for (int i0 = 0; i0 < CC; i0 += 16) {
        __syncthreads();
        #pragma unroll
        for (int p = 0; p < 2; p++) {
            int f = tid + p * 256;
            int k = f >> 5, j4 = (f & 31) << 2;
            *reinterpret_cast<float4*>(&Ws[k][j4]) =
                *reinterpret_cast<const float4*>(g_W + (size_t)n * (CC * CC) + (i0 + k) * CC + j4);
        }
        __syncthreads();
        #pragma unroll
        for (int k = 0; k < 16; k++) {
            float a[4], bv[8];
            #pragma unroll
            for (int bb = 0; bb < 4; bb++) a[bb] = Xs[tb + bb][i0 + k];
            *reinterpret_cast<float4*>(&bv[0]) = *reinterpret_cast<const float4*>(&Ws[k][tj]);
            *reinterpret_cast<float4*>(&bv[4]) = *reinterpret_cast<const float4*>(&Ws[k][tj + 4]);
            #pragma unroll
            for (int bb = 0; bb < 4; bb++)
                #pragma unroll
                for (int jj = 0; jj < 8; jj++)
                    acc[bb][jj] += a[bb] * bv[jj];
        }
    }

    float bias[8];
    *reinterpret_cast<float4*>(&bias[0]) = *reinterpret_cast<const float4*>(g_BIAS + n * CC + tj);
    *reinterpret_cast<float4*>(&bias[4]) = *reinterpret_cast<const float4*>(g_BIAS + n * CC + tj + 4);
    #pragma unroll
    for (int bb = 0; bb < 4; bb++) {
        float y[8];
        #pragma unroll
        for (int jj = 0; jj < 8; jj++) {
            float v = acc[bb][jj] + bias[jj];
            y[jj] = 1.0f / (1.0f + __expf(-v));
        }
        float* dst = g_ZR + (size_t)n * XGPITCH + (tb + bb) * CC + tj;
        *reinterpret_cast<float4*>(dst) = make_float4(y[0], y[1], y[2], y[3]);
        *reinterpret_cast<float4*>(dst + 4) = make_float4(y[4], y[5], y[6], y[7]);
    }
}

// ================ per-node update GEMM + tanh + GRU combine ======================
__global__ __launch_bounds__(256) void k_node_final(const float* __restrict__ st,
                                                    float* __restrict__ out) {
    int n = blockIdx.x, tid = threadIdx.x;
    __shared__ float Xs[BB][132];
    __shared__ float Ws[16][68];

    #pragma unroll
    for (int p = 0; p < 8; p++) {
        int f = tid + p * 256;
        int b = f >> 5, i4 = (f & 31) << 2;
        *reinterpret_cast<float4*>(&Xs[b][i4]) =
            *reinterpret_cast<const float4*>(g_XG + (size_t)n * XGPITCH + b * CC + i4);
    }

    int tb = (tid >> 4) << 2;
    int to = (tid & 15) << 2;
    float acc[4][4] = {};

    for (int i0 = 0; i0 < CC; i0 += 16) {
        __syncthreads();
        {
            int k = tid >> 4, o4 = (tid & 15) << 2;
            *reinterpret_cast<float4*>(&Ws[k][o4]) =
                *reinterpret_cast<const float4*>(g_W + (size_t)n * (CC * DH) + (i0 + k) * DH + o4);
        }
        __syncthreads();
        #pragma unroll
        for (int k = 0; k < 16; k++) {
            float a[4], bv[4];
            #pragma unroll
            for (int bb = 0; bb < 4; bb++) a[bb] = Xs[tb + bb][i0 + k];
            *reinterpret_cast<float4*>(&bv[0]) = *reinterpret_cast<const float4*>(&Ws[k][to]);
            #pragma unroll
            for (int bb = 0; bb < 4; bb++)
                #pragma unroll
                for (int oo = 0; oo < 4; oo++)
                    acc[bb][oo] += a[bb] * bv[oo];
        }
    }

    float bias[4];
    *reinterpret_cast<float4*>(&bias[0]) = *reinterpret_cast<const float4*>(g_BIAS + n * DH + to);
    #pragma unroll
    for (int bb = 0; bb < 4; bb++) {
        int b = tb + bb;
        float4 r4 = *reinterpret_cast<const float4*>(g_ZR + (size_t)n * XGPITCH + b * CC + DH + to);
        float4 s4 = *reinterpret_cast<const float4*>(st + ((size_t)b * NN + n) * DH + to);
        float hc0 = tanhf(acc[bb][0] + bias[0]);
        float hc1 = tanhf(acc[bb][1] + bias[1]);
        float hc2 = tanhf(acc[bb][2] + bias[2]);
        float hc3 = tanhf(acc[bb][3] + bias[3]);
        float4 h;
        h.x = r4.x * s4.x + (1.0f - r4.x) * hc0;
        h.y = r4.y * s4.y + (1.0f - r4.y) * hc1;
        h.z = r4.z * s4.z + (1.0f - r4.z) * hc2;
        h.w = r4.w * s4.w + (1.0f - r4.w) * hc3;
        *reinterpret_cast<float4*>(out + ((size_t)b * NN + n) * DH + to) = h;
    }
}

// ================ launch =========================================================
extern "C" void kernel_launch(void* const* d_in, const int* in_sizes, int n_in,
                              void* d_out, int out_size) {
    const float* x   = (const float*)d_in[0];
    const float* st  = (const float*)d_in[1];
    const float* ne  = (const float*)d_in[2];
    const float* gwp = (const float*)d_in[3];
    const float* gbp = (const float*)d_in[4];
    const float* uwp = (const float*)d_in[5];
    const float* ubp = (const float*)d_in[6];
    float* out = (float*)d_out;

    static int smem_set = 0;
    if (!smem_set) {
        cudaFuncSetAttribute(k_hgemm, cudaFuncAttributeMaxDynamicSharedMemorySize, GEMM_SMEM);
        smem_set = 1;
    }

    __nv_bfloat16 *bxh, *bxl, *bsh, *bsl;
    cudaGetSymbolAddress((void**)&bxh, g_BXhi);
    cudaGetSymbolAddress((void**)&bxl, g_BXlo);
    cudaGetSymbolAddress((void**)&bsh, g_BShi);
    cudaGetSymbolAddress((void**)&bsl, g_BSlo);

    dim3 ggrid(NN / 256, NN / 128);

    // order chosen so k_hgemm is launch #3 (ncu captures that index)
    k_supports<<<NN, 256>>>(ne);                           // 0
    k_trans<<<dim3(NN / 64, BB), 256>>>(x, bxh, bxl, 0);   // 1
    k_trans<<<dim3(NN / 64, BB), 256>>>(st, bsh, bsl, 0);  // 2

    k_hgemm<<<ggrid, 256, GEMM_SMEM>>>(bxh, bxl, 0);       // 3  S@x (profiled)
    k_hgemm<<<ggrid, 256, GEMM_SMEM>>>(bsh, bsl, 64);      // 4  S@state

    k_mkweights<<<(CC * CC) / 256, 256>>>(ne, gwp, CC * CC);
    k_bias<<<NN, CC>>>(ne, gbp, CC);
    k_node_gate<<<NN, 256>>>();

    // update path
    k_trans<<<dim3(NN / 64, BB), 256>>>(st, bsh, bsl, 1);  // (z*state)^T
    k_mkweights<<<(CC * DH) / 256, 256>>>(ne, uwp, CC * DH);
    k_bias<<<NN, DH>>>(ne, ubp, DH);
    k_hgemm<<<ggrid, 256, GEMM_SMEM>>>(bsh, bsl, 64);
    k_node_final<<<NN, 256>>>(st, out);
}

// round 6
// speedup vs baseline: 1.0568x; 1.0568x over previous
#include <cuda_runtime.h>
#include <cuda_bf16.h>
#include <math.h>
#include <stdint.h>

#define NN 4096
#define BB 64
#define DIN 64
#define DH 64
#define CC 128              // DIN + DH
#define EE 16
#define XGPITCH (BB * CC)   // 8192

// ================= device scratch (no runtime allocs) ==========================
__device__ __nv_bfloat16 g_Shi[(size_t)NN * NN];     // 32 MB supports hi (A operand)
__device__ __nv_bfloat16 g_Slo[(size_t)NN * NN];     // 32 MB supports lo
__device__ __nv_bfloat16 g_BXhi[(size_t)NN * NN];    // 32 MB x^T hi    [j=b*64+c][m]
__device__ __nv_bfloat16 g_BXlo[(size_t)NN * NN];    // 32 MB x^T lo
__device__ __nv_bfloat16 g_BShi[(size_t)NN * NN];    // 32 MB state^T / (z*state)^T hi
__device__ __nv_bfloat16 g_BSlo[(size_t)NN * NN];    // 32 MB
__device__ float g_XG[(size_t)NN * XGPITCH];         // 128 MB [n][b][128]
__device__ float g_W[(size_t)NN * CC * CC];          // 256 MB per-node weights
__device__ float g_BIAS[(size_t)NN * CC];            // 2 MB
__device__ float g_ZR[(size_t)NN * XGPITCH];         // 128 MB z_r [n][b*128+j]

// ================= PTX helpers (sm_80-level only; NO tcgen05) ====================
__device__ __forceinline__ uint32_t smem_u32(const void* p) {
    uint32_t a;
    asm("{ .reg .u64 t; cvta.to.shared.u64 t, %1; cvt.u32.u64 %0, t; }" : "=r"(a) : "l"(p));
    return a;
}
__device__ __forceinline__ void cpa16(uint32_t dst, const void* src) {
    asm volatile("cp.async.cg.shared.global [%0], [%1], 16;" :: "r"(dst), "l"(src));
}
#define CP_COMMIT() asm volatile("cp.async.commit_group;" ::: "memory")
#define CP_WAIT1()  asm volatile("cp.async.wait_group 1;" ::: "memory")

#define LDSM4(r0, r1, r2, r3, addr) \
    asm volatile("ldmatrix.sync.aligned.m8n8.x4.shared.b16 {%0,%1,%2,%3}, [%4];" \
        : "=r"(r0), "=r"(r1), "=r"(r2), "=r"(r3) : "r"(addr))

#define MMA_BF16(c, a, b) \
    asm volatile("mma.sync.aligned.m16n8k16.row.col.f32.bf16.bf16.f32 " \
        "{%0,%1,%2,%3}, {%4,%5,%6,%7}, {%8,%9}, {%0,%1,%2,%3};" \
        : "+f"((c)[0]), "+f"((c)[1]), "+f"((c)[2]), "+f"((c)[3]) \
        : "r"((a)[0]), "r"((a)[1]), "r"((a)[2]), "r"((a)[3]), \
          "r"((b)[0]), "r"((b)[1]))

// ================ supports = softmax(relu(NE @ NE^T)) -> bf16 hi/lo ==============
__global__ __launch_bounds__(256) void k_supports(const float* __restrict__ ne) {
    int n = blockIdx.x, tid = threadIdx.x;
    __shared__ float e[EE];
    __shared__ float redm[8], reds[8];
    if (tid < EE) e[tid] = ne[n * EE + tid];
    __syncthreads();

    float vals[16];
    float mx = 0.0f;
    #pragma unroll
    for (int j = 0; j < 16; j++) {
        int m = tid + j * 256;
        const float4* p = reinterpret_cast<const float4*>(ne + m * EE);
        float4 v0 = p[0], v1 = p[1], v2 = p[2], v3 = p[3];
        float d = e[0]*v0.x + e[1]*v0.y + e[2]*v0.z + e[3]*v0.w
                + e[4]*v1.x + e[5]*v1.y + e[6]*v1.z + e[7]*v1.w
                + e[8]*v2.x + e[9]*v2.y + e[10]*v2.z + e[11]*v2.w
                + e[12]*v3.x + e[13]*v3.y + e[14]*v3.z + e[15]*v3.w;
        d = fmaxf(d, 0.0f);
        vals[j] = d;
        mx = fmaxf(mx, d);
    }
    #pragma unroll
    for (int o = 16; o > 0; o >>= 1) mx = fmaxf(mx, __shfl_xor_sync(0xffffffffu, mx, o));
    if ((tid & 31) == 0) redm[tid >> 5] = mx;
    __syncthreads();
    mx = redm[0];
    #pragma unroll
    for (int w = 1; w < 8; w++) mx = fmaxf(mx, redm[w]);

    float s = 0.0f;
    #pragma unroll
    for (int j = 0; j < 16; j++) { vals[j] = __expf(vals[j] - mx); s += vals[j]; }
    #pragma unroll
    for (int o = 16; o > 0; o >>= 1) s += __shfl_xor_sync(0xffffffffu, s, o);
    if ((tid & 31) == 0) reds[tid >> 5] = s;
    __syncthreads();
    s = 0.0f;
    #pragma unroll
    for (int w = 0; w < 8; w++) s += reds[w];
    float inv = 1.0f / s;
    #pragma unroll
    for (int j = 0; j < 16; j++) {
        float v = vals[j] * inv;
        __nv_bfloat16 h = __float2bfloat16(v);
        size_t o = (size_t)n * NN + tid + j * 256;
        g_Shi[o] = h;
        g_Slo[o] = __float2bfloat16(v - __bfloat162float(h));
    }
}

// ================ per-node weights / bias ========================================
__global__ __launch_bounds__(256) void k_mkweights(const float* __restrict__ ne,
                                                   const float* __restrict__ wp,
                                                   int IO) {
    int io = blockIdx.x * 256 + threadIdx.x;
    float wv[EE];
    #pragma unroll
    for (int d = 0; d < EE; d++) wv[d] = wp[(size_t)d * IO + io];
    __shared__ float sne[128 * EE];
    for (int n0 = 0; n0 < NN; n0 += 128) {
        __syncthreads();
        for (int t = threadIdx.x; t < 128 * EE; t += 256) sne[t] = ne[n0 * EE + t];
        __syncthreads();
        for (int nn = 0; nn < 128; nn++) {
            float v = 0.0f;
            #pragma unroll
            for (int d = 0; d < EE; d++) v += sne[nn * EE + d] * wv[d];
            g_W[(size_t)(n0 + nn) * IO + io] = v;
        }
    }
}

__global__ void k_bias(const float* __restrict__ ne, const float* __restrict__ bp, int O) {
    int n = blockIdx.x, o = threadIdx.x;
    float v = 0.0f;
    #pragma unroll
    for (int d = 0; d < EE; d++) v += ne[n * EE + d] * bp[d * O + o];
    g_BIAS[n * O + o] = v;
}

// ================ transpose + hi/lo split: B operand build =======================
__global__ __launch_bounds__(256) void k_trans(const float* __restrict__ src,
                                               __nv_bfloat16* __restrict__ dhi,
                                               __nv_bfloat16* __restrict__ dlo,
                                               int zmul) {
    __shared__ float tile[64][68];
    int b = blockIdx.y, m0 = blockIdx.x * 64, tid = threadIdx.x;
    #pragma unroll
    for (int i = 0; i < 4; i++) {
        int id = i * 256 + tid;
        int r = id >> 4, c4 = id & 15;
        float4 v = *reinterpret_cast<const float4*>(
            src + ((size_t)b * NN + m0 + r) * 64 + c4 * 4);
        if (zmul) {
            float4 z = *reinterpret_cast<const float4*>(
                g_ZR + (size_t)(m0 + r) * XGPITCH + b * CC + c4 * 4);
            v.x *= z.x; v.y *= z.y; v.z *= z.z; v.w *= z.w;
        }
        *reinterpret_cast<float4*>(&tile[r][c4 * 4]) = v;
    }
    __syncthreads();
    int c = tid >> 2, mg = (tid & 3) * 16;
    uint32_t hi[8], lo[8];
    #pragma unroll
    for (int p = 0; p < 8; p++) {
        float v0 = tile[mg + 2 * p][c], v1 = tile[mg + 2 * p + 1][c];
        __nv_bfloat16 h0 = __float2bfloat16(v0);
        __nv_bfloat16 h1 = __float2bfloat16(v1);
        float l0 = v0 - __bfloat162float(h0);
        float l1 = v1 - __bfloat162float(h1);
        __nv_bfloat162 hp; hp.x = h0; hp.y = h1;
        __nv_bfloat162 lp = __floats2bfloat162_rn(l0, l1);
        hi[p] = *reinterpret_cast<uint32_t*>(&hp);
        lo[p] = *reinterpret_cast<uint32_t*>(&lp);
    }
    size_t o = (size_t)(b * 64 + c) * NN + m0 + mg;
    *reinterpret_cast<uint4*>(dhi + o)     = make_uint4(hi[0], hi[1], hi[2], hi[3]);
    *reinterpret_cast<uint4*>(dhi + o + 8) = make_uint4(hi[4], hi[5], hi[6], hi[7]);
    *reinterpret_cast<uint4*>(dlo + o)     = make_uint4(lo[0], lo[1], lo[2], lo[3]);
    *reinterpret_cast<uint4*>(dlo + o + 8) = make_uint4(lo[4], lo[5], lo[6], lo[7]);
}

// ================ big GEMM via mma.sync bf16, split-precision (3 terms) ==========
// CTA tile 128(M) x 128(N), K-chunk 32 (64B rows), 3-stage, 2 CTAs/SM.
// 8 warps: 2(M) x 4(N), warptile 64x32.
// 64B-row swizzle: chunk c' = c ^ (r&3) ^ ((r>>2)&1)  (conflict-free LDSM phases)
#define OFF_ALO  8192
#define OFF_BHI 16384
#define OFF_BLO 24576
#define STAGE_BYTES 32768            // 4 matrices x 128 rows x 64 B
#define GEMM_SMEM (3 * STAGE_BYTES)  // 96 KB -> 2 CTAs/SM

__device__ __forceinline__ uint32_t swz64(int r, int c) {
    return (uint32_t)(r * 64 + ((c ^ (r & 3) ^ ((r >> 2) & 1)) << 4));
}

__device__ __forceinline__ void load_stage(uint32_t base, int kt, int tid,
        const __nv_bfloat16* Ah, const __nv_bfloat16* Al,
        const __nv_bfloat16* Bh, const __nv_bfloat16* Bl) {
    int k0 = kt * 32;
    #pragma unroll
    for (int i = 0; i < 2; i++) {               // A: 128 rows x 4 chunks
        int id = i * 256 + tid;
        int r = id >> 2, c = id & 3;
        uint32_t off = swz64(r, c);
        size_t g = (size_t)r * NN + k0 + c * 8;
        cpa16(base + off,           Ah + g);
        cpa16(base + OFF_ALO + off, Al + g);
    }
    #pragma unroll
    for (int i = 0; i < 2; i++) {               // B: 128 rows x 4 chunks
        int id = i * 256 + tid;
        int r = id >> 2, c = id & 3;
        uint32_t off = swz64(r, c);
        size_t g = (size_t)r * NN + k0 + c * 8;
        cpa16(base + OFF_BHI + off, Bh + g);
        cpa16(base + OFF_BLO + off, Bl + g);
    }
    CP_COMMIT();
}

__global__ __launch_bounds__(256, 2) void k_hgemm(
        const __nv_bfloat16* __restrict__ Bhi,
        const __nv_bfloat16* __restrict__ Blo,
        int coff) {
    extern __shared__ char dsm[];
    uint32_t sb = smem_u32(dsm);
    int tid = threadIdx.x, lane = tid & 31, wid = tid >> 5;
    int bn = blockIdx.x, bm = blockIdx.y;

    const __nv_bfloat16* Ah = g_Shi + (size_t)(bm * 128) * NN;
    const __nv_bfloat16* Al = g_Slo + (size_t)(bm * 128) * NN;
    const __nv_bfloat16* Bh = Bhi + (size_t)(bn * 128) * NN;
    const __nv_bfloat16* Bl = Blo + (size_t)(bn * 128) * NN;

    int warp_m = (wid >> 2) * 64;    // 2 warps in M
    int warp_n = (wid & 3) * 32;     // 4 warps in N
    float acc[4][4][4] = {};         // [mt16][nt8][frag]

    load_stage(sb, 0, tid, Ah, Al, Bh, Bl);
    load_stage(sb + STAGE_BYTES, 1, tid, Ah, Al, Bh, Bl);

    const int NKT = NN / 32;         // 128
    int lrowA = lane & 15, lgrp = lane >> 4;

    for (int kt = 0; kt < NKT; kt++) {
        CP_WAIT1();
        __syncthreads();

        // prefetch kt+2 first so the copy overlaps this iteration's MMAs
        if (kt + 2 < NKT)
            load_stage(sb + ((kt + 2) % 3) * STAGE_BYTES, kt + 2, tid, Ah, Al, Bh, Bl);
        else
            CP_COMMIT();             // keep group counting uniform

        uint32_t base = sb + (kt % 3) * STAGE_BYTES;
        #pragma unroll
        for (int s = 0; s < 2; s++) {            // two k16 steps per 32-chunk
            int cb = s * 2 + lgrp;
            // B fragments resident (16 regs)
            uint32_t bh[4][2], bl[4][2];
            #pragma unroll
            for (int ng = 0; ng < 2; ng++) {
                int r = warp_n + ng * 16 + lrowA;
                uint32_t off = swz64(r, cb);
                uint32_t t0, t1, t2, t3;
                LDSM4(t0, t1, t2, t3, base + OFF_BHI + off);
                bh[ng * 2][0] = t0; bh[ng * 2][1] = t2;
                bh[ng * 2 + 1][0] = t1; bh[ng * 2 + 1][1] = t3;
                LDSM4(t0, t1, t2, t3, base + OFF_BLO + off);
                bl[ng * 2][0] = t0; bl[ng * 2][1] = t2;
                bl[ng * 2 + 1][0] = t1; bl[ng * 2 + 1][1] = t3;
            }
            // A fragments transient (8 regs at a time)
            #pragma unroll
            for (int mt = 0; mt < 4; mt++) {
                int r = warp_m + mt * 16 + lrowA;
                uint32_t off = swz64(r, cb);
                uint32_t ahi[4], alo[4];
                LDSM4(ahi[0], ahi[1], ahi[2], ahi[3], base + off);
                LDSM4(alo[0], alo[1], alo[2], alo[3], base + OFF_ALO + off);
                #pragma unroll
                for (int nt = 0; nt < 4; nt++) {
                    MMA_BF16(acc[mt][nt], ahi, bh[nt]);
                    MMA_BF16(acc[mt][nt], ahi, bl[nt]);
                    MMA_BF16(acc[mt][nt], alo, bh[nt]);
                }
            }
        }
    }

    // epilogue: C fragment (row = lane>>2 [+8], col = 2*(lane&3) [+1])
    int row0 = bm * 128 + warp_m + (lane >> 2);
    #pragma unroll
    for (int mt = 0; mt < 4; mt++) {
        #pragma unroll
        for (int nt = 0; nt < 4; nt++) {
            int j = bn * 128 + warp_n + nt * 8 + (lane & 3) * 2;
            int b = j >> 6, c = j & 63;
            float* p = g_XG + (size_t)(row0 + mt * 16) * XGPITCH + b * CC + coff + c;
            *reinterpret_cast<float2*>(p) = make_float2(acc[mt][nt][0], acc[mt][nt][1]);
            *reinterpret_cast<float2*>(p + (size_t)8 * XGPITCH) =
                make_float2(acc[mt][nt][2], acc[mt][nt][3]);
        }
    }
}

// ================ per-node gate GEMM + sigmoid ===================================
__global__ __launch_bounds__(256) void k_node_gate() {
    int n = blockIdx.x, tid = threadIdx.x;
    __shared__ float Xs[BB][132];
    __shared__ float Ws[16][132];

    #pragma unroll
    for (int p = 0; p < 8; p++) {
        int f = tid + p * 256;
        int b = f >> 5, i4 = (f & 31) << 2;
        *reinterpret_cast<float4*>(&Xs[b][i4]) =
            *reinterpret_cast<const float4*>(g_XG + (size_t)n * XGPITCH + b * CC + i4);
    }

    int tb = (tid >> 4) << 2;
    int tj = (tid & 15) << 3;
    float acc[4][8] = {};

    for (int i0 = 0; i0 < CC; i0 += 16) {
        __syncthreads();
        #pragma unroll
        for (int p = 0; p < 2; p++) {
            int f = tid + p * 256;
            int k = f >> 5, j4 = (f & 31) << 2;
            *reinterpret_cast<float4*>(&Ws[k][j4]) =
                *reinterpret_cast<const float4*>(g_W + (size_t)n * (CC * CC) + (i0 + k) * CC + j4);
        }
        __syncthreads();
        #pragma unroll
        for (int k = 0; k < 16; k++) {
            float a[4], bv[8];
            #pragma unroll
            for (int bb = 0; bb < 4; bb++) a[bb] = Xs[tb + bb][i0 + k];
            *reinterpret_cast<float4*>(&bv[0]) = *reinterpret_cast<const float4*>(&Ws[k][tj]);
            *reinterpret_cast<float4*>(&bv[4]) = *reinterpret_cast<const float4*>(&Ws[k][tj + 4]);
            #pragma unroll
            for (int bb = 0; bb < 4; bb++)
                #pragma unroll
                for (int jj = 0; jj < 8; jj++)
                    acc[bb][jj] += a[bb] * bv[jj];
        }
    }

    float bias[8];
    *reinterpret_cast<float4*>(&bias[0]) = *reinterpret_cast<const float4*>(g_BIAS + n * CC + tj);
    *reinterpret_cast<float4*>(&bias[4]) = *reinterpret_cast<const float4*>(g_BIAS + n * CC + tj + 4);
    #pragma unroll
    for (int bb = 0; bb < 4; bb++) {
        float y[8];
        #pragma unroll
        for (int jj = 0; jj < 8; jj++) {
            float v = acc[bb][jj] + bias[jj];
            y[jj] = 1.0f / (1.0f + __expf(-v));
        }
        float* dst = g_ZR + (size_t)n * XGPITCH + (tb + bb) * CC + tj;
        *reinterpret_cast<float4*>(dst) = make_float4(y[0], y[1], y[2], y[3]);
        *reinterpret_cast<float4*>(dst + 4) = make_float4(y[4], y[5], y[6], y[7]);
    }
}

// ================ per-node update GEMM + tanh + GRU combine ======================
__global__ __launch_bounds__(256) void k_node_final(const float* __restrict__ st,
                                                    float* __restrict__ out) {
    int n = blockIdx.x, tid = threadIdx.x;
    __shared__ float Xs[BB][132];
    __shared__ float Ws[16][68];

    #pragma unroll
    for (int p = 0; p < 8; p++) {
        int f = tid + p * 256;
        int b = f >> 5, i4 = (f & 31) << 2;
        *reinterpret_cast<float4*>(&Xs[b][i4]) =
            *reinterpret_cast<const float4*>(g_XG + (size_t)n * XGPITCH + b * CC + i4);
    }

    int tb = (tid >> 4) << 2;
    int to = (tid & 15) << 2;
    float acc[4][4] = {};

    for (int i0 = 0; i0 < CC; i0 += 16) {
        __syncthreads();
        {
            int k = tid >> 4, o4 = (tid & 15) << 2;
            *reinterpret_cast<float4*>(&Ws[k][o4]) =
                *reinterpret_cast<const float4*>(g_W + (size_t)n * (CC * DH) + (i0 + k) * DH + o4);
        }
        __syncthreads();
        #pragma unroll
        for (int k = 0; k < 16; k++) {
            float a[4], bv[4];
            #pragma unroll
            for (int bb = 0; bb < 4; bb++) a[bb] = Xs[tb + bb][i0 + k];
            *reinterpret_cast<float4*>(&bv[0]) = *reinterpret_cast<const float4*>(&Ws[k][to]);
            #pragma unroll
            for (int bb = 0; bb < 4; bb++)
                #pragma unroll
                for (int oo = 0; oo < 4; oo++)
                    acc[bb][oo] += a[bb] * bv[oo];
        }
    }

    float bias[4];
    *reinterpret_cast<float4*>(&bias[0]) = *reinterpret_cast<const float4*>(g_BIAS + n * DH + to);
    #pragma unroll
    for (int bb = 0; bb < 4; bb++) {
        int b = tb + bb;
        float4 r4 = *reinterpret_cast<const float4*>(g_ZR + (size_t)n * XGPITCH + b * CC + DH + to);
        float4 s4 = *reinterpret_cast<const float4*>(st + ((size_t)b * NN + n) * DH + to);
        float hc0 = tanhf(acc[bb][0] + bias[0]);
        float hc1 = tanhf(acc[bb][1] + bias[1]);
        float hc2 = tanhf(acc[bb][2] + bias[2]);
        float hc3 = tanhf(acc[bb][3] + bias[3]);
        float4 h;
        h.x = r4.x * s4.x + (1.0f - r4.x) * hc0;
        h.y = r4.y * s4.y + (1.0f - r4.y) * hc1;
        h.z = r4.z * s4.z + (1.0f - r4.z) * hc2;
        h.w = r4.w * s4.w + (1.0f - r4.w) * hc3;
        *reinterpret_cast<float4*>(out + ((size_t)b * NN + n) * DH + to) = h;
    }
}

// ================ launch =========================================================
extern "C" void kernel_launch(void* const* d_in, const int* in_sizes, int n_in,
                              void* d_out, int out_size) {
    const float* x   = (const float*)d_in[0];
    const float* st  = (const float*)d_in[1];
    const float* ne  = (const float*)d_in[2];
    const float* gwp = (const float*)d_in[3];
    const float* gbp = (const float*)d_in[4];
    const float* uwp = (const float*)d_in[5];
    const float* ubp = (const float*)d_in[6];
    float* out = (float*)d_out;

    static int smem_set = 0;
    if (!smem_set) {
        cudaFuncSetAttribute(k_hgemm, cudaFuncAttributeMaxDynamicSharedMemorySize, GEMM_SMEM);
        smem_set = 1;
    }

    __nv_bfloat16 *bxh, *bxl, *bsh, *bsl;
    cudaGetSymbolAddress((void**)&bxh, g_BXhi);
    cudaGetSymbolAddress((void**)&bxl, g_BXlo);
    cudaGetSymbolAddress((void**)&bsh, g_BShi);
    cudaGetSymbolAddress((void**)&bsl, g_BSlo);

    dim3 ggrid(NN / 128, NN / 128);

    // order chosen so k_hgemm is launch #3 (ncu captures that index)
    k_supports<<<NN, 256>>>(ne);                           // 0
    k_trans<<<dim3(NN / 64, BB), 256>>>(x, bxh, bxl, 0);   // 1
    k_trans<<<dim3(NN / 64, BB), 256>>>(st, bsh, bsl, 0);  // 2

    k_hgemm<<<ggrid, 256, GEMM_SMEM>>>(bxh, bxl, 0);       // 3  S@x (profiled)
    k_hgemm<<<ggrid, 256, GEMM_SMEM>>>(bsh, bsl, 64);      // 4  S@state

    k_mkweights<<<(CC * CC) / 256, 256>>>(ne, gwp, CC * CC);
    k_bias<<<NN, CC>>>(ne, gbp, CC);
    k_node_gate<<<NN, 256>>>();

    // update path
    k_trans<<<dim3(NN / 64, BB), 256>>>(st, bsh, bsl, 1);  // (z*state)^T
    k_mkweights<<<(CC * DH) / 256, 256>>>(ne, uwp, CC * DH);
    k_bias<<<NN, DH>>>(ne, ubp, DH);
    k_hgemm<<<ggrid, 256, GEMM_SMEM>>>(bsh, bsl, 64);
    k_node_final<<<NN, 256>>>(st, out);
}

// round 7
// speedup vs baseline: 1.0728x; 1.0152x over previous
#include <cuda_runtime.h>
#include <cuda_bf16.h>
#include <math.h>
#include <stdint.h>

#define NN 4096
#define BB 64
#define DIN 64
#define DH 64
#define CC 128              // DIN + DH
#define EE 16
#define XGPITCH (BB * CC)   // 8192

// ================= device scratch (no runtime allocs) ==========================
__device__ __nv_bfloat16 g_Shi[(size_t)NN * NN];     // supports hi (A operand)
__device__ __nv_bfloat16 g_Slo[(size_t)NN * NN];     // supports lo
__device__ __nv_bfloat16 g_BXhi[(size_t)NN * NN];    // x^T hi    [j=b*64+c][m]
__device__ __nv_bfloat16 g_BXlo[(size_t)NN * NN];
__device__ __nv_bfloat16 g_BShi[(size_t)NN * NN];    // state^T / (z*state)^T
__device__ __nv_bfloat16 g_BSlo[(size_t)NN * NN];
__device__ __nv_bfloat16 g_XGhi[(size_t)NN * XGPITCH]; // S@CAT hi  [n][b*128+i]
__device__ __nv_bfloat16 g_XGlo[(size_t)NN * XGPITCH]; // S@CAT lo
__device__ __nv_bfloat16 g_Wghi[(size_t)NN * CC * CC]; // gate W hi [n][i][o]
__device__ __nv_bfloat16 g_Wglo[(size_t)NN * CC * CC];
__device__ __nv_bfloat16 g_Wuhi[(size_t)NN * CC * DH]; // update W hi [n][i][o]
__device__ __nv_bfloat16 g_Wulo[(size_t)NN * CC * DH];
__device__ float g_ZR[(size_t)NN * XGPITCH];           // z_r [n][b*128+j]

// ================= PTX helpers (sm_80-level only; NO tcgen05) ====================
__device__ __forceinline__ uint32_t smem_u32(const void* p) {
    uint32_t a;
    asm("{ .reg .u64 t; cvta.to.shared.u64 t, %1; cvt.u32.u64 %0, t; }" : "=r"(a) : "l"(p));
    return a;
}
__device__ __forceinline__ void cpa16(uint32_t dst, const void* src) {
    asm volatile("cp.async.cg.shared.global [%0], [%1], 16;" :: "r"(dst), "l"(src));
}
#define CP_COMMIT() asm volatile("cp.async.commit_group;" ::: "memory")
#define CP_WAIT1()  asm volatile("cp.async.wait_group 1;" ::: "memory")
#define CP_WAIT0()  asm volatile("cp.async.wait_group 0;" ::: "memory")

#define LDSM4(r0, r1, r2, r3, addr) \
    asm volatile("ldmatrix.sync.aligned.m8n8.x4.shared.b16 {%0,%1,%2,%3}, [%4];" \
        : "=r"(r0), "=r"(r1), "=r"(r2), "=r"(r3) : "r"(addr))

#define LDSM4T(r0, r1, r2, r3, addr) \
    asm volatile("ldmatrix.sync.aligned.m8n8.x4.trans.shared.b16 {%0,%1,%2,%3}, [%4];" \
        : "=r"(r0), "=r"(r1), "=r"(r2), "=r"(r3) : "r"(addr))

#define MMA_BF16(c, a, b) \
    asm volatile("mma.sync.aligned.m16n8k16.row.col.f32.bf16.bf16.f32 " \
        "{%0,%1,%2,%3}, {%4,%5,%6,%7}, {%8,%9}, {%0,%1,%2,%3};" \
        : "+f"((c)[0]), "+f"((c)[1]), "+f"((c)[2]), "+f"((c)[3]) \
        : "r"((a)[0]), "r"((a)[1]), "r"((a)[2]), "r"((a)[3]), \
          "r"((b)[0]), "r"((b)[1]))

// ================ supports = softmax(relu(NE @ NE^T)) -> bf16 hi/lo ==============
__global__ __launch_bounds__(256) void k_supports(const float* __restrict__ ne) {
    int n = blockIdx.x, tid = threadIdx.x;
    __shared__ float e[EE];
    __shared__ float redm[8], reds[8];
    if (tid < EE) e[tid] = ne[n * EE + tid];
    __syncthreads();

    float vals[16];
    float mx = 0.0f;
    #pragma unroll
    for (int j = 0; j < 16; j++) {
        int m = tid + j * 256;
        const float4* p = reinterpret_cast<const float4*>(ne + m * EE);
        float4 v0 = p[0], v1 = p[1], v2 = p[2], v3 = p[3];
        float d = e[0]*v0.x + e[1]*v0.y + e[2]*v0.z + e[3]*v0.w
                + e[4]*v1.x + e[5]*v1.y + e[6]*v1.z + e[7]*v1.w
                + e[8]*v2.x + e[9]*v2.y + e[10]*v2.z + e[11]*v2.w
                + e[12]*v3.x + e[13]*v3.y + e[14]*v3.z + e[15]*v3.w;
        d = fmaxf(d, 0.0f);
        vals[j] = d;
        mx = fmaxf(mx, d);
    }
    #pragma unroll
    for (int o = 16; o > 0; o >>= 1) mx = fmaxf(mx, __shfl_xor_sync(0xffffffffu, mx, o));
    if ((tid & 31) == 0) redm[tid >> 5] = mx;
    __syncthreads();
    mx = redm[0];
    #pragma unroll
    for (int w = 1; w < 8; w++) mx = fmaxf(mx, redm[w]);

    float s = 0.0f;
    #pragma unroll
    for (int j = 0; j < 16; j++) { vals[j] = __expf(vals[j] - mx); s += vals[j]; }
    #pragma unroll
    for (int o = 16; o > 0; o >>= 1) s += __shfl_xor_sync(0xffffffffu, s, o);
    if ((tid & 31) == 0) reds[tid >> 5] = s;
    __syncthreads();
    s = 0.0f;
    #pragma unroll
    for (int w = 0; w < 8; w++) s += reds[w];
    float inv = 1.0f / s;
    #pragma unroll
    for (int j = 0; j < 16; j++) {
        float v = vals[j] * inv;
        __nv_bfloat16 h = __float2bfloat16(v);
        size_t o = (size_t)n * NN + tid + j * 256;
        g_Shi[o] = h;
        g_Slo[o] = __float2bfloat16(v - __bfloat162float(h));
    }
}

// ================ per-node weights -> bf16 hi/lo, layout [n][i][o] ===============
__global__ __launch_bounds__(256) void k_mkw(const float* __restrict__ ne,
                                             const float* __restrict__ wp,
                                             __nv_bfloat16* __restrict__ whi,
                                             __nv_bfloat16* __restrict__ wlo,
                                             int IO) {
    int io = blockIdx.x * 256 + threadIdx.x;
    float wv[EE];
    #pragma unroll
    for (int d = 0; d < EE; d++) wv[d] = wp[(size_t)d * IO + io];
    __shared__ float sne[128 * EE];
    for (int n0 = 0; n0 < NN; n0 += 128) {
        __syncthreads();
        for (int t = threadIdx.x; t < 128 * EE; t += 256) sne[t] = ne[n0 * EE + t];
        __syncthreads();
        for (int nn = 0; nn < 128; nn++) {
            float v = 0.0f;
            #pragma unroll
            for (int d = 0; d < EE; d++) v += sne[nn * EE + d] * wv[d];
            __nv_bfloat16 h = __float2bfloat16(v);
            size_t o = (size_t)(n0 + nn) * IO + io;
            whi[o] = h;
            wlo[o] = __float2bfloat16(v - __bfloat162float(h));
        }
    }
}

// ================ transpose + hi/lo split: B operand build =======================
__global__ __launch_bounds__(256) void k_trans(const float* __restrict__ src,
                                               __nv_bfloat16* __restrict__ dhi,
                                               __nv_bfloat16* __restrict__ dlo,
                                               int zmul) {
    __shared__ float tile[64][68];
    int b = blockIdx.y, m0 = blockIdx.x * 64, tid = threadIdx.x;
    #pragma unroll
    for (int i = 0; i < 4; i++) {
        int id = i * 256 + tid;
        int r = id >> 4, c4 = id & 15;
        float4 v = *reinterpret_cast<const float4*>(
            src + ((size_t)b * NN + m0 + r) * 64 + c4 * 4);
        if (zmul) {
            float4 z = *reinterpret_cast<const float4*>(
                g_ZR + (size_t)(m0 + r) * XGPITCH + b * CC + c4 * 4);
            v.x *= z.x; v.y *= z.y; v.z *= z.z; v.w *= z.w;
        }
        *reinterpret_cast<float4*>(&tile[r][c4 * 4]) = v;
    }
    __syncthreads();
    int c = tid >> 2, mg = (tid & 3) * 16;
    uint32_t hi[8], lo[8];
    #pragma unroll
    for (int p = 0; p < 8; p++) {
        float v0 = tile[mg + 2 * p][c], v1 = tile[mg + 2 * p + 1][c];
        __nv_bfloat16 h0 = __float2bfloat16(v0);
        __nv_bfloat16 h1 = __float2bfloat16(v1);
        float l0 = v0 - __bfloat162float(h0);
        float l1 = v1 - __bfloat162float(h1);
        __nv_bfloat162 hp; hp.x = h0; hp.y = h1;
        __nv_bfloat162 lp = __floats2bfloat162_rn(l0, l1);
        hi[p] = *reinterpret_cast<uint32_t*>(&hp);
        lo[p] = *reinterpret_cast<uint32_t*>(&lp);
    }
    size_t o = (size_t)(b * 64 + c) * NN + m0 + mg;
    *reinterpret_cast<uint4*>(dhi + o)     = make_uint4(hi[0], hi[1], hi[2], hi[3]);
    *reinterpret_cast<uint4*>(dhi + o + 8) = make_uint4(hi[4], hi[5], hi[6], hi[7]);
    *reinterpret_cast<uint4*>(dlo + o)     = make_uint4(lo[0], lo[1], lo[2], lo[3]);
    *reinterpret_cast<uint4*>(dlo + o + 8) = make_uint4(lo[4], lo[5], lo[6], lo[7]);
}

// ================ big GEMM via mma.sync bf16, split-precision (3 terms) ==========
// CTA tile 128(M) x 128(N), K-chunk 32 (64B rows), 3-stage, 2 CTAs/SM.
#define OFF_ALO  8192
#define OFF_BHI 16384
#define OFF_BLO 24576
#define STAGE_BYTES 32768
#define GEMM_SMEM (3 * STAGE_BYTES)  // 96 KB

__device__ __forceinline__ uint32_t swz64(int r, int c) {
    return (uint32_t)(r * 64 + ((c ^ (r & 3) ^ ((r >> 2) & 1)) << 4));
}
// 256-byte rows (16 x 16B chunks), conflict-free LDSM phases
__device__ __forceinline__ uint32_t swz256(int r, int c) {
    return (uint32_t)(r * 256 + ((c ^ (r & 7)) << 4));
}
// 128-byte rows (8 x 16B chunks)
__device__ __forceinline__ uint32_t swz128(int r, int c) {
    return (uint32_t)(r * 128 + ((c ^ (r & 7)) << 4));
}

__device__ __forceinline__ void load_stage(uint32_t base, int kt, int tid,
        const __nv_bfloat16* Ah, const __nv_bfloat16* Al,
        const __nv_bfloat16* Bh, const __nv_bfloat16* Bl) {
    int k0 = kt * 32;
    #pragma unroll
    for (int i = 0; i < 2; i++) {
        int id = i * 256 + tid;
        int r = id >> 2, c = id & 3;
        uint32_t off = swz64(r, c);
        size_t g = (size_t)r * NN + k0 + c * 8;
        cpa16(base + off,           Ah + g);
        cpa16(base + OFF_ALO + off, Al + g);
    }
    #pragma unroll
    for (int i = 0; i < 2; i++) {
        int id = i * 256 + tid;
        int r = id >> 2, c = id & 3;
        uint32_t off = swz64(r, c);
        size_t g = (size_t)r * NN + k0 + c * 8;
        cpa16(base + OFF_BHI + off, Bh + g);
        cpa16(base + OFF_BLO + off, Bl + g);
    }
    CP_COMMIT();
}

__global__ __launch_bounds__(256, 2) void k_hgemm(
        const __nv_bfloat16* __restrict__ Bhi,
        const __nv_bfloat16* __restrict__ Blo,
        int coff) {
    extern __shared__ char dsm[];
    uint32_t sb = smem_u32(dsm);
    int tid = threadIdx.x, lane = tid & 31, wid = tid >> 5;
    int bn = blockIdx.x, bm = blockIdx.y;

    const __nv_bfloat16* Ah = g_Shi + (size_t)(bm * 128) * NN;
    const __nv_bfloat16* Al = g_Slo + (size_t)(bm * 128) * NN;
    const __nv_bfloat16* Bh = Bhi + (size_t)(bn * 128) * NN;
    const __nv_bfloat16* Bl = Blo + (size_t)(bn * 128) * NN;

    int warp_m = (wid >> 2) * 64;
    int warp_n = (wid & 3) * 32;
    float acc[4][4][4] = {};

    load_stage(sb, 0, tid, Ah, Al, Bh, Bl);
    load_stage(sb + STAGE_BYTES, 1, tid, Ah, Al, Bh, Bl);

    const int NKT = NN / 32;
    int lrowA = lane & 15, lgrp = lane >> 4;

    for (int kt = 0; kt < NKT; kt++) {
        CP_WAIT1();
        __syncthreads();

        if (kt + 2 < NKT)
            load_stage(sb + ((kt + 2) % 3) * STAGE_BYTES, kt + 2, tid, Ah, Al, Bh, Bl);
        else
            CP_COMMIT();

        uint32_t base = sb + (kt % 3) * STAGE_BYTES;
        #pragma unroll
        for (int s = 0; s < 2; s++) {
            int cb = s * 2 + lgrp;
            uint32_t bh[4][2], bl[4][2];
            #pragma unroll
            for (int ng = 0; ng < 2; ng++) {
                int r = warp_n + ng * 16 + lrowA;
                uint32_t off = swz64(r, cb);
                uint32_t t0, t1, t2, t3;
                LDSM4(t0, t1, t2, t3, base + OFF_BHI + off);
                bh[ng * 2][0] = t0; bh[ng * 2][1] = t2;
                bh[ng * 2 + 1][0] = t1; bh[ng * 2 + 1][1] = t3;
                LDSM4(t0, t1, t2, t3, base + OFF_BLO + off);
                bl[ng * 2][0] = t0; bl[ng * 2][1] = t2;
                bl[ng * 2 + 1][0] = t1; bl[ng * 2 + 1][1] = t3;
            }
            #pragma unroll
            for (int mt = 0; mt < 4; mt++) {
                int r = warp_m + mt * 16 + lrowA;
                uint32_t off = swz64(r, cb);
                uint32_t ahi[4], alo[4];
                LDSM4(ahi[0], ahi[1], ahi[2], ahi[3], base + off);
                LDSM4(alo[0], alo[1], alo[2], alo[3], base + OFF_ALO + off);
                #pragma unroll
                for (int nt = 0; nt < 4; nt++) {
                    MMA_BF16(acc[mt][nt], ahi, bh[nt]);
                    MMA_BF16(acc[mt][nt], ahi, bl[nt]);
                    MMA_BF16(acc[mt][nt], alo, bh[nt]);
                }
            }
        }
    }

    // epilogue: write XG as bf16 hi/lo pairs
    int row0 = bm * 128 + warp_m + (lane >> 2);
    #pragma unroll
    for (int mt = 0; mt < 4; mt++) {
        #pragma unroll
        for (int nt = 0; nt < 4; nt++) {
            int j = bn * 128 + warp_n + nt * 8 + (lane & 3) * 2;
            int b = j >> 6, c = j & 63;
            size_t p0 = (size_t)(row0 + mt * 16) * XGPITCH + b * CC + coff + c;
            size_t p1 = p0 + (size_t)8 * XGPITCH;
            float a0 = acc[mt][nt][0], a1 = acc[mt][nt][1];
            float a2 = acc[mt][nt][2], a3 = acc[mt][nt][3];
            __nv_bfloat162 h01, l01, h23, l23;
            h01.x = __float2bfloat16(a0); h01.y = __float2bfloat16(a1);
            l01.x = __float2bfloat16(a0 - __bfloat162float(h01.x));
            l01.y = __float2bfloat16(a1 - __bfloat162float(h01.y));
            h23.x = __float2bfloat16(a2); h23.y = __float2bfloat16(a3);
            l23.x = __float2bfloat16(a2 - __bfloat162float(h23.x));
            l23.y = __float2bfloat16(a3 - __bfloat162float(h23.y));
            *reinterpret_cast<__nv_bfloat162*>(g_XGhi + p0) = h01;
            *reinterpret_cast<__nv_bfloat162*>(g_XGlo + p0) = l01;
            *reinterpret_cast<__nv_bfloat162*>(g_XGhi + p1) = h23;
            *reinterpret_cast<__nv_bfloat162*>(g_XGlo + p1) = l23;
        }
    }
}

// ================ per-node gate GEMM (tensorized) + sigmoid ======================
// block = 128 threads (4 warps), one n per block. X(64x128) @ W_n(128x128).
#define NG_XHI 0
#define NG_XLO 16384
#define NG_WHI 32768
#define NG_WLO 65536
#define NG_BIAS 98304
#define NG_SMEM 98816

__global__ __launch_bounds__(128, 2) void k_ngate(const float* __restrict__ ne,
                                                  const float* __restrict__ gbp) {
    extern __shared__ char dsm[];
    uint32_t sb = smem_u32(dsm);
    int n = blockIdx.x, tid = threadIdx.x, lane = tid & 31, wid = tid >> 5;

    // X: 64 rows x 16 chunks, hi+lo
    #pragma unroll
    for (int i = 0; i < 8; i++) {
        int id = i * 128 + tid;
        int r = id >> 4, c = id & 15;
        uint32_t off = swz256(r, c);
        size_t g = (size_t)n * XGPITCH + r * 128 + c * 8;
        cpa16(sb + NG_XHI + off, g_XGhi + g);
        cpa16(sb + NG_XLO + off, g_XGlo + g);
    }
    // W: 128 rows(i) x 16 chunks(o), hi+lo
    #pragma unroll
    for (int i = 0; i < 16; i++) {
        int id = i * 128 + tid;
        int r = id >> 4, c = id & 15;
        uint32_t off = swz256(r, c);
        size_t g = (size_t)n * (CC * CC) + r * 128 + c * 8;
        cpa16(sb + NG_WHI + off, g_Wghi + g);
        cpa16(sb + NG_WLO + off, g_Wglo + g);
    }
    CP_COMMIT();

    // bias[o] = ne[n,:] @ gbp[:,o]
    {
        float v = 0.0f;
        #pragma unroll
        for (int d = 0; d < EE; d++) v += ne[n * EE + d] * gbp[d * CC + tid];
        reinterpret_cast<float*>(dsm + NG_BIAS)[tid] = v;
    }
    CP_WAIT0();
    __syncthreads();

    int warp_n = wid * 32;
    int lrow = lane & 15, lgrp = lane >> 4;
    float acc[4][4][4] = {};

    #pragma unroll
    for (int k16 = 0; k16 < 8; k16++) {
        uint32_t bh[4][2], bl[4][2];
        #pragma unroll
        for (int half = 0; half < 2; half++) {
            uint32_t off = swz256(k16 * 16 + lrow, (warp_n >> 3) + half * 2 + lgrp);
            uint32_t t0, t1, t2, t3;
            LDSM4T(t0, t1, t2, t3, sb + NG_WHI + off);
            bh[half * 2][0] = t0; bh[half * 2][1] = t1;
            bh[half * 2 + 1][0] = t2; bh[half * 2 + 1][1] = t3;
            LDSM4T(t0, t1, t2, t3, sb + NG_WLO + off);
            bl[half * 2][0] = t0; bl[half * 2][1] = t1;
            bl[half * 2 + 1][0] = t2; bl[half * 2 + 1][1] = t3;
        }
        #pragma unroll
        for (int mt = 0; mt < 4; mt++) {
            uint32_t off = swz256(mt * 16 + lrow, k16 * 2 + lgrp);
            uint32_t ah[4], al[4];
            LDSM4(ah[0], ah[1], ah[2], ah[3], sb + NG_XHI + off);
            LDSM4(al[0], al[1], al[2], al[3], sb + NG_XLO + off);
            #pragma unroll
            for (int nb = 0; nb < 4; nb++) {
                MMA_BF16(acc[mt][nb], ah, bh[nb]);
                MMA_BF16(acc[mt][nb], ah, bl[nb]);
                MMA_BF16(acc[mt][nb], al, bh[nb]);
            }
        }
    }

    const float* biasp = reinterpret_cast<const float*>(dsm + NG_BIAS);
    #pragma unroll
    for (int mt = 0; mt < 4; mt++) {
        #pragma unroll
        for (int nb = 0; nb < 4; nb++) {
            int o = warp_n + nb * 8 + (lane & 3) * 2;
            int b = mt * 16 + (lane >> 2);
            float b0 = biasp[o], b1 = biasp[o + 1];
            float y0 = 1.0f / (1.0f + __expf(-(acc[mt][nb][0] + b0)));
            float y1 = 1.0f / (1.0f + __expf(-(acc[mt][nb][1] + b1)));
            float y2 = 1.0f / (1.0f + __expf(-(acc[mt][nb][2] + b0)));
            float y3 = 1.0f / (1.0f + __expf(-(acc[mt][nb][3] + b1)));
            *reinterpret_cast<float2*>(g_ZR + (size_t)n * XGPITCH + b * CC + o) =
                make_float2(y0, y1);
            *reinterpret_cast<float2*>(g_ZR + (size_t)n * XGPITCH + (b + 8) * CC + o) =
                make_float2(y2, y3);
        }
    }
}

// ================ per-node update GEMM + tanh + GRU combine ======================
// block = 128 threads (4 warps: 2M x 2N), X(64x128) @ Wu(128x64).
#define NF_XHI 0
#define NF_XLO 16384
#define NF_WHI 32768
#define NF_WLO 49152
#define NF_BIAS 65536
#define NF_SMEM 65792

__global__ __launch_bounds__(128, 3) void k_nfinal(const float* __restrict__ ne,
                                                   const float* __restrict__ ubp,
                                                   const float* __restrict__ st,
                                                   float* __restrict__ out) {
    extern __shared__ char dsm[];
    uint32_t sb = smem_u32(dsm);
    int n = blockIdx.x, tid = threadIdx.x, lane = tid & 31, wid = tid >> 5;

    #pragma unroll
    for (int i = 0; i < 8; i++) {
        int id = i * 128 + tid;
        int r = id >> 4, c = id & 15;
        uint32_t off = swz256(r, c);
        size_t g = (size_t)n * XGPITCH + r * 128 + c * 8;
        cpa16(sb + NF_XHI + off, g_XGhi + g);
        cpa16(sb + NF_XLO + off, g_XGlo + g);
    }
    // W: 128 rows(i) x 8 chunks(o=64)
    #pragma unroll
    for (int i = 0; i < 8; i++) {
        int id = i * 128 + tid;
        int r = id >> 3, c = id & 7;
        uint32_t off = swz128(r, c);
        size_t g = (size_t)n * (CC * DH) + r * 64 + c * 8;
        cpa16(sb + NF_WHI + off, g_Wuhi + g);
        cpa16(sb + NF_WLO + off, g_Wulo + g);
    }
    CP_COMMIT();

    if (tid < DH) {
        float v = 0.0f;
        #pragma unroll
        for (int d = 0; d < EE; d++) v += ne[n * EE + d] * ubp[d * DH + tid];
        reinterpret_cast<float*>(dsm + NF_BIAS)[tid] = v;
    }
    CP_WAIT0();
    __syncthreads();

    int warp_m = (wid >> 1) * 32;
    int warp_n = (wid & 1) * 32;
    int lrow = lane & 15, lgrp = lane >> 4;
    float acc[2][4][4] = {};

    #pragma unroll
    for (int k16 = 0; k16 < 8; k16++) {
        uint32_t bh[4][2], bl[4][2];
        #pragma unroll
        for (int half = 0; half < 2; half++) {
            uint32_t off = swz128(k16 * 16 + lrow, (warp_n >> 3) + half * 2 + lgrp);
            uint32_t t0, t1, t2, t3;
            LDSM4T(t0, t1, t2, t3, sb + NF_WHI + off);
            bh[half * 2][0] = t0; bh[half * 2][1] = t1;
            bh[half * 2 + 1][0] = t2; bh[half * 2 + 1][1] = t3;
            LDSM4T(t0, t1, t2, t3, sb + NF_WLO + off);
            bl[half * 2][0] = t0; bl[half * 2][1] = t1;
            bl[half * 2 + 1][0] = t2; bl[half * 2 + 1][1] = t3;
        }
        #pragma unroll
        for (int mt = 0; mt < 2; mt++) {
            uint32_t off = swz256(warp_m + mt * 16 + lrow, k16 * 2 + lgrp);
            uint32_t ah[4], al[4];
            LDSM4(ah[0], ah[1], ah[2], ah[3], sb + NF_XHI + off);
            LDSM4(al[0], al[1], al[2], al[3], sb + NF_XLO + off);
            #pragma unroll
            for (int nb = 0; nb < 4; nb++) {
                MMA_BF16(acc[mt][nb], ah, bh[nb]);
                MMA_BF16(acc[mt][nb], ah, bl[nb]);
                MMA_BF16(acc[mt][nb], al, bh[nb]);
            }
        }
    }

    const float* biasp = reinterpret_cast<const float*>(dsm + NF_BIAS);
    #pragma unroll
    for (int mt = 0; mt < 2; mt++) {
        #pragma unroll
        for (int nb = 0; nb < 4; nb++) {
            int o = warp_n + nb * 8 + (lane & 3) * 2;
            float b0 = biasp[o], b1 = biasp[o + 1];
            #pragma unroll
            for (int h = 0; h < 2; h++) {
                int b = warp_m + mt * 16 + (lane >> 2) + h * 8;
                float hc0 = tanhf(acc[mt][nb][h * 2] + b0);
                float hc1 = tanhf(acc[mt][nb][h * 2 + 1] + b1);
                float2 rr = *reinterpret_cast<const float2*>(
                    g_ZR + (size_t)n * XGPITCH + b * CC + DH + o);
                float2 ss = *reinterpret_cast<const float2*>(
                    st + ((size_t)b * NN + n) * DH + o);
                float2 hv;
                hv.x = rr.x * ss.x + (1.0f - rr.x) * hc0;
                hv.y = rr.y * ss.y + (1.0f - rr.y) * hc1;
                *reinterpret_cast<float2*>(out + ((size_t)b * NN + n) * DH + o) = hv;
            }
        }
    }
}

// ================ launch =========================================================
extern "C" void kernel_launch(void* const* d_in, const int* in_sizes, int n_in,
                              void* d_out, int out_size) {
    const float* x   = (const float*)d_in[0];
    const float* st  = (const float*)d_in[1];
    const float* ne  = (const float*)d_in[2];
    const float* gwp = (const float*)d_in[3];
    const float* gbp = (const float*)d_in[4];
    const float* uwp = (const float*)d_in[5];
    const float* ubp = (const float*)d_in[6];
    float* out = (float*)d_out;

    static int smem_set = 0;
    if (!smem_set) {
        cudaFuncSetAttribute(k_hgemm,  cudaFuncAttributeMaxDynamicSharedMemorySize, GEMM_SMEM);
        cudaFuncSetAttribute(k_ngate,  cudaFuncAttributeMaxDynamicSharedMemorySize, NG_SMEM);
        cudaFuncSetAttribute(k_nfinal, cudaFuncAttributeMaxDynamicSharedMemorySize, NF_SMEM);
        smem_set = 1;
    }

    __nv_bfloat16 *bxh, *bxl, *bsh, *bsl, *wgh, *wgl, *wuh, *wul;
    cudaGetSymbolAddress((void**)&bxh, g_BXhi);
    cudaGetSymbolAddress((void**)&bxl, g_BXlo);
    cudaGetSymbolAddress((void**)&bsh, g_BShi);
    cudaGetSymbolAddress((void**)&bsl, g_BSlo);
    cudaGetSymbolAddress((void**)&wgh, g_Wghi);
    cudaGetSymbolAddress((void**)&wgl, g_Wglo);
    cudaGetSymbolAddress((void**)&wuh, g_Wuhi);
    cudaGetSymbolAddress((void**)&wul, g_Wulo);

    dim3 ggrid(NN / 128, NN / 128);

    k_supports<<<NN, 256>>>(ne);                            // 0
    k_trans<<<dim3(NN / 64, BB), 256>>>(x, bxh, bxl, 0);    // 1
    k_trans<<<dim3(NN / 64, BB), 256>>>(st, bsh, bsl, 0);   // 2

    k_hgemm<<<ggrid, 256, GEMM_SMEM>>>(bxh, bxl, 0);        // 3  S@x (profiled)
    k_hgemm<<<ggrid, 256, GEMM_SMEM>>>(bsh, bsl, 64);       // 4  S@state

    k_mkw<<<(CC * CC) / 256, 256>>>(ne, gwp, wgh, wgl, CC * CC);
    k_ngate<<<NN, 128, NG_SMEM>>>(ne, gbp);

    // update path
    k_trans<<<dim3(NN / 64, BB), 256>>>(st, bsh, bsl, 1);   // (z*state)^T
    k_mkw<<<(CC * DH) / 256, 256>>>(ne, uwp, wuh, wul, CC * DH);
    k_hgemm<<<ggrid, 256, GEMM_SMEM>>>(bsh, bsl, 64);
    k_nfinal<<<NN, 128, NF_SMEM>>>(ne, ubp, st, out);
}

// round 9
// speedup vs baseline: 1.0834x; 1.0099x over previous
#include <cuda_runtime.h>
#include <cuda_bf16.h>
#include <math.h>
#include <stdint.h>

#define NN 4096
#define BB 64
#define DIN 64
#define DH 64
#define CC 128              // DIN + DH
#define EE 16
#define XGPITCH (BB * CC)   // 8192

// ================= device scratch (no runtime allocs) ==========================
__device__ __nv_bfloat16 g_Shi[(size_t)NN * NN];     // supports hi (A operand)
__device__ __nv_bfloat16 g_Slo[(size_t)NN * NN];     // supports lo
__device__ __nv_bfloat16 g_BXhi[(size_t)NN * NN];    // x^T hi    [j=b*64+c][m]
__device__ __nv_bfloat16 g_BXlo[(size_t)NN * NN];
__device__ __nv_bfloat16 g_BShi[(size_t)NN * NN];    // state^T / (z*state)^T
__device__ __nv_bfloat16 g_BSlo[(size_t)NN * NN];
__device__ __nv_bfloat16 g_XGhi[(size_t)NN * XGPITCH]; // S@CAT hi  [n][b*128+i]
__device__ __nv_bfloat16 g_XGlo[(size_t)NN * XGPITCH]; // S@CAT lo
__device__ __nv_bfloat16 g_Wghi[(size_t)NN * CC * CC]; // gate W hi [n][i][o]
__device__ __nv_bfloat16 g_Wglo[(size_t)NN * CC * CC];
__device__ __nv_bfloat16 g_Wuhi[(size_t)NN * CC * DH]; // update W hi [n][i][o]
__device__ __nv_bfloat16 g_Wulo[(size_t)NN * CC * DH];
__device__ float g_ZR[(size_t)NN * XGPITCH];           // z_r [n][b*128+j]

// ================= PTX helpers (sm_80-level only; NO tcgen05) ====================
__device__ __forceinline__ uint32_t smem_u32(const void* p) {
    uint32_t a;
    asm("{ .reg .u64 t; cvta.to.shared.u64 t, %1; cvt.u32.u64 %0, t; }" : "=r"(a) : "l"(p));
    return a;
}
__device__ __forceinline__ void cpa16(uint32_t dst, const void* src) {
    asm volatile("cp.async.cg.shared.global [%0], [%1], 16;" :: "r"(dst), "l"(src));
}
#define CP_COMMIT() asm volatile("cp.async.commit_group;" ::: "memory")
#define CP_WAIT1()  asm volatile("cp.async.wait_group 1;" ::: "memory")
#define CP_WAIT0()  asm volatile("cp.async.wait_group 0;" ::: "memory")

#define LDSM4(r0, r1, r2, r3, addr) \
    asm volatile("ldmatrix.sync.aligned.m8n8.x4.shared.b16 {%0,%1,%2,%3}, [%4];" \
        : "=r"(r0), "=r"(r1), "=r"(r2), "=r"(r3) : "r"(addr))

#define LDSM4T(r0, r1, r2, r3, addr) \
    asm volatile("ldmatrix.sync.aligned.m8n8.x4.trans.shared.b16 {%0,%1,%2,%3}, [%4];" \
        : "=r"(r0), "=r"(r1), "=r"(r2), "=r"(r3) : "r"(addr))

#define MMA_BF16(c, a, b) \
    asm volatile("mma.sync.aligned.m16n8k16.row.col.f32.bf16.bf16.f32 " \
        "{%0,%1,%2,%3}, {%4,%5,%6,%7}, {%8,%9}, {%0,%1,%2,%3};" \
        : "+f"((c)[0]), "+f"((c)[1]), "+f"((c)[2]), "+f"((c)[3]) \
        : "r"((a)[0]), "r"((a)[1]), "r"((a)[2]), "r"((a)[3]), \
          "r"((b)[0]), "r"((b)[1]))

// ================ supports = softmax(relu(NE @ NE^T)) -> bf16 hi/lo ==============
__global__ __launch_bounds__(256) void k_supports(const float* __restrict__ ne) {
    int n = blockIdx.x, tid = threadIdx.x;
    __shared__ float e[EE];
    __shared__ float redm[8], reds[8];
    if (tid < EE) e[tid] = ne[n * EE + tid];
    __syncthreads();

    float vals[16];
    float mx = 0.0f;
    #pragma unroll
    for (int j = 0; j < 16; j++) {
        int m = tid + j * 256;
        const float4* p = reinterpret_cast<const float4*>(ne + m * EE);
        float4 v0 = p[0], v1 = p[1], v2 = p[2], v3 = p[3];
        float d = e[0]*v0.x + e[1]*v0.y + e[2]*v0.z + e[3]*v0.w
                + e[4]*v1.x + e[5]*v1.y + e[6]*v1.z + e[7]*v1.w
                + e[8]*v2.x + e[9]*v2.y + e[10]*v2.z + e[11]*v2.w
                + e[12]*v3.x + e[13]*v3.y + e[14]*v3.z + e[15]*v3.w;
        d = fmaxf(d, 0.0f);
        vals[j] = d;
        mx = fmaxf(mx, d);
    }
    #pragma unroll
    for (int o = 16; o > 0; o >>= 1) mx = fmaxf(mx, __shfl_xor_sync(0xffffffffu, mx, o));
    if ((tid & 31) == 0) redm[tid >> 5] = mx;
    __syncthreads();
    mx = redm[0];
    #pragma unroll
    for (int w = 1; w < 8; w++) mx = fmaxf(mx, redm[w]);

    float s = 0.0f;
    #pragma unroll
    for (int j = 0; j < 16; j++) { vals[j] = __expf(vals[j] - mx); s += vals[j]; }
    #pragma unroll
    for (int o = 16; o > 0; o >>= 1) s += __shfl_xor_sync(0xffffffffu, s, o);
    if ((tid & 31) == 0) reds[tid >> 5] = s;
    __syncthreads();
    s = 0.0f;
    #pragma unroll
    for (int w = 0; w < 8; w++) s += reds[w];
    float inv = 1.0f / s;
    #pragma unroll
    for (int j = 0; j < 16; j++) {
        float v = vals[j] * inv;
        __nv_bfloat16 h = __float2bfloat16(v);
        size_t o = (size_t)n * NN + tid + j * 256;
        g_Shi[o] = h;
        g_Slo[o] = __float2bfloat16(v - __bfloat162float(h));
    }
}

// ================ per-node weights -> bf16 hi/lo, layout [n][i][o] ===============
__global__ __launch_bounds__(256) void k_mkw(const float* __restrict__ ne,
                                             const float* __restrict__ wp,
                                             __nv_bfloat16* __restrict__ whi,
                                             __nv_bfloat16* __restrict__ wlo,
                                             int IO) {
    int io = blockIdx.x * 256 + threadIdx.x;
    float wv[EE];
    #pragma unroll
    for (int d = 0; d < EE; d++) wv[d] = wp[(size_t)d * IO + io];
    __shared__ float sne[128 * EE];
    for (int n0 = 0; n0 < NN; n0 += 128) {
        __syncthreads();
        for (int t = threadIdx.x; t < 128 * EE; t += 256) sne[t] = ne[n0 * EE + t];
        __syncthreads();
        for (int nn = 0; nn < 128; nn++) {
            float v = 0.0f;
            #pragma unroll
            for (int d = 0; d < EE; d++) v += sne[nn * EE + d] * wv[d];
            __nv_bfloat16 h = __float2bfloat16(v);
            size_t o = (size_t)(n0 + nn) * IO + io;
            whi[o] = h;
            wlo[o] = __float2bfloat16(v - __bfloat162float(h));
        }
    }
}

// ================ transpose + hi/lo split: B operand build =======================
__global__ __launch_bounds__(256) void k_trans(const float* __restrict__ src,
                                               __nv_bfloat16* __restrict__ dhi,
                                               __nv_bfloat16* __restrict__ dlo,
                                               int zmul) {
    __shared__ float tile[64][68];
    int b = blockIdx.y, m0 = blockIdx.x * 64, tid = threadIdx.x;
    #pragma unroll
    for (int i = 0; i < 4; i++) {
        int id = i * 256 + tid;
        int r = id >> 4, c4 = id & 15;
        float4 v = *reinterpret_cast<const float4*>(
            src + ((size_t)b * NN + m0 + r) * 64 + c4 * 4);
        if (zmul) {
            float4 z = *reinterpret_cast<const float4*>(
                g_ZR + (size_t)(m0 + r) * XGPITCH + b * CC + c4 * 4);
            v.x *= z.x; v.y *= z.y; v.z *= z.z; v.w *= z.w;
        }
        *reinterpret_cast<float4*>(&tile[r][c4 * 4]) = v;
    }
    __syncthreads();
    int c = tid >> 2, mg = (tid & 3) * 16;
    uint32_t hi[8], lo[8];
    #pragma unroll
    for (int p = 0; p < 8; p++) {
        float v0 = tile[mg + 2 * p][c], v1 = tile[mg + 2 * p + 1][c];
        __nv_bfloat16 h0 = __float2bfloat16(v0);
        __nv_bfloat16 h1 = __float2bfloat16(v1);
        float l0 = v0 - __bfloat162float(h0);
        float l1 = v1 - __bfloat162float(h1);
        __nv_bfloat162 hp; hp.x = h0; hp.y = h1;
        __nv_bfloat162 lp = __floats2bfloat162_rn(l0, l1);
        hi[p] = *reinterpret_cast<uint32_t*>(&hp);
        lo[p] = *reinterpret_cast<uint32_t*>(&lp);
    }
    size_t o = (size_t)(b * 64 + c) * NN + m0 + mg;
    *reinterpret_cast<uint4*>(dhi + o)     = make_uint4(hi[0], hi[1], hi[2], hi[3]);
    *reinterpret_cast<uint4*>(dhi + o + 8) = make_uint4(hi[4], hi[5], hi[6], hi[7]);
    *reinterpret_cast<uint4*>(dlo + o)     = make_uint4(lo[0], lo[1], lo[2], lo[3]);
    *reinterpret_cast<uint4*>(dlo + o + 8) = make_uint4(lo[4], lo[5], lo[6], lo[7]);
}

// ================ big GEMM via mma.sync bf16, split-precision (3 terms) ==========
// CTA tile 128(M) x 128(N), K-chunk 32 (64B rows), 3-stage, 2 CTAs/SM.
// Dual-B: bn < split -> (Bh0,Bl0) with coff0; else (Bh1,Bl1) with coff 64.
// Both halves write the same rows but disjoint column ranges of g_XG (coff).
#define OFF_ALO  8192
#define OFF_BHI 16384
#define OFF_BLO 24576
#define STAGE_BYTES 32768
#define GEMM_SMEM (3 * STAGE_BYTES)  // 96 KB

__device__ __forceinline__ uint32_t swz64(int r, int c) {
    return (uint32_t)(r * 64 + ((c ^ (r & 3) ^ ((r >> 2) & 1)) << 4));
}
__device__ __forceinline__ uint32_t swz256(int r, int c) {
    return (uint32_t)(r * 256 + ((c ^ (r & 7)) << 4));
}
__device__ __forceinline__ uint32_t swz128(int r, int c) {
    return (uint32_t)(r * 128 + ((c ^ (r & 7)) << 4));
}

__device__ __forceinline__ void load_stage(uint32_t base, int kt, int tid,
        const __nv_bfloat16* Ah, const __nv_bfloat16* Al,
        const __nv_bfloat16* Bh, const __nv_bfloat16* Bl) {
    int k0 = kt * 32;
    #pragma unroll
    for (int i = 0; i < 2; i++) {
        int id = i * 256 + tid;
        int r = id >> 2, c = id & 3;
        uint32_t off = swz64(r, c);
        size_t g = (size_t)r * NN + k0 + c * 8;
        cpa16(base + off,           Ah + g);
        cpa16(base + OFF_ALO + off, Al + g);
    }
    #pragma unroll
    for (int i = 0; i < 2; i++) {
        int id = i * 256 + tid;
        int r = id >> 2, c = id & 3;
        uint32_t off = swz64(r, c);
        size_t g = (size_t)r * NN + k0 + c * 8;
        cpa16(base + OFF_BHI + off, Bh + g);
        cpa16(base + OFF_BLO + off, Bl + g);
    }
    CP_COMMIT();
}

__global__ __launch_bounds__(256, 2) void k_hgemm(
        const __nv_bfloat16* __restrict__ Bhi0,
        const __nv_bfloat16* __restrict__ Blo0,
        int coff0,
        const __nv_bfloat16* __restrict__ Bhi1,
        const __nv_bfloat16* __restrict__ Blo1,
        int split) {
    extern __shared__ char dsm[];
    uint32_t sb = smem_u32(dsm);
    int tid = threadIdx.x, lane = tid & 31, wid = tid >> 5;
    int bn = blockIdx.x, bm = blockIdx.y;

    // uniform (blockIdx-only) operand select — no per-thread divergence
    const __nv_bfloat16 *Bhp, *Blp;
    int coff;
    if (bn < split) { Bhp = Bhi0; Blp = Blo0; coff = coff0; }
    else            { Bhp = Bhi1; Blp = Blo1; coff = 64; bn -= split; }

    const __nv_bfloat16* Ah = g_Shi + (size_t)(bm * 128) * NN;
    const __nv_bfloat16* Al = g_Slo + (size_t)(bm * 128) * NN;
    const __nv_bfloat16* Bh = Bhp + (size_t)(bn * 128) * NN;
    const __nv_bfloat16* Bl = Blp + (size_t)(bn * 128) * NN;

    int warp_m = (wid >> 2) * 64;
    int warp_n = (wid & 3) * 32;
    float acc[4][4][4] = {};

    load_stage(sb, 0, tid, Ah, Al, Bh, Bl);
    load_stage(sb + STAGE_BYTES, 1, tid, Ah, Al, Bh, Bl);

    const int NKT = NN / 32;
    int lrowA = lane & 15, lgrp = lane >> 4;

    for (int kt = 0; kt < NKT; kt++) {
        CP_WAIT1();
        __syncthreads();

        if (kt + 2 < NKT)
            load_stage(sb + ((kt + 2) % 3) * STAGE_BYTES, kt + 2, tid, Ah, Al, Bh, Bl);
        else
            CP_COMMIT();

        uint32_t base = sb + (kt % 3) * STAGE_BYTES;
        #pragma unroll
        for (int s = 0; s < 2; s++) {
            int cb = s * 2 + lgrp;
            uint32_t bh[4][2], bl[4][2];
            #pragma unroll
            for (int ng = 0; ng < 2; ng++) {
                int r = warp_n + ng * 16 + lrowA;
                uint32_t off = swz64(r, cb);
                uint32_t t0, t1, t2, t3;
                LDSM4(t0, t1, t2, t3, base + OFF_BHI + off);
                bh[ng * 2][0] = t0; bh[ng * 2][1] = t2;
                bh[ng * 2 + 1][0] = t1; bh[ng * 2 + 1][1] = t3;
                LDSM4(t0, t1, t2, t3, base + OFF_BLO + off);
                bl[ng * 2][0] = t0; bl[ng * 2][1] = t2;
                bl[ng * 2 + 1][0] = t1; bl[ng * 2 + 1][1] = t3;
            }
            #pragma unroll
            for (int mt = 0; mt < 4; mt++) {
                int r = warp_m + mt * 16 + lrowA;
                uint32_t off = swz64(r, cb);
                uint32_t ahi[4], alo[4];
                LDSM4(ahi[0], ahi[1], ahi[2], ahi[3], base + off);
                LDSM4(alo[0], alo[1], alo[2], alo[3], base + OFF_ALO + off);
                #pragma unroll
                for (int nt = 0; nt < 4; nt++) {
                    MMA_BF16(acc[mt][nt], ahi, bh[nt]);
                    MMA_BF16(acc[mt][nt], ahi, bl[nt]);
                    MMA_BF16(acc[mt][nt], alo, bh[nt]);
                }
            }
        }
    }

    // epilogue: write XG as bf16 hi/lo pairs
    int row0 = bm * 128 + warp_m + (lane >> 2);
    #pragma unroll
    for (int mt = 0; mt < 4; mt++) {
        #pragma unroll
        for (int nt = 0; nt < 4; nt++) {
            int j = bn * 128 + warp_n + nt * 8 + (lane & 3) * 2;
            int b = j >> 6, c = j & 63;
            size_t p0 = (size_t)(row0 + mt * 16) * XGPITCH + b * CC + coff + c;
            size_t p1 = p0 + (size_t)8 * XGPITCH;
            float a0 = acc[mt][nt][0], a1 = acc[mt][nt][1];
            float a2 = acc[mt][nt][2], a3 = acc[mt][nt][3];
            __nv_bfloat162 h01, l01, h23, l23;
            h01.x = __float2bfloat16(a0); h01.y = __float2bfloat16(a1);
            l01.x = __float2bfloat16(a0 - __bfloat162float(h01.x));
            l01.y = __float2bfloat16(a1 - __bfloat162float(h01.y));
            h23.x = __float2bfloat16(a2); h23.y = __float2bfloat16(a3);
            l23.x = __float2bfloat16(a2 - __bfloat162float(h23.x));
            l23.y = __float2bfloat16(a3 - __bfloat162float(h23.y));
            *reinterpret_cast<__nv_bfloat162*>(g_XGhi + p0) = h01;
            *reinterpret_cast<__nv_bfloat162*>(g_XGlo + p0) = l01;
            *reinterpret_cast<__nv_bfloat162*>(g_XGhi + p1) = h23;
            *reinterpret_cast<__nv_bfloat162*>(g_XGlo + p1) = l23;
        }
    }
}

// ================ per-node gate GEMM (tensorized) + sigmoid ======================
#define NG_XHI 0
#define NG_XLO 16384
#define NG_WHI 32768
#define NG_WLO 65536
#define NG_BIAS 98304
#define NG_SMEM 98816

__global__ __launch_bounds__(128, 2) void k_ngate(const float* __restrict__ ne,
                                                  const float* __restrict__ gbp) {
    extern __shared__ char dsm[];
    uint32_t sb = smem_u32(dsm);
    int n = blockIdx.x, tid = threadIdx.x, lane = tid & 31, wid = tid >> 5;

    #pragma unroll
    for (int i = 0; i < 8; i++) {
        int id = i * 128 + tid;
        int r = id >> 4, c = id & 15;
        uint32_t off = swz256(r, c);
        size_t g = (size_t)n * XGPITCH + r * 128 + c * 8;
        cpa16(sb + NG_XHI + off, g_XGhi + g);
        cpa16(sb + NG_XLO + off, g_XGlo + g);
    }
    #pragma unroll
    for (int i = 0; i < 16; i++) {
        int id = i * 128 + tid;
        int r = id >> 4, c = id & 15;
        uint32_t off = swz256(r, c);
        size_t g = (size_t)n * (CC * CC) + r * 128 + c * 8;
        cpa16(sb + NG_WHI + off, g_Wghi + g);
        cpa16(sb + NG_WLO + off, g_Wglo + g);
    }
    CP_COMMIT();

    {
        float v = 0.0f;
        #pragma unroll
        for (int d = 0; d < EE; d++) v += ne[n * EE + d] * gbp[d * CC + tid];
        reinterpret_cast<float*>(dsm + NG_BIAS)[tid] = v;
    }
    CP_WAIT0();
    __syncthreads();

    int warp_n = wid * 32;
    int lrow = lane & 15, lgrp = lane >> 4;
    float acc[4][4][4] = {};

    #pragma unroll
    for (int k16 = 0; k16 < 8; k16++) {
        uint32_t bh[4][2], bl[4][2];
        #pragma unroll
        for (int half = 0; half < 2; half++) {
            uint32_t off = swz256(k16 * 16 + lrow, (warp_n >> 3) + half * 2 + lgrp);
            uint32_t t0, t1, t2, t3;
            LDSM4T(t0, t1, t2, t3, sb + NG_WHI + off);
            bh[half * 2][0] = t0; bh[half * 2][1] = t1;
            bh[half * 2 + 1][0] = t2; bh[half * 2 + 1][1] = t3;
            LDSM4T(t0, t1, t2, t3, sb + NG_WLO + off);
            bl[half * 2][0] = t0; bl[half * 2][1] = t1;
            bl[half * 2 + 1][0] = t2; bl[half * 2 + 1][1] = t3;
        }
        #pragma unroll
        for (int mt = 0; mt < 4; mt++) {
            uint32_t off = swz256(mt * 16 + lrow, k16 * 2 + lgrp);
            uint32_t ah[4], al[4];
            LDSM4(ah[0], ah[1], ah[2], ah[3], sb + NG_XHI + off);
            LDSM4(al[0], al[1], al[2], al[3], sb + NG_XLO + off);
            #pragma unroll
            for (int nb = 0; nb < 4; nb++) {
                MMA_BF16(acc[mt][nb], ah, bh[nb]);
                MMA_BF16(acc[mt][nb], ah, bl[nb]);
                MMA_BF16(acc[mt][nb], al, bh[nb]);
            }
        }
    }

    const float* biasp = reinterpret_cast<const float*>(dsm + NG_BIAS);
    #pragma unroll
    for (int mt = 0; mt < 4; mt++) {
        #pragma unroll
        for (int nb = 0; nb < 4; nb++) {
            int o = warp_n + nb * 8 + (lane & 3) * 2;
            int b = mt * 16 + (lane >> 2);
            float b0 = biasp[o], b1 = biasp[o + 1];
            float y0 = 1.0f / (1.0f + __expf(-(acc[mt][nb][0] + b0)));
            float y1 = 1.0f / (1.0f + __expf(-(acc[mt][nb][1] + b1)));
            float y2 = 1.0f / (1.0f + __expf(-(acc[mt][nb][2] + b0)));
            float y3 = 1.0f / (1.0f + __expf(-(acc[mt][nb][3] + b1)));
            *reinterpret_cast<float2*>(g_ZR + (size_t)n * XGPITCH + b * CC + o) =
                make_float2(y0, y1);
            *reinterpret_cast<float2*>(g_ZR + (size_t)n * XGPITCH + (b + 8) * CC + o) =
                make_float2(y2, y3);
        }
    }
}

// ================ per-node update GEMM + tanh + GRU combine ======================
#define NF_XHI 0
#define NF_XLO 16384
#define NF_WHI 32768
#define NF_WLO 49152
#define NF_BIAS 65536
#define NF_SMEM 65792

__global__ __launch_bounds__(128, 3) void k_nfinal(const float* __restrict__ ne,
                                                   const float* __restrict__ ubp,
                                                   const float* __restrict__ st,
                                                   float* __restrict__ out) {
    extern __shared__ char dsm[];
    uint32_t sb = smem_u32(dsm);
    int n = blockIdx.x, tid = threadIdx.x, lane = tid & 31, wid = tid >> 5;

    #pragma unroll
    for (int i = 0; i < 8; i++) {
        int id = i * 128 + tid;
        int r = id >> 4, c = id & 15;
        uint32_t off = swz256(r, c);
        size_t g = (size_t)n * XGPITCH + r * 128 + c * 8;
        cpa16(sb + NF_XHI + off, g_XGhi + g);
        cpa16(sb + NF_XLO + off, g_XGlo + g);
    }
    #pragma unroll
    for (int i = 0; i < 8; i++) {
        int id = i * 128 + tid;
        int r = id >> 3, c = id & 7;
        uint32_t off = swz128(r, c);
        size_t g = (size_t)n * (CC * DH) + r * 64 + c * 8;
        cpa16(sb + NF_WHI + off, g_Wuhi + g);
        cpa16(sb + NF_WLO + off, g_Wulo + g);
    }
    CP_COMMIT();

    if (tid < DH) {
        float v = 0.0f;
        #pragma unroll
        for (int d = 0; d < EE; d++) v += ne[n * EE + d] * ubp[d * DH + tid];
        reinterpret_cast<float*>(dsm + NF_BIAS)[tid] = v;
    }
    CP_WAIT0();
    __syncthreads();

    int warp_m = (wid >> 1) * 32;
    int warp_n = (wid & 1) * 32;
    int lrow = lane & 15, lgrp = lane >> 4;
    float acc[2][4][4] = {};

    #pragma unroll
    for (int k16 = 0; k16 < 8; k16++) {
        uint32_t bh[4][2], bl[4][2];
        #pragma unroll
        for (int half = 0; half < 2; half++) {
            uint32_t off = swz128(k16 * 16 + lrow, (warp_n >> 3) + half * 2 + lgrp);
            uint32_t t0, t1, t2, t3;
            LDSM4T(t0, t1, t2, t3, sb + NF_WHI + off);
            bh[half * 2][0] = t0; bh[half * 2][1] = t1;
            bh[half * 2 + 1][0] = t2; bh[half * 2 + 1][1] = t3;
            LDSM4T(t0, t1, t2, t3, sb + NF_WLO + off);
            bl[half * 2][0] = t0; bl[half * 2][1] = t1;
            bl[half * 2 + 1][0] = t2; bl[half * 2 + 1][1] = t3;
        }
        #pragma unroll
        for (int mt = 0; mt < 2; mt++) {
            uint32_t off = swz256(warp_m + mt * 16 + lrow, k16 * 2 + lgrp);
            uint32_t ah[4], al[4];
            LDSM4(ah[0], ah[1], ah[2], ah[3], sb + NF_XHI + off);
            LDSM4(al[0], al[1], al[2], al[3], sb + NF_XLO + off);
            #pragma unroll
            for (int nb = 0; nb < 4; nb++) {
                MMA_BF16(acc[mt][nb], ah, bh[nb]);
                MMA_BF16(acc[mt][nb], ah, bl[nb]);
                MMA_BF16(acc[mt][nb], al, bh[nb]);
            }
        }
    }

    const float* biasp = reinterpret_cast<const float*>(dsm + NF_BIAS);
    #pragma unroll
    for (int mt = 0; mt < 2; mt++) {
        #pragma unroll
        for (int nb = 0; nb < 4; nb++) {
            int o = warp_n + nb * 8 + (lane & 3) * 2;
            float b0 = biasp[o], b1 = biasp[o + 1];
            #pragma unroll
            for (int h = 0; h < 2; h++) {
                int b = warp_m + mt * 16 + (lane >> 2) + h * 8;
                float hc0 = tanhf(acc[mt][nb][h * 2] + b0);
                float hc1 = tanhf(acc[mt][nb][h * 2 + 1] + b1);
                float2 rr = *reinterpret_cast<const float2*>(
                    g_ZR + (size_t)n * XGPITCH + b * CC + DH + o);
                float2 ss = *reinterpret_cast<const float2*>(
                    st + ((size_t)b * NN + n) * DH + o);
                float2 hv;
                hv.x = rr.x * ss.x + (1.0f - rr.x) * hc0;
                hv.y = rr.y * ss.y + (1.0f - rr.y) * hc1;
                *reinterpret_cast<float2*>(out + ((size_t)b * NN + n) * DH + o) = hv;
            }
        }
    }
}

// ================ launch =========================================================
extern "C" void kernel_launch(void* const* d_in, const int* in_sizes, int n_in,
                              void* d_out, int out_size) {
    const float* x   = (const float*)d_in[0];
    const float* st  = (const float*)d_in[1];
    const float* ne  = (const float*)d_in[2];
    const float* gwp = (const float*)d_in[3];
    const float* gbp = (const float*)d_in[4];
    const float* uwp = (const float*)d_in[5];
    const float* ubp = (const float*)d_in[6];
    float* out = (float*)d_out;

    static int smem_set = 0;
    if (!smem_set) {
        cudaFuncSetAttribute(k_hgemm,  cudaFuncAttributeMaxDynamicSharedMemorySize, GEMM_SMEM);
        cudaFuncSetAttribute(k_ngate,  cudaFuncAttributeMaxDynamicSharedMemorySize, NG_SMEM);
        cudaFuncSetAttribute(k_nfinal, cudaFuncAttributeMaxDynamicSharedMemorySize, NF_SMEM);
        smem_set = 1;
    }

    __nv_bfloat16 *bxh, *bxl, *bsh, *bsl, *wgh, *wgl, *wuh, *wul;
    cudaGetSymbolAddress((void**)&bxh, g_BXhi);
    cudaGetSymbolAddress((void**)&bxl, g_BXlo);
    cudaGetSymbolAddress((void**)&bsh, g_BShi);
    cudaGetSymbolAddress((void**)&bsl, g_BSlo);
    cudaGetSymbolAddress((void**)&wgh, g_Wghi);
    cudaGetSymbolAddress((void**)&wgl, g_Wglo);
    cudaGetSymbolAddress((void**)&wuh, g_Wuhi);
    cudaGetSymbolAddress((void**)&wul, g_Wulo);

    k_supports<<<NN, 256>>>(ne);                            // 0
    k_trans<<<dim3(NN / 64, BB), 256>>>(x, bxh, bxl, 0);    // 1
    k_trans<<<dim3(NN / 64, BB), 256>>>(st, bsh, bsl, 0);   // 2

    // merged S@x | S@state : 2048 CTAs -> 6.92 waves (vs 2 x 3.46->4)
    k_hgemm<<<dim3(2 * NN / 128, NN / 128), 256, GEMM_SMEM>>>(
        bxh, bxl, 0, bsh, bsl, NN / 128);                   // 3 (profiled)

    k_mkw<<<(CC * CC) / 256, 256>>>(ne, gwp, wgh, wgl, CC * CC);
    k_ngate<<<NN, 128, NG_SMEM>>>(ne, gbp);

    // update path
    k_trans<<<dim3(NN / 64, BB), 256>>>(st, bsh, bsl, 1);   // (z*state)^T
    k_mkw<<<(CC * DH) / 256, 256>>>(ne, uwp, wuh, wul, CC * DH);
    k_hgemm<<<dim3(NN / 128, NN / 128), 256, GEMM_SMEM>>>(
        bsh, bsl, 64, bsh, bsl, NN / 128);
    k_nfinal<<<NN, 128, NF_SMEM>>>(ne, ubp, st, out);
}

// round 10
// speedup vs baseline: 1.0862x; 1.0027x over previous
#include <cuda_runtime.h>
#include <cuda_bf16.h>
#include <math.h>
#include <stdint.h>

#define NN 4096
#define BB 64
#define DIN 64
#define DH 64
#define CC 128              // DIN + DH
#define EE 16
#define XGPITCH (BB * CC)   // 8192

// ================= device scratch (no runtime allocs) ==========================
__device__ __nv_bfloat16 g_Shi[(size_t)NN * NN];     // supports hi (A operand)
__device__ __nv_bfloat16 g_Slo[(size_t)NN * NN];     // supports lo
__device__ __nv_bfloat16 g_BXhi[(size_t)NN * NN];    // x^T hi    [j=b*64+c][m]
__device__ __nv_bfloat16 g_BXlo[(size_t)NN * NN];
__device__ __nv_bfloat16 g_BShi[(size_t)NN * NN];    // state^T / (z*state)^T
__device__ __nv_bfloat16 g_BSlo[(size_t)NN * NN];
__device__ __nv_bfloat16 g_XGhi[(size_t)NN * XGPITCH]; // S@CAT hi  [n][b*128+i]
__device__ __nv_bfloat16 g_XGlo[(size_t)NN * XGPITCH]; // S@CAT lo
__device__ __nv_bfloat16 g_Wghi[(size_t)NN * CC * CC]; // gate W hi [n][i][o]
__device__ __nv_bfloat16 g_Wglo[(size_t)NN * CC * CC];
__device__ __nv_bfloat16 g_Wuhi[(size_t)NN * CC * DH]; // update W hi [n][i][o]
__device__ __nv_bfloat16 g_Wulo[(size_t)NN * CC * DH];
__device__ float g_ZR[(size_t)NN * XGPITCH];           // z_r [n][b*128+j]

// ================= PTX helpers (sm_80-level only; NO tcgen05) ====================
__device__ __forceinline__ uint32_t smem_u32(const void* p) {
    uint32_t a;
    asm("{ .reg .u64 t; cvta.to.shared.u64 t, %1; cvt.u32.u64 %0, t; }" : "=r"(a) : "l"(p));
    return a;
}
__device__ __forceinline__ void cpa16(uint32_t dst, const void* src) {
    asm volatile("cp.async.cg.shared.global [%0], [%1], 16;" :: "r"(dst), "l"(src));
}
#define CP_COMMIT() asm volatile("cp.async.commit_group;" ::: "memory")
#define CP_WAIT1()  asm volatile("cp.async.wait_group 1;" ::: "memory")
#define CP_WAIT0()  asm volatile("cp.async.wait_group 0;" ::: "memory")

#define LDSM4(r0, r1, r2, r3, addr) \
    asm volatile("ldmatrix.sync.aligned.m8n8.x4.shared.b16 {%0,%1,%2,%3}, [%4];" \
        : "=r"(r0), "=r"(r1), "=r"(r2), "=r"(r3) : "r"(addr))

#define LDSM4T(r0, r1, r2, r3, addr) \
    asm volatile("ldmatrix.sync.aligned.m8n8.x4.trans.shared.b16 {%0,%1,%2,%3}, [%4];" \
        : "=r"(r0), "=r"(r1), "=r"(r2), "=r"(r3) : "r"(addr))

#define MMA_BF16(c, a, b) \
    asm volatile("mma.sync.aligned.m16n8k16.row.col.f32.bf16.bf16.f32 " \
        "{%0,%1,%2,%3}, {%4,%5,%6,%7}, {%8,%9}, {%0,%1,%2,%3};" \
        : "+f"((c)[0]), "+f"((c)[1]), "+f"((c)[2]), "+f"((c)[3]) \
        : "r"((a)[0]), "r"((a)[1]), "r"((a)[2]), "r"((a)[3]), \
          "r"((b)[0]), "r"((b)[1]))

// ================ supports = softmax(relu(NE @ NE^T)) -> bf16 hi/lo ==============
__global__ __launch_bounds__(256) void k_supports(const float* __restrict__ ne) {
    int n = blockIdx.x, tid = threadIdx.x;
    __shared__ float e[EE];
    __shared__ float redm[8], reds[8];
    if (tid < EE) e[tid] = ne[n * EE + tid];
    __syncthreads();

    float vals[16];
    float mx = 0.0f;
    #pragma unroll
    for (int j = 0; j < 16; j++) {
        int m = tid + j * 256;
        const float4* p = reinterpret_cast<const float4*>(ne + m * EE);
        float4 v0 = p[0], v1 = p[1], v2 = p[2], v3 = p[3];
        float d = e[0]*v0.x + e[1]*v0.y + e[2]*v0.z + e[3]*v0.w
                + e[4]*v1.x + e[5]*v1.y + e[6]*v1.z + e[7]*v1.w
                + e[8]*v2.x + e[9]*v2.y + e[10]*v2.z + e[11]*v2.w
                + e[12]*v3.x + e[13]*v3.y + e[14]*v3.z + e[15]*v3.w;
        d = fmaxf(d, 0.0f);
        vals[j] = d;
        mx = fmaxf(mx, d);
    }
    #pragma unroll
    for (int o = 16; o > 0; o >>= 1) mx = fmaxf(mx, __shfl_xor_sync(0xffffffffu, mx, o));
    if ((tid & 31) == 0) redm[tid >> 5] = mx;
    __syncthreads();
    mx = redm[0];
    #pragma unroll
    for (int w = 1; w < 8; w++) mx = fmaxf(mx, redm[w]);

    float s = 0.0f;
    #pragma unroll
    for (int j = 0; j < 16; j++) { vals[j] = __expf(vals[j] - mx); s += vals[j]; }
    #pragma unroll
    for (int o = 16; o > 0; o >>= 1) s += __shfl_xor_sync(0xffffffffu, s, o);
    if ((tid & 31) == 0) reds[tid >> 5] = s;
    __syncthreads();
    s = 0.0f;
    #pragma unroll
    for (int w = 0; w < 8; w++) s += reds[w];
    float inv = 1.0f / s;
    #pragma unroll
    for (int j = 0; j < 16; j++) {
        float v = vals[j] * inv;
        __nv_bfloat16 h = __float2bfloat16(v);
        size_t o = (size_t)n * NN + tid + j * 256;
        g_Shi[o] = h;
        g_Slo[o] = __float2bfloat16(v - __bfloat162float(h));
    }
}

// ================ per-node weights -> bf16 hi/lo, layout [n][i][o] ===============
__global__ __launch_bounds__(256) void k_mkw(const float* __restrict__ ne,
                                             const float* __restrict__ wp,
                                             __nv_bfloat16* __restrict__ whi,
                                             __nv_bfloat16* __restrict__ wlo,
                                             int IO) {
    int io = blockIdx.x * 256 + threadIdx.x;
    float wv[EE];
    #pragma unroll
    for (int d = 0; d < EE; d++) wv[d] = wp[(size_t)d * IO + io];
    __shared__ float sne[128 * EE];
    for (int n0 = 0; n0 < NN; n0 += 128) {
        __syncthreads();
        for (int t = threadIdx.x; t < 128 * EE; t += 256) sne[t] = ne[n0 * EE + t];
        __syncthreads();
        for (int nn = 0; nn < 128; nn++) {
            float v = 0.0f;
            #pragma unroll
            for (int d = 0; d < EE; d++) v += sne[nn * EE + d] * wv[d];
            __nv_bfloat16 h = __float2bfloat16(v);
            size_t o = (size_t)(n0 + nn) * IO + io;
            whi[o] = h;
            wlo[o] = __float2bfloat16(v - __bfloat162float(h));
        }
    }
}

// ================ transpose + hi/lo split: B operand build =======================
__global__ __launch_bounds__(256) void k_trans(const float* __restrict__ src,
                                               __nv_bfloat16* __restrict__ dhi,
                                               __nv_bfloat16* __restrict__ dlo,
                                               int zmul) {
    __shared__ float tile[64][68];
    int b = blockIdx.y, m0 = blockIdx.x * 64, tid = threadIdx.x;
    #pragma unroll
    for (int i = 0; i < 4; i++) {
        int id = i * 256 + tid;
        int r = id >> 4, c4 = id & 15;
        float4 v = *reinterpret_cast<const float4*>(
            src + ((size_t)b * NN + m0 + r) * 64 + c4 * 4);
        if (zmul) {
            float4 z = *reinterpret_cast<const float4*>(
                g_ZR + (size_t)(m0 + r) * XGPITCH + b * CC + c4 * 4);
            v.x *= z.x; v.y *= z.y; v.z *= z.z; v.w *= z.w;
        }
        *reinterpret_cast<float4*>(&tile[r][c4 * 4]) = v;
    }
    __syncthreads();
    int c = tid >> 2, mg = (tid & 3) * 16;
    uint32_t hi[8], lo[8];
    #pragma unroll
    for (int p = 0; p < 8; p++) {
        float v0 = tile[mg + 2 * p][c], v1 = tile[mg + 2 * p + 1][c];
        __nv_bfloat16 h0 = __float2bfloat16(v0);
        __nv_bfloat16 h1 = __float2bfloat16(v1);
        float l0 = v0 - __bfloat162float(h0);
        float l1 = v1 - __bfloat162float(h1);
        __nv_bfloat162 hp; hp.x = h0; hp.y = h1;
        __nv_bfloat162 lp = __floats2bfloat162_rn(l0, l1);
        hi[p] = *reinterpret_cast<uint32_t*>(&hp);
        lo[p] = *reinterpret_cast<uint32_t*>(&lp);
    }
    size_t o = (size_t)(b * 64 + c) * NN + m0 + mg;
    *reinterpret_cast<uint4*>(dhi + o)     = make_uint4(hi[0], hi[1], hi[2], hi[3]);
    *reinterpret_cast<uint4*>(dhi + o + 8) = make_uint4(hi[4], hi[5], hi[6], hi[7]);
    *reinterpret_cast<uint4*>(dlo + o)     = make_uint4(lo[0], lo[1], lo[2], lo[3]);
    *reinterpret_cast<uint4*>(dlo + o + 8) = make_uint4(lo[4], lo[5], lo[6], lo[7]);
}

// ================ big GEMM via mma.sync bf16, split-precision (3 terms) ==========
// CTA tile 128(M) x 128(N), K-chunk 32 (64B rows), 3-stage, 2 CTAs/SM.
// Dual-B: bn < split -> (Bh0,Bl0) with coff0; else (Bh1,Bl1) with coff 64.
#define OFF_ALO  8192
#define OFF_BHI 16384
#define OFF_BLO 24576
#define STAGE_BYTES 32768
#define GEMM_SMEM (3 * STAGE_BYTES)  // 96 KB

__device__ __forceinline__ uint32_t swz64(int r, int c) {
    return (uint32_t)(r * 64 + ((c ^ (r & 3) ^ ((r >> 2) & 1)) << 4));
}
__device__ __forceinline__ uint32_t swz256(int r, int c) {
    return (uint32_t)(r * 256 + ((c ^ (r & 7)) << 4));
}
__device__ __forceinline__ uint32_t swz128(int r, int c) {
    return (uint32_t)(r * 128 + ((c ^ (r & 7)) << 4));
}

__device__ __forceinline__ void load_stage(uint32_t base, int kt, int tid,
        const __nv_bfloat16* Ah, const __nv_bfloat16* Al,
        const __nv_bfloat16* Bh, const __nv_bfloat16* Bl) {
    int k0 = kt * 32;
    #pragma unroll
    for (int i = 0; i < 2; i++) {
        int id = i * 256 + tid;
        int r = id >> 2, c = id & 3;
        uint32_t off = swz64(r, c);
        size_t g = (size_t)r * NN + k0 + c * 8;
        cpa16(base + off,           Ah + g);
        cpa16(base + OFF_ALO + off, Al + g);
    }
    #pragma unroll
    for (int i = 0; i < 2; i++) {
        int id = i * 256 + tid;
        int r = id >> 2, c = id & 3;
        uint32_t off = swz64(r, c);
        size_t g = (size_t)r * NN + k0 + c * 8;
        cpa16(base + OFF_BHI + off, Bh + g);
        cpa16(base + OFF_BLO + off, Bl + g);
    }
    CP_COMMIT();
}

__global__ __launch_bounds__(256, 2) void k_hgemm(
        const __nv_bfloat16* __restrict__ Bhi0,
        const __nv_bfloat16* __restrict__ Blo0,
        int coff0,
        const __nv_bfloat16* __restrict__ Bhi1,
        const __nv_bfloat16* __restrict__ Blo1,
        int split) {
    extern __shared__ char dsm[];
    uint32_t sb = smem_u32(dsm);
    int tid = threadIdx.x, lane = tid & 31, wid = tid >> 5;
    int bn = blockIdx.x, bm = blockIdx.y;

    // uniform (blockIdx-only) operand select — no per-thread divergence
    const __nv_bfloat16 *Bhp, *Blp;
    int coff;
    if (bn < split) { Bhp = Bhi0; Blp = Blo0; coff = coff0; }
    else            { Bhp = Bhi1; Blp = Blo1; coff = 64; bn -= split; }

    const __nv_bfloat16* Ah = g_Shi + (size_t)(bm * 128) * NN;
    const __nv_bfloat16* Al = g_Slo + (size_t)(bm * 128) * NN;
    const __nv_bfloat16* Bh = Bhp + (size_t)(bn * 128) * NN;
    const __nv_bfloat16* Bl = Blp + (size_t)(bn * 128) * NN;

    int warp_m = (wid >> 2) * 64;
    int warp_n = (wid & 3) * 32;
    float acc[4][4][4] = {};

    load_stage(sb, 0, tid, Ah, Al, Bh, Bl);
    load_stage(sb + STAGE_BYTES, 1, tid, Ah, Al, Bh, Bl);

    const int NKT = NN / 32;
    int lrowA = lane & 15, lgrp = lane >> 4;

    for (int kt = 0; kt < NKT; kt++) {
        CP_WAIT1();
        __syncthreads();

        if (kt + 2 < NKT)
            load_stage(sb + ((kt + 2) % 3) * STAGE_BYTES, kt + 2, tid, Ah, Al, Bh, Bl);
        else
            CP_COMMIT();

        uint32_t base = sb + (kt % 3) * STAGE_BYTES;
        #pragma unroll
        for (int s = 0; s < 2; s++) {
            int cb = s * 2 + lgrp;
            uint32_t bh[4][2], bl[4][2];
            #pragma unroll
            for (int ng = 0; ng < 2; ng++) {
                int r = warp_n + ng * 16 + lrowA;
                uint32_t off = swz64(r, cb);
                uint32_t t0, t1, t2, t3;
                LDSM4(t0, t1, t2, t3, base + OFF_BHI + off);
                bh[ng * 2][0] = t0; bh[ng * 2][1] = t2;
                bh[ng * 2 + 1][0] = t1; bh[ng * 2 + 1][1] = t3;
                LDSM4(t0, t1, t2, t3, base + OFF_BLO + off);
                bl[ng * 2][0] = t0; bl[ng * 2][1] = t2;
                bl[ng * 2 + 1][0] = t1; bl[ng * 2 + 1][1] = t3;
            }
            #pragma unroll
            for (int mt = 0; mt < 4; mt++) {
                int r = warp_m + mt * 16 + lrowA;
                uint32_t off = swz64(r, cb);
                uint32_t ahi[4], alo[4];
                LDSM4(ahi[0], ahi[1], ahi[2], ahi[3], base + off);
                LDSM4(alo[0], alo[1], alo[2], alo[3], base + OFF_ALO + off);
                #pragma unroll
                for (int nt = 0; nt < 4; nt++) {
                    MMA_BF16(acc[mt][nt], ahi, bh[nt]);
                    MMA_BF16(acc[mt][nt], ahi, bl[nt]);
                    MMA_BF16(acc[mt][nt], alo, bh[nt]);
                }
            }
        }
    }

    // epilogue: write XG as bf16 hi/lo pairs
    int row0 = bm * 128 + warp_m + (lane >> 2);
    #pragma unroll
    for (int mt = 0; mt < 4; mt++) {
        #pragma unroll
        for (int nt = 0; nt < 4; nt++) {
            int j = bn * 128 + warp_n + nt * 8 + (lane & 3) * 2;
            int b = j >> 6, c = j & 63;
            size_t p0 = (size_t)(row0 + mt * 16) * XGPITCH + b * CC + coff + c;
            size_t p1 = p0 + (size_t)8 * XGPITCH;
            float a0 = acc[mt][nt][0], a1 = acc[mt][nt][1];
            float a2 = acc[mt][nt][2], a3 = acc[mt][nt][3];
            __nv_bfloat162 h01, l01, h23, l23;
            h01.x = __float2bfloat16(a0); h01.y = __float2bfloat16(a1);
            l01.x = __float2bfloat16(a0 - __bfloat162float(h01.x));
            l01.y = __float2bfloat16(a1 - __bfloat162float(h01.y));
            h23.x = __float2bfloat16(a2); h23.y = __float2bfloat16(a3);
            l23.x = __float2bfloat16(a2 - __bfloat162float(h23.x));
            l23.y = __float2bfloat16(a3 - __bfloat162float(h23.y));
            *reinterpret_cast<__nv_bfloat162*>(g_XGhi + p0) = h01;
            *reinterpret_cast<__nv_bfloat162*>(g_XGlo + p0) = l01;
            *reinterpret_cast<__nv_bfloat162*>(g_XGhi + p1) = h23;
            *reinterpret_cast<__nv_bfloat162*>(g_XGlo + p1) = l23;
        }
    }
}

// ================ per-node gate GEMM (tensorized) + sigmoid ======================
#define NG_XHI 0
#define NG_XLO 16384
#define NG_WHI 32768
#define NG_WLO 65536
#define NG_BIAS 98304
#define NG_SMEM 98816

__global__ __launch_bounds__(128, 2) void k_ngate(const float* __restrict__ ne,
                                                  const float* __restrict__ gbp) {
    extern __shared__ char dsm[];
    uint32_t sb = smem_u32(dsm);
    int n = blockIdx.x, tid = threadIdx.x, lane = tid & 31, wid = tid >> 5;

    #pragma unroll
    for (int i = 0; i < 8; i++) {
        int id = i * 128 + tid;
        int r = id >> 4, c = id & 15;
        uint32_t off = swz256(r, c);
        size_t g = (size_t)n * XGPITCH + r * 128 + c * 8;
        cpa16(sb + NG_XHI + off, g_XGhi + g);
        cpa16(sb + NG_XLO + off, g_XGlo + g);
    }
    #pragma unroll
    for (int i = 0; i < 16; i++) {
        int id = i * 128 + tid;
        int r = id >> 4, c = id & 15;
        uint32_t off = swz256(r, c);
        size_t g = (size_t)n * (CC * CC) + r * 128 + c * 8;
        cpa16(sb + NG_WHI + off, g_Wghi + g);
        cpa16(sb + NG_WLO + off, g_Wglo + g);
    }
    CP_COMMIT();

    {
        float v = 0.0f;
        #pragma unroll
        for (int d = 0; d < EE; d++) v += ne[n * EE + d] * gbp[d * CC + tid];
        reinterpret_cast<float*>(dsm + NG_BIAS)[tid] = v;
    }
    CP_WAIT0();
    __syncthreads();

    int warp_n = wid * 32;
    int lrow = lane & 15, lgrp = lane >> 4;
    float acc[4][4][4] = {};

    #pragma unroll
    for (int k16 = 0; k16 < 8; k16++) {
        uint32_t bh[4][2], bl[4][2];
        #pragma unroll
        for (int half = 0; half < 2; half++) {
            uint32_t off = swz256(k16 * 16 + lrow, (warp_n >> 3) + half * 2 + lgrp);
            uint32_t t0, t1, t2, t3;
            LDSM4T(t0, t1, t2, t3, sb + NG_WHI + off);
            bh[half * 2][0] = t0; bh[half * 2][1] = t1;
            bh[half * 2 + 1][0] = t2; bh[half * 2 + 1][1] = t3;
            LDSM4T(t0, t1, t2, t3, sb + NG_WLO + off);
            bl[half * 2][0] = t0; bl[half * 2][1] = t1;
            bl[half * 2 + 1][0] = t2; bl[half * 2 + 1][1] = t3;
        }
        #pragma unroll
        for (int mt = 0; mt < 4; mt++) {
            uint32_t off = swz256(mt * 16 + lrow, k16 * 2 + lgrp);
            uint32_t ah[4], al[4];
            LDSM4(ah[0], ah[1], ah[2], ah[3], sb + NG_XHI + off);
            LDSM4(al[0], al[1], al[2], al[3], sb + NG_XLO + off);
            #pragma unroll
            for (int nb = 0; nb < 4; nb++) {
                MMA_BF16(acc[mt][nb], ah, bh[nb]);
                MMA_BF16(acc[mt][nb], ah, bl[nb]);
                MMA_BF16(acc[mt][nb], al, bh[nb]);
            }
        }
    }

    const float* biasp = reinterpret_cast<const float*>(dsm + NG_BIAS);
    #pragma unroll
    for (int mt = 0; mt < 4; mt++) {
        #pragma unroll
        for (int nb = 0; nb < 4; nb++) {
            int o = warp_n + nb * 8 + (lane & 3) * 2;
            int b = mt * 16 + (lane >> 2);
            float b0 = biasp[o], b1 = biasp[o + 1];
            float y0 = 1.0f / (1.0f + __expf(-(acc[mt][nb][0] + b0)));
            float y1 = 1.0f / (1.0f + __expf(-(acc[mt][nb][1] + b1)));
            float y2 = 1.0f / (1.0f + __expf(-(acc[mt][nb][2] + b0)));
            float y3 = 1.0f / (1.0f + __expf(-(acc[mt][nb][3] + b1)));
            *reinterpret_cast<float2*>(g_ZR + (size_t)n * XGPITCH + b * CC + o) =
                make_float2(y0, y1);
            *reinterpret_cast<float2*>(g_ZR + (size_t)n * XGPITCH + (b + 8) * CC + o) =
                make_float2(y2, y3);
        }
    }
}

// ================ per-node update GEMM + tanh + GRU combine ======================
#define NF_XHI 0
#define NF_XLO 16384
#define NF_WHI 32768
#define NF_WLO 49152
#define NF_BIAS 65536
#define NF_SMEM 65792

__global__ __launch_bounds__(128, 3) void k_nfinal(const float* __restrict__ ne,
                                                   const float* __restrict__ ubp,
                                                   const float* __restrict__ st,
                                                   float* __restrict__ out) {
    extern __shared__ char dsm[];
    uint32_t sb = smem_u32(dsm);
    int n = blockIdx.x, tid = threadIdx.x, lane = tid & 31, wid = tid >> 5;

    #pragma unroll
    for (int i = 0; i < 8; i++) {
        int id = i * 128 + tid;
        int r = id >> 4, c = id & 15;
        uint32_t off = swz256(r, c);
        size_t g = (size_t)n * XGPITCH + r * 128 + c * 8;
        cpa16(sb + NF_XHI + off, g_XGhi + g);
        cpa16(sb + NF_XLO + off, g_XGlo + g);
    }
    #pragma unroll
    for (int i = 0; i < 8; i++) {
        int id = i * 128 + tid;
        int r = id >> 3, c = id & 7;
        uint32_t off = swz128(r, c);
        size_t g = (size_t)n * (CC * DH) + r * 64 + c * 8;
        cpa16(sb + NF_WHI + off, g_Wuhi + g);
        cpa16(sb + NF_WLO + off, g_Wulo + g);
    }
    CP_COMMIT();

    if (tid < DH) {
        float v = 0.0f;
        #pragma unroll
        for (int d = 0; d < EE; d++) v += ne[n * EE + d] * ubp[d * DH + tid];
        reinterpret_cast<float*>(dsm + NF_BIAS)[tid] = v;
    }
    CP_WAIT0();
    __syncthreads();

    int warp_m = (wid >> 1) * 32;
    int warp_n = (wid & 1) * 32;
    int lrow = lane & 15, lgrp = lane >> 4;
    float acc[2][4][4] = {};

    #pragma unroll
    for (int k16 = 0; k16 < 8; k16++) {
        uint32_t bh[4][2], bl[4][2];
        #pragma unroll
        for (int half = 0; half < 2; half++) {
            uint32_t off = swz128(k16 * 16 + lrow, (warp_n >> 3) + half * 2 + lgrp);
            uint32_t t0, t1, t2, t3;
            LDSM4T(t0, t1, t2, t3, sb + NF_WHI + off);
            bh[half * 2][0] = t0; bh[half * 2][1] = t1;
            bh[half * 2 + 1][0] = t2; bh[half * 2 + 1][1] = t3;
            LDSM4T(t0, t1, t2, t3, sb + NF_WLO + off);
            bl[half * 2][0] = t0; bl[half * 2][1] = t1;
            bl[half * 2 + 1][0] = t2; bl[half * 2 + 1][1] = t3;
        }
        #pragma unroll
        for (int mt = 0; mt < 2; mt++) {
            uint32_t off = swz256(warp_m + mt * 16 + lrow, k16 * 2 + lgrp);
            uint32_t ah[4], al[4];
            LDSM4(ah[0], ah[1], ah[2], ah[3], sb + NF_XHI + off);
            LDSM4(al[0], al[1], al[2], al[3], sb + NF_XLO + off);
            #pragma unroll
            for (int nb = 0; nb < 4; nb++) {
                MMA_BF16(acc[mt][nb], ah, bh[nb]);
                MMA_BF16(acc[mt][nb], ah, bl[nb]);
                MMA_BF16(acc[mt][nb], al, bh[nb]);
            }
        }
    }

    const float* biasp = reinterpret_cast<const float*>(dsm + NF_BIAS);
    #pragma unroll
    for (int mt = 0; mt < 2; mt++) {
        #pragma unroll
        for (int nb = 0; nb < 4; nb++) {
            int o = warp_n + nb * 8 + (lane & 3) * 2;
            float b0 = biasp[o], b1 = biasp[o + 1];
            #pragma unroll
            for (int h = 0; h < 2; h++) {
                int b = warp_m + mt * 16 + (lane >> 2) + h * 8;
                float hc0 = tanhf(acc[mt][nb][h * 2] + b0);
                float hc1 = tanhf(acc[mt][nb][h * 2 + 1] + b1);
                float2 rr = *reinterpret_cast<const float2*>(
                    g_ZR + (size_t)n * XGPITCH + b * CC + DH + o);
                float2 ss = *reinterpret_cast<const float2*>(
                    st + ((size_t)b * NN + n) * DH + o);
                float2 hv;
                hv.x = rr.x * ss.x + (1.0f - rr.x) * hc0;
                hv.y = rr.y * ss.y + (1.0f - rr.y) * hc1;
                *reinterpret_cast<float2*>(out + ((size_t)b * NN + n) * DH + o) = hv;
            }
        }
    }
}

// ================ launch (multi-stream fork/join, capture-legal) =================
extern "C" void kernel_launch(void* const* d_in, const int* in_sizes, int n_in,
                              void* d_out, int out_size) {
    const float* x   = (const float*)d_in[0];
    const float* st  = (const float*)d_in[1];
    const float* ne  = (const float*)d_in[2];
    const float* gwp = (const float*)d_in[3];
    const float* gbp = (const float*)d_in[4];
    const float* uwp = (const float*)d_in[5];
    const float* ubp = (const float*)d_in[6];
    float* out = (float*)d_out;

    static cudaStream_t s1 = nullptr, s2 = nullptr;
    static cudaEvent_t e_fork, e_mkw, e_trans;
    static int initialized = 0;
    if (!initialized) {
        cudaFuncSetAttribute(k_hgemm,  cudaFuncAttributeMaxDynamicSharedMemorySize, GEMM_SMEM);
        cudaFuncSetAttribute(k_ngate,  cudaFuncAttributeMaxDynamicSharedMemorySize, NG_SMEM);
        cudaFuncSetAttribute(k_nfinal, cudaFuncAttributeMaxDynamicSharedMemorySize, NF_SMEM);
        cudaStreamCreateWithFlags(&s1, cudaStreamNonBlocking);
        cudaStreamCreateWithFlags(&s2, cudaStreamNonBlocking);
        cudaEventCreateWithFlags(&e_fork,  cudaEventDisableTiming);
        cudaEventCreateWithFlags(&e_mkw,   cudaEventDisableTiming);
        cudaEventCreateWithFlags(&e_trans, cudaEventDisableTiming);
        initialized = 1;
    }

    __nv_bfloat16 *bxh, *bxl, *bsh, *bsl, *wgh, *wgl, *wuh, *wul;
    cudaGetSymbolAddress((void**)&bxh, g_BXhi);
    cudaGetSymbolAddress((void**)&bxl, g_BXlo);
    cudaGetSymbolAddress((void**)&bsh, g_BShi);
    cudaGetSymbolAddress((void**)&bsl, g_BSlo);
    cudaGetSymbolAddress((void**)&wgh, g_Wghi);
    cudaGetSymbolAddress((void**)&wgl, g_Wglo);
    cudaGetSymbolAddress((void**)&wuh, g_Wuhi);
    cudaGetSymbolAddress((void**)&wul, g_Wulo);

    // fork from default stream
    cudaEventRecord(e_fork, 0);
    cudaStreamWaitEvent(s1, e_fork, 0);
    cudaStreamWaitEvent(s2, e_fork, 0);

    // s1: per-node weight materialization (needed first by k_ngate, much later)
    k_mkw<<<(CC * CC) / 256, 256, 0, s1>>>(ne, gwp, wgh, wgl, CC * CC);
    k_mkw<<<(CC * DH) / 256, 256, 0, s1>>>(ne, uwp, wuh, wul, CC * DH);
    cudaEventRecord(e_mkw, s1);

    // s2: input transposes (needed by hgemm1), concurrent with k_supports
    k_trans<<<dim3(NN / 64, BB), 256, 0, s2>>>(x, bxh, bxl, 0);
    k_trans<<<dim3(NN / 64, BB), 256, 0, s2>>>(st, bsh, bsl, 0);
    cudaEventRecord(e_trans, s2);

    // default: supports, then join transposes before the merged GEMM
    k_supports<<<NN, 256>>>(ne);
    cudaStreamWaitEvent(0, e_trans, 0);

    // merged S@x | S@state : 2048 CTAs (6.92 waves)
    k_hgemm<<<dim3(2 * NN / 128, NN / 128), 256, GEMM_SMEM>>>(
        bxh, bxl, 0, bsh, bsl, NN / 128);

    // join weights before per-node gate GEMM
    cudaStreamWaitEvent(0, e_mkw, 0);
    k_ngate<<<NN, 128, NG_SMEM>>>(ne, gbp);

    // update path
    k_trans<<<dim3(NN / 64, BB), 256>>>(st, bsh, bsl, 1);   // (z*state)^T
    k_hgemm<<<dim3(NN / 128, NN / 128), 256, GEMM_SMEM>>>(
        bsh, bsl, 64, bsh, bsl, NN / 128);
    k_nfinal<<<NN, 128, NF_SMEM>>>(ne, ubp, st, out);
}

// round 11
// speedup vs baseline: 1.0956x; 1.0086x over previous
#include <cuda_runtime.h>
#include <cuda_bf16.h>
#include <math.h>
#include <stdint.h>

#define NN 4096
#define BB 64
#define DIN 64
#define DH 64
#define CC 128              // DIN + DH
#define EE 16
#define XGPITCH (BB * CC)   // 8192

// ================= device scratch (no runtime allocs) ==========================
__device__ __nv_bfloat16 g_Shi[(size_t)NN * NN];     // supports hi (A operand)
__device__ __nv_bfloat16 g_Slo[(size_t)NN * NN];     // supports lo
__device__ __nv_bfloat16 g_BXhi[(size_t)NN * NN];    // x^T hi    [j=b*64+c][m]
__device__ __nv_bfloat16 g_BXlo[(size_t)NN * NN];
__device__ __nv_bfloat16 g_BShi[(size_t)NN * NN];    // state^T / (z*state)^T
__device__ __nv_bfloat16 g_BSlo[(size_t)NN * NN];
__device__ __nv_bfloat16 g_XGhi[(size_t)NN * XGPITCH]; // S@CAT hi  [n][b*128+i]
__device__ __nv_bfloat16 g_XGlo[(size_t)NN * XGPITCH]; // S@CAT lo
__device__ __nv_bfloat16 g_Wghi[(size_t)NN * CC * CC]; // gate W hi [n][i][o]
__device__ __nv_bfloat16 g_Wglo[(size_t)NN * CC * CC];
__device__ __nv_bfloat16 g_Wuhi[(size_t)NN * CC * DH]; // update W hi [n][i][o]
__device__ __nv_bfloat16 g_Wulo[(size_t)NN * CC * DH];
__device__ float g_ZR[(size_t)NN * XGPITCH];           // z_r [n][b*128+j]

// ================= PTX helpers (sm_80-level only; NO tcgen05) ====================
__device__ __forceinline__ uint32_t smem_u32(const void* p) {
    uint32_t a;
    asm("{ .reg .u64 t; cvta.to.shared.u64 t, %1; cvt.u32.u64 %0, t; }" : "=r"(a) : "l"(p));
    return a;
}
__device__ __forceinline__ void cpa16(uint32_t dst, const void* src) {
    asm volatile("cp.async.cg.shared.global [%0], [%1], 16;" :: "r"(dst), "l"(src));
}
#define CP_COMMIT() asm volatile("cp.async.commit_group;" ::: "memory")
#define CP_WAIT1()  asm volatile("cp.async.wait_group 1;" ::: "memory")
#define CP_WAIT0()  asm volatile("cp.async.wait_group 0;" ::: "memory")

#define LDSM4(r0, r1, r2, r3, addr) \
    asm volatile("ldmatrix.sync.aligned.m8n8.x4.shared.b16 {%0,%1,%2,%3}, [%4];" \
        : "=r"(r0), "=r"(r1), "=r"(r2), "=r"(r3) : "r"(addr))

#define LDSM4T(r0, r1, r2, r3, addr) \
    asm volatile("ldmatrix.sync.aligned.m8n8.x4.trans.shared.b16 {%0,%1,%2,%3}, [%4];" \
        : "=r"(r0), "=r"(r1), "=r"(r2), "=r"(r3) : "r"(addr))

#define MMA_BF16(c, a, b) \
    asm volatile("mma.sync.aligned.m16n8k16.row.col.f32.bf16.bf16.f32 " \
        "{%0,%1,%2,%3}, {%4,%5,%6,%7}, {%8,%9}, {%0,%1,%2,%3};" \
        : "+f"((c)[0]), "+f"((c)[1]), "+f"((c)[2]), "+f"((c)[3]) \
        : "r"((a)[0]), "r"((a)[1]), "r"((a)[2]), "r"((a)[3]), \
          "r"((b)[0]), "r"((b)[1]))

// ================ supports = softmax(relu(NE @ NE^T)) -> bf16 hi/lo ==============
__global__ __launch_bounds__(256) void k_supports(const float* __restrict__ ne) {
    int n = blockIdx.x, tid = threadIdx.x;
    __shared__ float e[EE];
    __shared__ float redm[8], reds[8];
    if (tid < EE) e[tid] = ne[n * EE + tid];
    __syncthreads();

    float vals[16];
    float mx = 0.0f;
    #pragma unroll
    for (int j = 0; j < 16; j++) {
        int m = tid + j * 256;
        const float4* p = reinterpret_cast<const float4*>(ne + m * EE);
        float4 v0 = p[0], v1 = p[1], v2 = p[2], v3 = p[3];
        float d = e[0]*v0.x + e[1]*v0.y + e[2]*v0.z + e[3]*v0.w
                + e[4]*v1.x + e[5]*v1.y + e[6]*v1.z + e[7]*v1.w
                + e[8]*v2.x + e[9]*v2.y + e[10]*v2.z + e[11]*v2.w
                + e[12]*v3.x + e[13]*v3.y + e[14]*v3.z + e[15]*v3.w;
        d = fmaxf(d, 0.0f);
        vals[j] = d;
        mx = fmaxf(mx, d);
    }
    #pragma unroll
    for (int o = 16; o > 0; o >>= 1) mx = fmaxf(mx, __shfl_xor_sync(0xffffffffu, mx, o));
    if ((tid & 31) == 0) redm[tid >> 5] = mx;
    __syncthreads();
    mx = redm[0];
    #pragma unroll
    for (int w = 1; w < 8; w++) mx = fmaxf(mx, redm[w]);

    float s = 0.0f;
    #pragma unroll
    for (int j = 0; j < 16; j++) { vals[j] = __expf(vals[j] - mx); s += vals[j]; }
    #pragma unroll
    for (int o = 16; o > 0; o >>= 1) s += __shfl_xor_sync(0xffffffffu, s, o);
    if ((tid & 31) == 0) reds[tid >> 5] = s;
    __syncthreads();
    s = 0.0f;
    #pragma unroll
    for (int w = 0; w < 8; w++) s += reds[w];
    float inv = 1.0f / s;
    #pragma unroll
    for (int j = 0; j < 16; j++) {
        float v = vals[j] * inv;
        __nv_bfloat16 h = __float2bfloat16(v);
        size_t o = (size_t)n * NN + tid + j * 256;
        g_Shi[o] = h;
        g_Slo[o] = __float2bfloat16(v - __bfloat162float(h));
    }
}

// ================ per-node weights -> bf16 hi/lo, layout [n][i][o] ===============
__global__ __launch_bounds__(256) void k_mkw(const float* __restrict__ ne,
                                             const float* __restrict__ wp,
                                             __nv_bfloat16* __restrict__ whi,
                                             __nv_bfloat16* __restrict__ wlo,
                                             int IO) {
    int io = blockIdx.x * 256 + threadIdx.x;
    float wv[EE];
    #pragma unroll
    for (int d = 0; d < EE; d++) wv[d] = wp[(size_t)d * IO + io];
    __shared__ float sne[128 * EE];
    for (int n0 = 0; n0 < NN; n0 += 128) {
        __syncthreads();
        for (int t = threadIdx.x; t < 128 * EE; t += 256) sne[t] = ne[n0 * EE + t];
        __syncthreads();
        for (int nn = 0; nn < 128; nn++) {
            float v = 0.0f;
            #pragma unroll
            for (int d = 0; d < EE; d++) v += sne[nn * EE + d] * wv[d];
            __nv_bfloat16 h = __float2bfloat16(v);
            size_t o = (size_t)(n0 + nn) * IO + io;
            whi[o] = h;
            wlo[o] = __float2bfloat16(v - __bfloat162float(h));
        }
    }
}

// ================ transpose + hi/lo split: B operand build =======================
__global__ __launch_bounds__(256) void k_trans(const float* __restrict__ src,
                                               __nv_bfloat16* __restrict__ dhi,
                                               __nv_bfloat16* __restrict__ dlo,
                                               int zmul) {
    __shared__ float tile[64][68];
    int b = blockIdx.y, m0 = blockIdx.x * 64, tid = threadIdx.x;
    #pragma unroll
    for (int i = 0; i < 4; i++) {
        int id = i * 256 + tid;
        int r = id >> 4, c4 = id & 15;
        float4 v = *reinterpret_cast<const float4*>(
            src + ((size_t)b * NN + m0 + r) * 64 + c4 * 4);
        if (zmul) {
            float4 z = *reinterpret_cast<const float4*>(
                g_ZR + (size_t)(m0 + r) * XGPITCH + b * CC + c4 * 4);
            v.x *= z.x; v.y *= z.y; v.z *= z.z; v.w *= z.w;
        }
        *reinterpret_cast<float4*>(&tile[r][c4 * 4]) = v;
    }
    __syncthreads();
    int c = tid >> 2, mg = (tid & 3) * 16;
    uint32_t hi[8], lo[8];
    #pragma unroll
    for (int p = 0; p < 8; p++) {
        float v0 = tile[mg + 2 * p][c], v1 = tile[mg + 2 * p + 1][c];
        __nv_bfloat16 h0 = __float2bfloat16(v0);
        __nv_bfloat16 h1 = __float2bfloat16(v1);
        float l0 = v0 - __bfloat162float(h0);
        float l1 = v1 - __bfloat162float(h1);
        __nv_bfloat162 hp; hp.x = h0; hp.y = h1;
        __nv_bfloat162 lp = __floats2bfloat162_rn(l0, l1);
        hi[p] = *reinterpret_cast<uint32_t*>(&hp);
        lo[p] = *reinterpret_cast<uint32_t*>(&lp);
    }
    size_t o = (size_t)(b * 64 + c) * NN + m0 + mg;
    *reinterpret_cast<uint4*>(dhi + o)     = make_uint4(hi[0], hi[1], hi[2], hi[3]);
    *reinterpret_cast<uint4*>(dhi + o + 8) = make_uint4(hi[4], hi[5], hi[6], hi[7]);
    *reinterpret_cast<uint4*>(dlo + o)     = make_uint4(lo[0], lo[1], lo[2], lo[3]);
    *reinterpret_cast<uint4*>(dlo + o + 8) = make_uint4(lo[4], lo[5], lo[6], lo[7]);
}

// ================ big GEMM via mma.sync bf16, split-precision (3 terms) ==========
// CTA tile 128(M) x 128(N), K-chunk 32 (64B rows), 3-stage, 2 CTAs/SM.
// Dual-B: bn < split -> (Bh0,Bl0) with coff0; else (Bh1,Bl1) with coff 64.
#define OFF_ALO  8192
#define OFF_BHI 16384
#define OFF_BLO 24576
#define STAGE_BYTES 32768
#define GEMM_SMEM (3 * STAGE_BYTES)  // 96 KB

__device__ __forceinline__ uint32_t swz64(int r, int c) {
    return (uint32_t)(r * 64 + ((c ^ (r & 3) ^ ((r >> 2) & 1)) << 4));
}
__device__ __forceinline__ uint32_t swz256(int r, int c) {
    return (uint32_t)(r * 256 + ((c ^ (r & 7)) << 4));
}
__device__ __forceinline__ uint32_t swz128(int r, int c) {
    return (uint32_t)(r * 128 + ((c ^ (r & 7)) << 4));
}

__device__ __forceinline__ void load_stage(uint32_t base, int kt, int tid,
        const __nv_bfloat16* Ah, const __nv_bfloat16* Al,
        const __nv_bfloat16* Bh, const __nv_bfloat16* Bl) {
    int k0 = kt * 32;
    #pragma unroll
    for (int i = 0; i < 2; i++) {
        int id = i * 256 + tid;
        int r = id >> 2, c = id & 3;
        uint32_t off = swz64(r, c);
        size_t g = (size_t)r * NN + k0 + c * 8;
        cpa16(base + off,           Ah + g);
        cpa16(base + OFF_ALO + off, Al + g);
    }
    #pragma unroll
    for (int i = 0; i < 2; i++) {
        int id = i * 256 + tid;
        int r = id >> 2, c = id & 3;
        uint32_t off = swz64(r, c);
        size_t g = (size_t)r * NN + k0 + c * 8;
        cpa16(base + OFF_BHI + off, Bh + g);
        cpa16(base + OFF_BLO + off, Bl + g);
    }
    CP_COMMIT();
}

__global__ __launch_bounds__(256, 2) void k_hgemm(
        const __nv_bfloat16* __restrict__ Bhi0,
        const __nv_bfloat16* __restrict__ Blo0,
        int coff0,
        const __nv_bfloat16* __restrict__ Bhi1,
        const __nv_bfloat16* __restrict__ Blo1,
        int split) {
    extern __shared__ char dsm[];
    uint32_t sb = smem_u32(dsm);
    int tid = threadIdx.x, lane = tid & 31, wid = tid >> 5;
    int bn = blockIdx.x, bm = blockIdx.y;

    // uniform (blockIdx-only) operand select — no per-thread divergence
    const __nv_bfloat16 *Bhp, *Blp;
    int coff;
    if (bn < split) { Bhp = Bhi0; Blp = Blo0; coff = coff0; }
    else            { Bhp = Bhi1; Blp = Blo1; coff = 64; bn -= split; }

    const __nv_bfloat16* Ah = g_Shi + (size_t)(bm * 128) * NN;
    const __nv_bfloat16* Al = g_Slo + (size_t)(bm * 128) * NN;
    const __nv_bfloat16* Bh = Bhp + (size_t)(bn * 128) * NN;
    const __nv_bfloat16* Bl = Blp + (size_t)(bn * 128) * NN;

    int warp_m = (wid >> 2) * 64;
    int warp_n = (wid & 3) * 32;
    float acc[4][4][4] = {};

    load_stage(sb, 0, tid, Ah, Al, Bh, Bl);
    load_stage(sb + STAGE_BYTES, 1, tid, Ah, Al, Bh, Bl);

    const int NKT = NN / 32;
    int lrowA = lane & 15, lgrp = lane >> 4;

    for (int kt = 0; kt < NKT; kt++) {
        CP_WAIT1();
        __syncthreads();

        if (kt + 2 < NKT)
            load_stage(sb + ((kt + 2) % 3) * STAGE_BYTES, kt + 2, tid, Ah, Al, Bh, Bl);
        else
            CP_COMMIT();

        uint32_t base = sb + (kt % 3) * STAGE_BYTES;
        #pragma unroll
        for (int s = 0; s < 2; s++) {
            int cb = s * 2 + lgrp;
            uint32_t bh[4][2], bl[4][2];
            #pragma unroll
            for (int ng = 0; ng < 2; ng++) {
                int r = warp_n + ng * 16 + lrowA;
                uint32_t off = swz64(r, cb);
                uint32_t t0, t1, t2, t3;
                LDSM4(t0, t1, t2, t3, base + OFF_BHI + off);
                bh[ng * 2][0] = t0; bh[ng * 2][1] = t2;
                bh[ng * 2 + 1][0] = t1; bh[ng * 2 + 1][1] = t3;
                LDSM4(t0, t1, t2, t3, base + OFF_BLO + off);
                bl[ng * 2][0] = t0; bl[ng * 2][1] = t2;
                bl[ng * 2 + 1][0] = t1; bl[ng * 2 + 1][1] = t3;
            }
            #pragma unroll
            for (int mt = 0; mt < 4; mt++) {
                int r = warp_m + mt * 16 + lrowA;
                uint32_t off = swz64(r, cb);
                uint32_t ahi[4], alo[4];
                LDSM4(ahi[0], ahi[1], ahi[2], ahi[3], base + off);
                LDSM4(alo[0], alo[1], alo[2], alo[3], base + OFF_ALO + off);
                #pragma unroll
                for (int nt = 0; nt < 4; nt++) {
                    MMA_BF16(acc[mt][nt], ahi, bh[nt]);
                    MMA_BF16(acc[mt][nt], ahi, bl[nt]);
                    MMA_BF16(acc[mt][nt], alo, bh[nt]);
                }
            }
        }
    }

    // epilogue: write XG as bf16 hi/lo pairs
    int row0 = bm * 128 + warp_m + (lane >> 2);
    #pragma unroll
    for (int mt = 0; mt < 4; mt++) {
        #pragma unroll
        for (int nt = 0; nt < 4; nt++) {
            int j = bn * 128 + warp_n + nt * 8 + (lane & 3) * 2;
            int b = j >> 6, c = j & 63;
            size_t p0 = (size_t)(row0 + mt * 16) * XGPITCH + b * CC + coff + c;
            size_t p1 = p0 + (size_t)8 * XGPITCH;
            float a0 = acc[mt][nt][0], a1 = acc[mt][nt][1];
            float a2 = acc[mt][nt][2], a3 = acc[mt][nt][3];
            __nv_bfloat162 h01, l01, h23, l23;
            h01.x = __float2bfloat16(a0); h01.y = __float2bfloat16(a1);
            l01.x = __float2bfloat16(a0 - __bfloat162float(h01.x));
            l01.y = __float2bfloat16(a1 - __bfloat162float(h01.y));
            h23.x = __float2bfloat16(a2); h23.y = __float2bfloat16(a3);
            l23.x = __float2bfloat16(a2 - __bfloat162float(h23.x));
            l23.y = __float2bfloat16(a3 - __bfloat162float(h23.y));
            *reinterpret_cast<__nv_bfloat162*>(g_XGhi + p0) = h01;
            *reinterpret_cast<__nv_bfloat162*>(g_XGlo + p0) = l01;
            *reinterpret_cast<__nv_bfloat162*>(g_XGhi + p1) = h23;
            *reinterpret_cast<__nv_bfloat162*>(g_XGlo + p1) = l23;
        }
    }
}

// ================ per-node gate GEMM (tensorized, 256 thr) + sigmoid =============
// 8 warps: 2(M) x 4(N), warptile 32x32. X(64x128) @ W_n(128x128).
#define NG_XHI 0
#define NG_XLO 16384
#define NG_WHI 32768
#define NG_WLO 65536
#define NG_BIAS 98304
#define NG_SMEM 98816

__global__ __launch_bounds__(256, 2) void k_ngate(const float* __restrict__ ne,
                                                  const float* __restrict__ gbp) {
    extern __shared__ char dsm[];
    uint32_t sb = smem_u32(dsm);
    int n = blockIdx.x, tid = threadIdx.x, lane = tid & 31, wid = tid >> 5;

    // X: 64 rows x 16 chunks, hi+lo
    #pragma unroll
    for (int i = 0; i < 4; i++) {
        int id = i * 256 + tid;
        int r = id >> 4, c = id & 15;
        uint32_t off = swz256(r, c);
        size_t g = (size_t)n * XGPITCH + r * 128 + c * 8;
        cpa16(sb + NG_XHI + off, g_XGhi + g);
        cpa16(sb + NG_XLO + off, g_XGlo + g);
    }
    // W: 128 rows(i) x 16 chunks(o), hi+lo
    #pragma unroll
    for (int i = 0; i < 8; i++) {
        int id = i * 256 + tid;
        int r = id >> 4, c = id & 15;
        uint32_t off = swz256(r, c);
        size_t g = (size_t)n * (CC * CC) + r * 128 + c * 8;
        cpa16(sb + NG_WHI + off, g_Wghi + g);
        cpa16(sb + NG_WLO + off, g_Wglo + g);
    }
    CP_COMMIT();

    // bias[o] = ne[n,:] @ gbp[:,o]
    if (tid < CC) {
        float v = 0.0f;
        #pragma unroll
        for (int d = 0; d < EE; d++) v += ne[n * EE + d] * gbp[d * CC + tid];
        reinterpret_cast<float*>(dsm + NG_BIAS)[tid] = v;
    }
    CP_WAIT0();
    __syncthreads();

    int warp_m = (wid >> 2) * 32;
    int warp_n = (wid & 3) * 32;
    int lrow = lane & 15, lgrp = lane >> 4;
    float acc[2][4][4] = {};

    #pragma unroll
    for (int k16 = 0; k16 < 8; k16++) {
        uint32_t bh[4][2], bl[4][2];
        #pragma unroll
        for (int half = 0; half < 2; half++) {
            uint32_t off = swz256(k16 * 16 + lrow, (warp_n >> 3) + half * 2 + lgrp);
            uint32_t t0, t1, t2, t3;
            LDSM4T(t0, t1, t2, t3, sb + NG_WHI + off);
            bh[half * 2][0] = t0; bh[half * 2][1] = t1;
            bh[half * 2 + 1][0] = t2; bh[half * 2 + 1][1] = t3;
            LDSM4T(t0, t1, t2, t3, sb + NG_WLO + off);
            bl[half * 2][0] = t0; bl[half * 2][1] = t1;
            bl[half * 2 + 1][0] = t2; bl[half * 2 + 1][1] = t3;
        }
        #pragma unroll
        for (int mt = 0; mt < 2; mt++) {
            uint32_t off = swz256(warp_m + mt * 16 + lrow, k16 * 2 + lgrp);
            uint32_t ah[4], al[4];
            LDSM4(ah[0], ah[1], ah[2], ah[3], sb + NG_XHI + off);
            LDSM4(al[0], al[1], al[2], al[3], sb + NG_XLO + off);
            #pragma unroll
            for (int nb = 0; nb < 4; nb++) {
                MMA_BF16(acc[mt][nb], ah, bh[nb]);
                MMA_BF16(acc[mt][nb], ah, bl[nb]);
                MMA_BF16(acc[mt][nb], al, bh[nb]);
            }
        }
    }

    const float* biasp = reinterpret_cast<const float*>(dsm + NG_BIAS);
    #pragma unroll
    for (int mt = 0; mt < 2; mt++) {
        #pragma unroll
        for (int nb = 0; nb < 4; nb++) {
            int o = warp_n + nb * 8 + (lane & 3) * 2;
            int b = warp_m + mt * 16 + (lane >> 2);
            float b0 = biasp[o], b1 = biasp[o + 1];
            float y0 = 1.0f / (1.0f + __expf(-(acc[mt][nb][0] + b0)));
            float y1 = 1.0f / (1.0f + __expf(-(acc[mt][nb][1] + b1)));
            float y2 = 1.0f / (1.0f + __expf(-(acc[mt][nb][2] + b0)));
            float y3 = 1.0f / (1.0f + __expf(-(acc[mt][nb][3] + b1)));
            *reinterpret_cast<float2*>(g_ZR + (size_t)n * XGPITCH + b * CC + o) =
                make_float2(y0, y1);
            *reinterpret_cast<float2*>(g_ZR + (size_t)n * XGPITCH + (b + 8) * CC + o) =
                make_float2(y2, y3);
        }
    }
}

// ================ per-node update GEMM (256 thr) + tanh + GRU combine ============
// 8 warps: 2(M) x 4(N), warptile 32x16. X(64x128) @ Wu(128x64).
#define NF_XHI 0
#define NF_XLO 16384
#define NF_WHI 32768
#define NF_WLO 49152
#define NF_BIAS 65536
#define NF_SMEM 65792

__global__ __launch_bounds__(256, 3) void k_nfinal(const float* __restrict__ ne,
                                                   const float* __restrict__ ubp,
                                                   const float* __restrict__ st,
                                                   float* __restrict__ out) {
    extern __shared__ char dsm[];
    uint32_t sb = smem_u32(dsm);
    int n = blockIdx.x, tid = threadIdx.x, lane = tid & 31, wid = tid >> 5;

    #pragma unroll
    for (int i = 0; i < 4; i++) {
        int id = i * 256 + tid;
        int r = id >> 4, c = id & 15;
        uint32_t off = swz256(r, c);
        size_t g = (size_t)n * XGPITCH + r * 128 + c * 8;
        cpa16(sb + NF_XHI + off, g_XGhi + g);
        cpa16(sb + NF_XLO + off, g_XGlo + g);
    }
    // W: 128 rows(i) x 8 chunks(o=64)
    #pragma unroll
    for (int i = 0; i < 4; i++) {
        int id = i * 256 + tid;
        int r = id >> 3, c = id & 7;
        uint32_t off = swz128(r, c);
        size_t g = (size_t)n * (CC * DH) + r * 64 + c * 8;
        cpa16(sb + NF_WHI + off, g_Wuhi + g);
        cpa16(sb + NF_WLO + off, g_Wulo + g);
    }
    CP_COMMIT();

    if (tid < DH) {
        float v = 0.0f;
        #pragma unroll
        for (int d = 0; d < EE; d++) v += ne[n * EE + d] * ubp[d * DH + tid];
        reinterpret_cast<float*>(dsm + NF_BIAS)[tid] = v;
    }
    CP_WAIT0();
    __syncthreads();

    int warp_m = (wid >> 2) * 32;
    int warp_n = (wid & 3) * 16;
    int lrow = lane & 15, lgrp = lane >> 4;
    float acc[2][2][4] = {};

    #pragma unroll
    for (int k16 = 0; k16 < 8; k16++) {
        uint32_t bh[2][2], bl[2][2];
        {
            uint32_t off = swz128(k16 * 16 + lrow, (warp_n >> 3) + lgrp);
            uint32_t t0, t1, t2, t3;
            LDSM4T(t0, t1, t2, t3, sb + NF_WHI + off);
            bh[0][0] = t0; bh[0][1] = t1;
            bh[1][0] = t2; bh[1][1] = t3;
            LDSM4T(t0, t1, t2, t3, sb + NF_WLO + off);
            bl[0][0] = t0; bl[0][1] = t1;
            bl[1][0] = t2; bl[1][1] = t3;
        }
        #pragma unroll
        for (int mt = 0; mt < 2; mt++) {
            uint32_t off = swz256(warp_m + mt * 16 + lrow, k16 * 2 + lgrp);
            uint32_t ah[4], al[4];
            LDSM4(ah[0], ah[1], ah[2], ah[3], sb + NF_XHI + off);
            LDSM4(al[0], al[1], al[2], al[3], sb + NF_XLO + off);
            #pragma unroll
            for (int nb = 0; nb < 2; nb++) {
                MMA_BF16(acc[mt][nb], ah, bh[nb]);
                MMA_BF16(acc[mt][nb], ah, bl[nb]);
                MMA_BF16(acc[mt][nb], al, bh[nb]);
            }
        }
    }

    const float* biasp = reinterpret_cast<const float*>(dsm + NF_BIAS);
    #pragma unroll
    for (int mt = 0; mt < 2; mt++) {
        #pragma unroll
        for (int nb = 0; nb < 2; nb++) {
            int o = warp_n + nb * 8 + (lane & 3) * 2;
            float b0 = biasp[o], b1 = biasp[o + 1];
            #pragma unroll
            for (int h = 0; h < 2; h++) {
                int b = warp_m + mt * 16 + (lane >> 2) + h * 8;
                float hc0 = tanhf(acc[mt][nb][h * 2] + b0);
                float hc1 = tanhf(acc[mt][nb][h * 2 + 1] + b1);
                float2 rr = *reinterpret_cast<const float2*>(
                    g_ZR + (size_t)n * XGPITCH + b * CC + DH + o);
                float2 ss = *reinterpret_cast<const float2*>(
                    st + ((size_t)b * NN + n) * DH + o);
                float2 hv;
                hv.x = rr.x * ss.x + (1.0f - rr.x) * hc0;
                hv.y = rr.y * ss.y + (1.0f - rr.y) * hc1;
                *reinterpret_cast<float2*>(out + ((size_t)b * NN + n) * DH + o) = hv;
            }
        }
    }
}

// ================ launch (multi-stream fork/join, capture-legal) =================
extern "C" void kernel_launch(void* const* d_in, const int* in_sizes, int n_in,
                              void* d_out, int out_size) {
    const float* x   = (const float*)d_in[0];
    const float* st  = (const float*)d_in[1];
    const float* ne  = (const float*)d_in[2];
    const float* gwp = (const float*)d_in[3];
    const float* gbp = (const float*)d_in[4];
    const float* uwp = (const float*)d_in[5];
    const float* ubp = (const float*)d_in[6];
    float* out = (float*)d_out;

    static cudaStream_t s1 = nullptr, s2 = nullptr;
    static cudaEvent_t e_fork, e_mkw, e_trans;
    static int initialized = 0;
    if (!initialized) {
        cudaFuncSetAttribute(k_hgemm,  cudaFuncAttributeMaxDynamicSharedMemorySize, GEMM_SMEM);
        cudaFuncSetAttribute(k_ngate,  cudaFuncAttributeMaxDynamicSharedMemorySize, NG_SMEM);
        cudaFuncSetAttribute(k_nfinal, cudaFuncAttributeMaxDynamicSharedMemorySize, NF_SMEM);
        cudaStreamCreateWithFlags(&s1, cudaStreamNonBlocking);
        cudaStreamCreateWithFlags(&s2, cudaStreamNonBlocking);
        cudaEventCreateWithFlags(&e_fork,  cudaEventDisableTiming);
        cudaEventCreateWithFlags(&e_mkw,   cudaEventDisableTiming);
        cudaEventCreateWithFlags(&e_trans, cudaEventDisableTiming);
        initialized = 1;
    }

    __nv_bfloat16 *bxh, *bxl, *bsh, *bsl, *wgh, *wgl, *wuh, *wul;
    cudaGetSymbolAddress((void**)&bxh, g_BXhi);
    cudaGetSymbolAddress((void**)&bxl, g_BXlo);
    cudaGetSymbolAddress((void**)&bsh, g_BShi);
    cudaGetSymbolAddress((void**)&bsl, g_BSlo);
    cudaGetSymbolAddress((void**)&wgh, g_Wghi);
    cudaGetSymbolAddress((void**)&wgl, g_Wglo);
    cudaGetSymbolAddress((void**)&wuh, g_Wuhi);
    cudaGetSymbolAddress((void**)&wul, g_Wulo);

    // fork from default stream
    cudaEventRecord(e_fork, 0);
    cudaStreamWaitEvent(s1, e_fork, 0);
    cudaStreamWaitEvent(s2, e_fork, 0);

    // s1: per-node weight materialization (needed by k_ngate, much later)
    k_mkw<<<(CC * CC) / 256, 256, 0, s1>>>(ne, gwp, wgh, wgl, CC * CC);
    k_mkw<<<(CC * DH) / 256, 256, 0, s1>>>(ne, uwp, wuh, wul, CC * DH);
    cudaEventRecord(e_mkw, s1);

    // s2: input transposes (needed by hgemm1), concurrent with k_supports
    k_trans<<<dim3(NN / 64, BB), 256, 0, s2>>>(x, bxh, bxl, 0);
    k_trans<<<dim3(NN / 64, BB), 256, 0, s2>>>(st, bsh, bsl, 0);
    cudaEventRecord(e_trans, s2);

    // default: supports, then join transposes before the merged GEMM
    k_supports<<<NN, 256>>>(ne);
    cudaStreamWaitEvent(0, e_trans, 0);

    // merged S@x | S@state : 2048 CTAs (6.92 waves)
    k_hgemm<<<dim3(2 * NN / 128, NN / 128), 256, GEMM_SMEM>>>(
        bxh, bxl, 0, bsh, bsl, NN / 128);

    // join weights before per-node gate GEMM
    cudaStreamWaitEvent(0, e_mkw, 0);
    k_ngate<<<NN, 256, NG_SMEM>>>(ne, gbp);

    // update path
    k_trans<<<dim3(NN / 64, BB), 256>>>(st, bsh, bsl, 1);   // (z*state)^T
    k_hgemm<<<dim3(NN / 128, NN / 128), 256, GEMM_SMEM>>>(
        bsh, bsl, 64, bsh, bsl, NN / 128);
    k_nfinal<<<NN, 256, NF_SMEM>>>(ne, ubp, st, out);
}

// round 12
// speedup vs baseline: 1.4443x; 1.3183x over previous
#include <cuda_runtime.h>
#include <cuda_bf16.h>
#include <cuda_fp16.h>
#include <math.h>
#include <stdint.h>

#define NN 4096
#define BB 64
#define DIN 64
#define DH 64
#define CC 128              // DIN + DH
#define EE 16
#define XGPITCH (BB * CC)   // 8192

// ================= device scratch (no runtime allocs) ==========================
__device__ __half g_Shi[(size_t)NN * NN];            // supports fp16 (A operand, hi only)
__device__ __half g_BXhi[(size_t)NN * NN];           // x^T hi    [j=b*64+c][m]
__device__ __half g_BXlo[(size_t)NN * NN];
__device__ __half g_BShi[(size_t)NN * NN];           // state^T / (z*state)^T
__device__ __half g_BSlo[(size_t)NN * NN];
__device__ __nv_bfloat16 g_XGhi[(size_t)NN * XGPITCH]; // S@CAT hi  [n][b*128+i] (bf16)
__device__ __nv_bfloat16 g_XGlo[(size_t)NN * XGPITCH]; // S@CAT lo
__device__ __nv_bfloat16 g_Wghi[(size_t)NN * CC * CC]; // gate W hi [n][i][o]
__device__ __nv_bfloat16 g_Wglo[(size_t)NN * CC * CC];
__device__ __nv_bfloat16 g_Wuhi[(size_t)NN * CC * DH]; // update W hi [n][i][o]
__device__ __nv_bfloat16 g_Wulo[(size_t)NN * CC * DH];
__device__ float g_ZR[(size_t)NN * XGPITCH];           // z_r [n][b*128+j]

// ================= PTX helpers (sm_80-level only; NO tcgen05) ====================
__device__ __forceinline__ uint32_t smem_u32(const void* p) {
    uint32_t a;
    asm("{ .reg .u64 t; cvta.to.shared.u64 t, %1; cvt.u32.u64 %0, t; }" : "=r"(a) : "l"(p));
    return a;
}
__device__ __forceinline__ void cpa16(uint32_t dst, const void* src) {
    asm volatile("cp.async.cg.shared.global [%0], [%1], 16;" :: "r"(dst), "l"(src));
}
#define CP_COMMIT() asm volatile("cp.async.commit_group;" ::: "memory")
#define CP_WAIT1()  asm volatile("cp.async.wait_group 1;" ::: "memory")
#define CP_WAIT0()  asm volatile("cp.async.wait_group 0;" ::: "memory")

#define LDSM4(r0, r1, r2, r3, addr) \
    asm volatile("ldmatrix.sync.aligned.m8n8.x4.shared.b16 {%0,%1,%2,%3}, [%4];" \
        : "=r"(r0), "=r"(r1), "=r"(r2), "=r"(r3) : "r"(addr))

#define LDSM4T(r0, r1, r2, r3, addr) \
    asm volatile("ldmatrix.sync.aligned.m8n8.x4.trans.shared.b16 {%0,%1,%2,%3}, [%4];" \
        : "=r"(r0), "=r"(r1), "=r"(r2), "=r"(r3) : "r"(addr))

#define MMA_BF16(c, a, b) \
    asm volatile("mma.sync.aligned.m16n8k16.row.col.f32.bf16.bf16.f32 " \
        "{%0,%1,%2,%3}, {%4,%5,%6,%7}, {%8,%9}, {%0,%1,%2,%3};" \
        : "+f"((c)[0]), "+f"((c)[1]), "+f"((c)[2]), "+f"((c)[3]) \
        : "r"((a)[0]), "r"((a)[1]), "r"((a)[2]), "r"((a)[3]), \
          "r"((b)[0]), "r"((b)[1]))

#define MMA_F16(c, a, b) \
    asm volatile("mma.sync.aligned.m16n8k16.row.col.f32.f16.f16.f32 " \
        "{%0,%1,%2,%3}, {%4,%5,%6,%7}, {%8,%9}, {%0,%1,%2,%3};" \
        : "+f"((c)[0]), "+f"((c)[1]), "+f"((c)[2]), "+f"((c)[3]) \
        : "r"((a)[0]), "r"((a)[1]), "r"((a)[2]), "r"((a)[3]), \
          "r"((b)[0]), "r"((b)[1]))

// ================ supports = softmax(relu(NE @ NE^T)) -> fp16 ====================
__global__ __launch_bounds__(256) void k_supports(const float* __restrict__ ne) {
    int n = blockIdx.x, tid = threadIdx.x;
    __shared__ float e[EE];
    __shared__ float redm[8], reds[8];
    if (tid < EE) e[tid] = ne[n * EE + tid];
    __syncthreads();

    float vals[16];
    float mx = 0.0f;
    #pragma unroll
    for (int j = 0; j < 16; j++) {
        int m = tid + j * 256;
        const float4* p = reinterpret_cast<const float4*>(ne + m * EE);
        float4 v0 = p[0], v1 = p[1], v2 = p[2], v3 = p[3];
        float d = e[0]*v0.x + e[1]*v0.y + e[2]*v0.z + e[3]*v0.w
                + e[4]*v1.x + e[5]*v1.y + e[6]*v1.z + e[7]*v1.w
                + e[8]*v2.x + e[9]*v2.y + e[10]*v2.z + e[11]*v2.w
                + e[12]*v3.x + e[13]*v3.y + e[14]*v3.z + e[15]*v3.w;
        d = fmaxf(d, 0.0f);
        vals[j] = d;
        mx = fmaxf(mx, d);
    }
    #pragma unroll
    for (int o = 16; o > 0; o >>= 1) mx = fmaxf(mx, __shfl_xor_sync(0xffffffffu, mx, o));
    if ((tid & 31) == 0) redm[tid >> 5] = mx;
    __syncthreads();
    mx = redm[0];
    #pragma unroll
    for (int w = 1; w < 8; w++) mx = fmaxf(mx, redm[w]);

    float s = 0.0f;
    #pragma unroll
    for (int j = 0; j < 16; j++) { vals[j] = __expf(vals[j] - mx); s += vals[j]; }
    #pragma unroll
    for (int o = 16; o > 0; o >>= 1) s += __shfl_xor_sync(0xffffffffu, s, o);
    if ((tid & 31) == 0) reds[tid >> 5] = s;
    __syncthreads();
    s = 0.0f;
    #pragma unroll
    for (int w = 0; w < 8; w++) s += reds[w];
    float inv = 1.0f / s;
    #pragma unroll
    for (int j = 0; j < 16; j++) {
        g_Shi[(size_t)n * NN + tid + j * 256] = __float2half_rn(vals[j] * inv);
    }
}

// ================ per-node weights -> bf16 hi/lo, layout [n][i][o] ===============
__global__ __launch_bounds__(256) void k_mkw(const float* __restrict__ ne,
                                             const float* __restrict__ wp,
                                             __nv_bfloat16* __restrict__ whi,
                                             __nv_bfloat16* __restrict__ wlo,
                                             int IO) {
    int io = blockIdx.x * 256 + threadIdx.x;
    float wv[EE];
    #pragma unroll
    for (int d = 0; d < EE; d++) wv[d] = wp[(size_t)d * IO + io];
    __shared__ float sne[128 * EE];
    for (int n0 = 0; n0 < NN; n0 += 128) {
        __syncthreads();
        for (int t = threadIdx.x; t < 128 * EE; t += 256) sne[t] = ne[n0 * EE + t];
        __syncthreads();
        for (int nn = 0; nn < 128; nn++) {
            float v = 0.0f;
            #pragma unroll
            for (int d = 0; d < EE; d++) v += sne[nn * EE + d] * wv[d];
            __nv_bfloat16 h = __float2bfloat16(v);
            size_t o = (size_t)(n0 + nn) * IO + io;
            whi[o] = h;
            wlo[o] = __float2bfloat16(v - __bfloat162float(h));
        }
    }
}

// ================ transpose + fp16 hi/lo split: B operand build ==================
__global__ __launch_bounds__(256) void k_trans(const float* __restrict__ src,
                                               __half* __restrict__ dhi,
                                               __half* __restrict__ dlo,
                                               int zmul) {
    __shared__ float tile[64][68];
    int b = blockIdx.y, m0 = blockIdx.x * 64, tid = threadIdx.x;
    #pragma unroll
    for (int i = 0; i < 4; i++) {
        int id = i * 256 + tid;
        int r = id >> 4, c4 = id & 15;
        float4 v = *reinterpret_cast<const float4*>(
            src + ((size_t)b * NN + m0 + r) * 64 + c4 * 4);
        if (zmul) {
            float4 z = *reinterpret_cast<const float4*>(
                g_ZR + (size_t)(m0 + r) * XGPITCH + b * CC + c4 * 4);
            v.x *= z.x; v.y *= z.y; v.z *= z.z; v.w *= z.w;
        }
        *reinterpret_cast<float4*>(&tile[r][c4 * 4]) = v;
    }
    __syncthreads();
    int c = tid >> 2, mg = (tid & 3) * 16;
    uint32_t hi[8], lo[8];
    #pragma unroll
    for (int p = 0; p < 8; p++) {
        float v0 = tile[mg + 2 * p][c], v1 = tile[mg + 2 * p + 1][c];
        __half h0 = __float2half_rn(v0);
        __half h1 = __float2half_rn(v1);
        float l0 = v0 - __half2float(h0);
        float l1 = v1 - __half2float(h1);
        __half2 hp = __halves2half2(h0, h1);
        __half2 lp = __floats2half2_rn(l0, l1);
        hi[p] = *reinterpret_cast<uint32_t*>(&hp);
        lo[p] = *reinterpret_cast<uint32_t*>(&lp);
    }
    size_t o = (size_t)(b * 64 + c) * NN + m0 + mg;
    *reinterpret_cast<uint4*>(dhi + o)     = make_uint4(hi[0], hi[1], hi[2], hi[3]);
    *reinterpret_cast<uint4*>(dhi + o + 8) = make_uint4(hi[4], hi[5], hi[6], hi[7]);
    *reinterpret_cast<uint4*>(dlo + o)     = make_uint4(lo[0], lo[1], lo[2], lo[3]);
    *reinterpret_cast<uint4*>(dlo + o + 8) = make_uint4(lo[4], lo[5], lo[6], lo[7]);
}

// ================ big GEMM via mma.sync fp16, 2-term split =======================
// C = S @ CAT^T;  terms: S_hi*B_hi + S_hi*B_lo (A_lo dropped; S is fp16-friendly).
// CTA tile 128(M) x 128(N), K-chunk 32 (64B rows), 3-stage, 2 CTAs/SM.
#define OFF_BHI  8192
#define OFF_BLO 16384
#define STAGE_BYTES 24576
#define GEMM_SMEM (3 * STAGE_BYTES)  // 72 KB

__device__ __forceinline__ uint32_t swz64(int r, int c) {
    return (uint32_t)(r * 64 + ((c ^ (r & 3) ^ ((r >> 2) & 1)) << 4));
}
__device__ __forceinline__ uint32_t swz256(int r, int c) {
    return (uint32_t)(r * 256 + ((c ^ (r & 7)) << 4));
}
__device__ __forceinline__ uint32_t swz128(int r, int c) {
    return (uint32_t)(r * 128 + ((c ^ (r & 7)) << 4));
}

__device__ __forceinline__ void load_stage(uint32_t base, int kt, int tid,
        const __half* Ah, const __half* Bh, const __half* Bl) {
    int k0 = kt * 32;
    #pragma unroll
    for (int i = 0; i < 2; i++) {
        int id = i * 256 + tid;
        int r = id >> 2, c = id & 3;
        uint32_t off = swz64(r, c);
        size_t g = (size_t)r * NN + k0 + c * 8;
        cpa16(base + off, Ah + g);
    }
    #pragma unroll
    for (int i = 0; i < 2; i++) {
        int id = i * 256 + tid;
        int r = id >> 2, c = id & 3;
        uint32_t off = swz64(r, c);
        size_t g = (size_t)r * NN + k0 + c * 8;
        cpa16(base + OFF_BHI + off, Bh + g);
        cpa16(base + OFF_BLO + off, Bl + g);
    }
    CP_COMMIT();
}

__global__ __launch_bounds__(256, 2) void k_hgemm(
        const __half* __restrict__ Bhi0,
        const __half* __restrict__ Blo0,
        int coff0,
        const __half* __restrict__ Bhi1,
        const __half* __restrict__ Blo1,
        int split) {
    extern __shared__ char dsm[];
    uint32_t sb = smem_u32(dsm);
    int tid = threadIdx.x, lane = tid & 31, wid = tid >> 5;
    int bn = blockIdx.x, bm = blockIdx.y;

    const __half *Bhp, *Blp;
    int coff;
    if (bn < split) { Bhp = Bhi0; Blp = Blo0; coff = coff0; }
    else            { Bhp = Bhi1; Blp = Blo1; coff = 64; bn -= split; }

    const __half* Ah = g_Shi + (size_t)(bm * 128) * NN;
    const __half* Bh = Bhp + (size_t)(bn * 128) * NN;
    const __half* Bl = Blp + (size_t)(bn * 128) * NN;

    int warp_m = (wid >> 2) * 64;
    int warp_n = (wid & 3) * 32;
    float acc[4][4][4] = {};

    load_stage(sb, 0, tid, Ah, Bh, Bl);
    load_stage(sb + STAGE_BYTES, 1, tid, Ah, Bh, Bl);

    const int NKT = NN / 32;
    int lrowA = lane & 15, lgrp = lane >> 4;

    for (int kt = 0; kt < NKT; kt++) {
        CP_WAIT1();
        __syncthreads();

        if (kt + 2 < NKT)
            load_stage(sb + ((kt + 2) % 3) * STAGE_BYTES, kt + 2, tid, Ah, Bh, Bl);
        else
            CP_COMMIT();

        uint32_t base = sb + (kt % 3) * STAGE_BYTES;
        #pragma unroll
        for (int s = 0; s < 2; s++) {
            int cb = s * 2 + lgrp;
            uint32_t bh[4][2], bl[4][2];
            #pragma unroll
            for (int ng = 0; ng < 2; ng++) {
                int r = warp_n + ng * 16 + lrowA;
                uint32_t off = swz64(r, cb);
                uint32_t t0, t1, t2, t3;
                LDSM4(t0, t1, t2, t3, base + OFF_BHI + off);
                bh[ng * 2][0] = t0; bh[ng * 2][1] = t2;
                bh[ng * 2 + 1][0] = t1; bh[ng * 2 + 1][1] = t3;
                LDSM4(t0, t1, t2, t3, base + OFF_BLO + off);
                bl[ng * 2][0] = t0; bl[ng * 2][1] = t2;
                bl[ng * 2 + 1][0] = t1; bl[ng * 2 + 1][1] = t3;
            }
            #pragma unroll
            for (int mt = 0; mt < 4; mt++) {
                int r = warp_m + mt * 16 + lrowA;
                uint32_t off = swz64(r, cb);
                uint32_t ahi[4];
                LDSM4(ahi[0], ahi[1], ahi[2], ahi[3], base + off);
                #pragma unroll
                for (int nt = 0; nt < 4; nt++) {
                    MMA_F16(acc[mt][nt], ahi, bh[nt]);
                    MMA_F16(acc[mt][nt], ahi, bl[nt]);
                }
            }
        }
    }

    // epilogue: write XG as bf16 hi/lo pairs (unchanged downstream format)
    int row0 = bm * 128 + warp_m + (lane >> 2);
    #pragma unroll
    for (int mt = 0; mt < 4; mt++) {
        #pragma unroll
        for (int nt = 0; nt < 4; nt++) {
            int j = bn * 128 + warp_n + nt * 8 + (lane & 3) * 2;
            int b = j >> 6, c = j & 63;
            size_t p0 = (size_t)(row0 + mt * 16) * XGPITCH + b * CC + coff + c;
            size_t p1 = p0 + (size_t)8 * XGPITCH;
            float a0 = acc[mt][nt][0], a1 = acc[mt][nt][1];
            float a2 = acc[mt][nt][2], a3 = acc[mt][nt][3];
            __nv_bfloat162 h01, l01, h23, l23;
            h01.x = __float2bfloat16(a0); h01.y = __float2bfloat16(a1);
            l01.x = __float2bfloat16(a0 - __bfloat162float(h01.x));
            l01.y = __float2bfloat16(a1 - __bfloat162float(h01.y));
            h23.x = __float2bfloat16(a2); h23.y = __float2bfloat16(a3);
            l23.x = __float2bfloat16(a2 - __bfloat162float(h23.x));
            l23.y = __float2bfloat16(a3 - __bfloat162float(h23.y));
            *reinterpret_cast<__nv_bfloat162*>(g_XGhi + p0) = h01;
            *reinterpret_cast<__nv_bfloat162*>(g_XGlo + p0) = l01;
            *reinterpret_cast<__nv_bfloat162*>(g_XGhi + p1) = h23;
            *reinterpret_cast<__nv_bfloat162*>(g_XGlo + p1) = l23;
        }
    }
}

// ================ per-node gate GEMM (tensorized, 256 thr) + sigmoid =============
// 8 warps: 2(M) x 4(N), warptile 32x32. X(64x128) @ W_n(128x128). bf16 3-term.
#define NG_XHI 0
#define NG_XLO 16384
#define NG_WHI 32768
#define NG_WLO 65536
#define NG_BIAS 98304
#define NG_SMEM 98816

__global__ __launch_bounds__(256, 2) void k_ngate(const float* __restrict__ ne,
                                                  const float* __restrict__ gbp) {
    extern __shared__ char dsm[];
    uint32_t sb = smem_u32(dsm);
    int n = blockIdx.x, tid = threadIdx.x, lane = tid & 31, wid = tid >> 5;

    #pragma unroll
    for (int i = 0; i < 4; i++) {
        int id = i * 256 + tid;
        int r = id >> 4, c = id & 15;
        uint32_t off = swz256(r, c);
        size_t g = (size_t)n * XGPITCH + r * 128 + c * 8;
        cpa16(sb + NG_XHI + off, g_XGhi + g);
        cpa16(sb + NG_XLO + off, g_XGlo + g);
    }
    #pragma unroll
    for (int i = 0; i < 8; i++) {
        int id = i * 256 + tid;
        int r = id >> 4, c = id & 15;
        uint32_t off = swz256(r, c);
        size_t g = (size_t)n * (CC * CC) + r * 128 + c * 8;
        cpa16(sb + NG_WHI + off, g_Wghi + g);
        cpa16(sb + NG_WLO + off, g_Wglo + g);
    }
    CP_COMMIT();

    if (tid < CC) {
        float v = 0.0f;
        #pragma unroll
        for (int d = 0; d < EE; d++) v += ne[n * EE + d] * gbp[d * CC + tid];
        reinterpret_cast<float*>(dsm + NG_BIAS)[tid] = v;
    }
    CP_WAIT0();
    __syncthreads();

    int warp_m = (wid >> 2) * 32;
    int warp_n = (wid & 3) * 32;
    int lrow = lane & 15, lgrp = lane >> 4;
    float acc[2][4][4] = {};

    #pragma unroll
    for (int k16 = 0; k16 < 8; k16++) {
        uint32_t bh[4][2], bl[4][2];
        #pragma unroll
        for (int half = 0; half < 2; half++) {
            uint32_t off = swz256(k16 * 16 + lrow, (warp_n >> 3) + half * 2 + lgrp);
            uint32_t t0, t1, t2, t3;
            LDSM4T(t0, t1, t2, t3, sb + NG_WHI + off);
            bh[half * 2][0] = t0; bh[half * 2][1] = t1;
            bh[half * 2 + 1][0] = t2; bh[half * 2 + 1][1] = t3;
            LDSM4T(t0, t1, t2, t3, sb + NG_WLO + off);
            bl[half * 2][0] = t0; bl[half * 2][1] = t1;
            bl[half * 2 + 1][0] = t2; bl[half * 2 + 1][1] = t3;
        }
        #pragma unroll
        for (int mt = 0; mt < 2; mt++) {
            uint32_t off = swz256(warp_m + mt * 16 + lrow, k16 * 2 + lgrp);
            uint32_t ah[4], al[4];
            LDSM4(ah[0], ah[1], ah[2], ah[3], sb + NG_XHI + off);
            LDSM4(al[0], al[1], al[2], al[3], sb + NG_XLO + off);
            #pragma unroll
            for (int nb = 0; nb < 4; nb++) {
                MMA_BF16(acc[mt][nb], ah, bh[nb]);
                MMA_BF16(acc[mt][nb], ah, bl[nb]);
                MMA_BF16(acc[mt][nb], al, bh[nb]);
            }
        }
    }

    const float* biasp = reinterpret_cast<const float*>(dsm + NG_BIAS);
    #pragma unroll
    for (int mt = 0; mt < 2; mt++) {
        #pragma unroll
        for (int nb = 0; nb < 4; nb++) {
            int o = warp_n + nb * 8 + (lane & 3) * 2;
            int b = warp_m + mt * 16 + (lane >> 2);
            float b0 = biasp[o], b1 = biasp[o + 1];
            float y0 = 1.0f / (1.0f + __expf(-(acc[mt][nb][0] + b0)));
            float y1 = 1.0f / (1.0f + __expf(-(acc[mt][nb][1] + b1)));
            float y2 = 1.0f / (1.0f + __expf(-(acc[mt][nb][2] + b0)));
            float y3 = 1.0f / (1.0f + __expf(-(acc[mt][nb][3] + b1)));
            *reinterpret_cast<float2*>(g_ZR + (size_t)n * XGPITCH + b * CC + o) =
                make_float2(y0, y1);
            *reinterpret_cast<float2*>(g_ZR + (size_t)n * XGPITCH + (b + 8) * CC + o) =
                make_float2(y2, y3);
        }
    }
}

// ================ per-node update GEMM (256 thr) + tanh + GRU combine ============
#define NF_XHI 0
#define NF_XLO 16384
#define NF_WHI 32768
#define NF_WLO 49152
#define NF_BIAS 65536
#define NF_SMEM 65792

__global__ __launch_bounds__(256, 3) void k_nfinal(const float* __restrict__ ne,
                                                   const float* __restrict__ ubp,
                                                   const float* __restrict__ st,
                                                   float* __restrict__ out) {
    extern __shared__ char dsm[];
    uint32_t sb = smem_u32(dsm);
    int n = blockIdx.x, tid = threadIdx.x, lane = tid & 31, wid = tid >> 5;

    #pragma unroll
    for (int i = 0; i < 4; i++) {
        int id = i * 256 + tid;
        int r = id >> 4, c = id & 15;
        uint32_t off = swz256(r, c);
        size_t g = (size_t)n * XGPITCH + r * 128 + c * 8;
        cpa16(sb + NF_XHI + off, g_XGhi + g);
        cpa16(sb + NF_XLO + off, g_XGlo + g);
    }
    #pragma unroll
    for (int i = 0; i < 4; i++) {
        int id = i * 256 + tid;
        int r = id >> 3, c = id & 7;
        uint32_t off = swz128(r, c);
        size_t g = (size_t)n * (CC * DH) + r * 64 + c * 8;
        cpa16(sb + NF_WHI + off, g_Wuhi + g);
        cpa16(sb + NF_WLO + off, g_Wulo + g);
    }
    CP_COMMIT();

    if (tid < DH) {
        float v = 0.0f;
        #pragma unroll
        for (int d = 0; d < EE; d++) v += ne[n * EE + d] * ubp[d * DH + tid];
        reinterpret_cast<float*>(dsm + NF_BIAS)[tid] = v;
    }
    CP_WAIT0();
    __syncthreads();

    int warp_m = (wid >> 2) * 32;
    int warp_n = (wid & 3) * 16;
    int lrow = lane & 15, lgrp = lane >> 4;
    float acc[2][2][4] = {};

    #pragma unroll
    for (int k16 = 0; k16 < 8; k16++) {
        uint32_t bh[2][2], bl[2][2];
        {
            uint32_t off = swz128(k16 * 16 + lrow, (warp_n >> 3) + lgrp);
            uint32_t t0, t1, t2, t3;
            LDSM4T(t0, t1, t2, t3, sb + NF_WHI + off);
            bh[0][0] = t0; bh[0][1] = t1;
            bh[1][0] = t2; bh[1][1] = t3;
            LDSM4T(t0, t1, t2, t3, sb + NF_WLO + off);
            bl[0][0] = t0; bl[0][1] = t1;
            bl[1][0] = t2; bl[1][1] = t3;
        }
        #pragma unroll
        for (int mt = 0; mt < 2; mt++) {
            uint32_t off = swz256(warp_m + mt * 16 + lrow, k16 * 2 + lgrp);
            uint32_t ah[4], al[4];
            LDSM4(ah[0], ah[1], ah[2], ah[3], sb + NF_XHI + off);
            LDSM4(al[0], al[1], al[2], al[3], sb + NF_XLO + off);
            #pragma unroll
            for (int nb = 0; nb < 2; nb++) {
                MMA_BF16(acc[mt][nb], ah, bh[nb]);
                MMA_BF16(acc[mt][nb], ah, bl[nb]);
                MMA_BF16(acc[mt][nb], al, bh[nb]);
            }
        }
    }

    const float* biasp = reinterpret_cast<const float*>(dsm + NF_BIAS);
    #pragma unroll
    for (int mt = 0; mt < 2; mt++) {
        #pragma unroll
        for (int nb = 0; nb < 2; nb++) {
            int o = warp_n + nb * 8 + (lane & 3) * 2;
            float b0 = biasp[o], b1 = biasp[o + 1];
            #pragma unroll
            for (int h = 0; h < 2; h++) {
                int b = warp_m + mt * 16 + (lane >> 2) + h * 8;
                float hc0 = tanhf(acc[mt][nb][h * 2] + b0);
                float hc1 = tanhf(acc[mt][nb][h * 2 + 1] + b1);
                float2 rr = *reinterpret_cast<const float2*>(
                    g_ZR + (size_t)n * XGPITCH + b * CC + DH + o);
                float2 ss = *reinterpret_cast<const float2*>(
                    st + ((size_t)b * NN + n) * DH + o);
                float2 hv;
                hv.x = rr.x * ss.x + (1.0f - rr.x) * hc0;
                hv.y = rr.y * ss.y + (1.0f - rr.y) * hc1;
                *reinterpret_cast<float2*>(out + ((size_t)b * NN + n) * DH + o) = hv;
            }
        }
    }
}

// ================ launch (multi-stream fork/join, capture-legal) =================
extern "C" void kernel_launch(void* const* d_in, const int* in_sizes, int n_in,
                              void* d_out, int out_size) {
    const float* x   = (const float*)d_in[0];
    const float* st  = (const float*)d_in[1];
    const float* ne  = (const float*)d_in[2];
    const float* gwp = (const float*)d_in[3];
    const float* gbp = (const float*)d_in[4];
    const float* uwp = (const float*)d_in[5];
    const float* ubp = (const float*)d_in[6];
    float* out = (float*)d_out;

    static cudaStream_t s1 = nullptr, s2 = nullptr;
    static cudaEvent_t e_fork, e_mkw, e_trans;
    static int initialized = 0;
    if (!initialized) {
        cudaFuncSetAttribute(k_hgemm,  cudaFuncAttributeMaxDynamicSharedMemorySize, GEMM_SMEM);
        cudaFuncSetAttribute(k_ngate,  cudaFuncAttributeMaxDynamicSharedMemorySize, NG_SMEM);
        cudaFuncSetAttribute(k_nfinal, cudaFuncAttributeMaxDynamicSharedMemorySize, NF_SMEM);
        cudaStreamCreateWithFlags(&s1, cudaStreamNonBlocking);
        cudaStreamCreateWithFlags(&s2, cudaStreamNonBlocking);
        cudaEventCreateWithFlags(&e_fork,  cudaEventDisableTiming);
        cudaEventCreateWithFlags(&e_mkw,   cudaEventDisableTiming);
        cudaEventCreateWithFlags(&e_trans, cudaEventDisableTiming);
        initialized = 1;
    }

    __half *bxh, *bxl, *bsh, *bsl;
    __nv_bfloat16 *wgh, *wgl, *wuh, *wul;
    cudaGetSymbolAddress((void**)&bxh, g_BXhi);
    cudaGetSymbolAddress((void**)&bxl, g_BXlo);
    cudaGetSymbolAddress((void**)&bsh, g_BShi);
    cudaGetSymbolAddress((void**)&bsl, g_BSlo);
    cudaGetSymbolAddress((void**)&wgh, g_Wghi);
    cudaGetSymbolAddress((void**)&wgl, g_Wglo);
    cudaGetSymbolAddress((void**)&wuh, g_Wuhi);
    cudaGetSymbolAddress((void**)&wul, g_Wulo);

    // fork from default stream
    cudaEventRecord(e_fork, 0);
    cudaStreamWaitEvent(s1, e_fork, 0);
    cudaStreamWaitEvent(s2, e_fork, 0);

    // s1: per-node weight materialization (needed by k_ngate, much later)
    k_mkw<<<(CC * CC) / 256, 256, 0, s1>>>(ne, gwp, wgh, wgl, CC * CC);
    k_mkw<<<(CC * DH) / 256, 256, 0, s1>>>(ne, uwp, wuh, wul, CC * DH);
    cudaEventRecord(e_mkw, s1);

    // s2: input transposes (needed by hgemm1), concurrent with k_supports
    k_trans<<<dim3(NN / 64, BB), 256, 0, s2>>>(x, bxh, bxl, 0);
    k_trans<<<dim3(NN / 64, BB), 256, 0, s2>>>(st, bsh, bsl, 0);
    cudaEventRecord(e_trans, s2);

    // default: supports, then join transposes before the merged GEMM
    k_supports<<<NN, 256>>>(ne);
    cudaStreamWaitEvent(0, e_trans, 0);

    // merged S@x | S@state : 2048 CTAs (6.92 waves)
    k_hgemm<<<dim3(2 * NN / 128, NN / 128), 256, GEMM_SMEM>>>(
        bxh, bxl, 0, bsh, bsl, NN / 128);

    // join weights before per-node gate GEMM
    cudaStreamWaitEvent(0, e_mkw, 0);
    k_ngate<<<NN, 256, NG_SMEM>>>(ne, gbp);

    // update path
    k_trans<<<dim3(NN / 64, BB), 256>>>(st, bsh, bsl, 1);   // (z*state)^T
    k_hgemm<<<dim3(NN / 128, NN / 128), 256, GEMM_SMEM>>>(
        bsh, bsl, 64, bsh, bsl, NN / 128);
    k_nfinal<<<NN, 256, NF_SMEM>>>(ne, ubp, st, out);
}

// round 13
// speedup vs baseline: 2.0036x; 1.3872x over previous
#include <cuda_runtime.h>
#include <cuda_bf16.h>
#include <cuda_fp16.h>
#include <math.h>
#include <stdint.h>

#define NN 4096
#define BB 64
#define DIN 64
#define DH 64
#define CC 128              // DIN + DH
#define EE 16
#define XGPITCH (BB * CC)   // 8192

// ================= device scratch (no runtime allocs) ==========================
__device__ __half g_Shi[(size_t)NN * NN];            // supports fp16 (A operand)
__device__ __half g_BXhi[(size_t)NN * NN];           // x^T fp16  [j=b*64+c][m]
__device__ __half g_BShi[(size_t)NN * NN];           // state^T / (z*state)^T fp16
__device__ __nv_bfloat16 g_XGhi[(size_t)NN * XGPITCH]; // S@CAT hi  [n][b*128+i] (bf16)
__device__ __nv_bfloat16 g_XGlo[(size_t)NN * XGPITCH]; // S@CAT lo
__device__ __nv_bfloat16 g_Wghi[(size_t)NN * CC * CC]; // gate W hi [n][i][o]
__device__ __nv_bfloat16 g_Wglo[(size_t)NN * CC * CC];
__device__ __nv_bfloat16 g_Wuhi[(size_t)NN * CC * DH]; // update W hi [n][i][o]
__device__ __nv_bfloat16 g_Wulo[(size_t)NN * CC * DH];
__device__ float g_ZR[(size_t)NN * XGPITCH];           // z_r [n][b*128+j]

// ================= PTX helpers (sm_80-level only; NO tcgen05) ====================
__device__ __forceinline__ uint32_t smem_u32(const void* p) {
    uint32_t a;
    asm("{ .reg .u64 t; cvta.to.shared.u64 t, %1; cvt.u32.u64 %0, t; }" : "=r"(a) : "l"(p));
    return a;
}
__device__ __forceinline__ void cpa16(uint32_t dst, const void* src) {
    asm volatile("cp.async.cg.shared.global [%0], [%1], 16;" :: "r"(dst), "l"(src));
}
#define CP_COMMIT() asm volatile("cp.async.commit_group;" ::: "memory")
#define CP_WAIT1()  asm volatile("cp.async.wait_group 1;" ::: "memory")
#define CP_WAIT0()  asm volatile("cp.async.wait_group 0;" ::: "memory")

#define LDSM4(r0, r1, r2, r3, addr) \
    asm volatile("ldmatrix.sync.aligned.m8n8.x4.shared.b16 {%0,%1,%2,%3}, [%4];" \
        : "=r"(r0), "=r"(r1), "=r"(r2), "=r"(r3) : "r"(addr))

#define LDSM4T(r0, r1, r2, r3, addr) \
    asm volatile("ldmatrix.sync.aligned.m8n8.x4.trans.shared.b16 {%0,%1,%2,%3}, [%4];" \
        : "=r"(r0), "=r"(r1), "=r"(r2), "=r"(r3) : "r"(addr))

#define MMA_BF16(c, a, b) \
    asm volatile("mma.sync.aligned.m16n8k16.row.col.f32.bf16.bf16.f32 " \
        "{%0,%1,%2,%3}, {%4,%5,%6,%7}, {%8,%9}, {%0,%1,%2,%3};" \
        : "+f"((c)[0]), "+f"((c)[1]), "+f"((c)[2]), "+f"((c)[3]) \
        : "r"((a)[0]), "r"((a)[1]), "r"((a)[2]), "r"((a)[3]), \
          "r"((b)[0]), "r"((b)[1]))

#define MMA_F16(c, a, b) \
    asm volatile("mma.sync.aligned.m16n8k16.row.col.f32.f16.f16.f32 " \
        "{%0,%1,%2,%3}, {%4,%5,%6,%7}, {%8,%9}, {%0,%1,%2,%3};" \
        : "+f"((c)[0]), "+f"((c)[1]), "+f"((c)[2]), "+f"((c)[3]) \
        : "r"((a)[0]), "r"((a)[1]), "r"((a)[2]), "r"((a)[3]), \
          "r"((b)[0]), "r"((b)[1]))

// ================ supports = softmax(relu(NE @ NE^T)) -> fp16 ====================
__global__ __launch_bounds__(256) void k_supports(const float* __restrict__ ne) {
    int n = blockIdx.x, tid = threadIdx.x;
    __shared__ float e[EE];
    __shared__ float redm[8], reds[8];
    if (tid < EE) e[tid] = ne[n * EE + tid];
    __syncthreads();

    float vals[16];
    float mx = 0.0f;
    #pragma unroll
    for (int j = 0; j < 16; j++) {
        int m = tid + j * 256;
        const float4* p = reinterpret_cast<const float4*>(ne + m * EE);
        float4 v0 = p[0], v1 = p[1], v2 = p[2], v3 = p[3];
        float d = e[0]*v0.x + e[1]*v0.y + e[2]*v0.z + e[3]*v0.w
                + e[4]*v1.x + e[5]*v1.y + e[6]*v1.z + e[7]*v1.w
                + e[8]*v2.x + e[9]*v2.y + e[10]*v2.z + e[11]*v2.w
                + e[12]*v3.x + e[13]*v3.y + e[14]*v3.z + e[15]*v3.w;
        d = fmaxf(d, 0.0f);
        vals[j] = d;
        mx = fmaxf(mx, d);
    }
    #pragma unroll
    for (int o = 16; o > 0; o >>= 1) mx = fmaxf(mx, __shfl_xor_sync(0xffffffffu, mx, o));
    if ((tid & 31) == 0) redm[tid >> 5] = mx;
    __syncthreads();
    mx = redm[0];
    #pragma unroll
    for (int w = 1; w < 8; w++) mx = fmaxf(mx, redm[w]);

    float s = 0.0f;
    #pragma unroll
    for (int j = 0; j < 16; j++) { vals[j] = __expf(vals[j] - mx); s += vals[j]; }
    #pragma unroll
    for (int o = 16; o > 0; o >>= 1) s += __shfl_xor_sync(0xffffffffu, s, o);
    if ((tid & 31) == 0) reds[tid >> 5] = s;
    __syncthreads();
    s = 0.0f;
    #pragma unroll
    for (int w = 0; w < 8; w++) s += reds[w];
    float inv = 1.0f / s;
    #pragma unroll
    for (int j = 0; j < 16; j++) {
        g_Shi[(size_t)n * NN + tid + j * 256] = __float2half_rn(vals[j] * inv);
    }
}

// ================ per-node weights -> bf16 hi/lo, layout [n][i][o] ===============
__global__ __launch_bounds__(256) void k_mkw(const float* __restrict__ ne,
                                             const float* __restrict__ wp,
                                             __nv_bfloat16* __restrict__ whi,
                                             __nv_bfloat16* __restrict__ wlo,
                                             int IO) {
    int io = blockIdx.x * 256 + threadIdx.x;
    float wv[EE];
    #pragma unroll
    for (int d = 0; d < EE; d++) wv[d] = wp[(size_t)d * IO + io];
    __shared__ float sne[128 * EE];
    for (int n0 = 0; n0 < NN; n0 += 128) {
        __syncthreads();
        for (int t = threadIdx.x; t < 128 * EE; t += 256) sne[t] = ne[n0 * EE + t];
        __syncthreads();
        for (int nn = 0; nn < 128; nn++) {
            float v = 0.0f;
            #pragma unroll
            for (int d = 0; d < EE; d++) v += sne[nn * EE + d] * wv[d];
            __nv_bfloat16 h = __float2bfloat16(v);
            size_t o = (size_t)(n0 + nn) * IO + io;
            whi[o] = h;
            wlo[o] = __float2bfloat16(v - __bfloat162float(h));
        }
    }
}

// ================ transpose -> fp16 (hi only): B operand build ===================
__global__ __launch_bounds__(256) void k_trans(const float* __restrict__ src,
                                               __half* __restrict__ dhi,
                                               int zmul) {
    __shared__ float tile[64][68];
    int b = blockIdx.y, m0 = blockIdx.x * 64, tid = threadIdx.x;
    #pragma unroll
    for (int i = 0; i < 4; i++) {
        int id = i * 256 + tid;
        int r = id >> 4, c4 = id & 15;
        float4 v = *reinterpret_cast<const float4*>(
            src + ((size_t)b * NN + m0 + r) * 64 + c4 * 4);
        if (zmul) {
            float4 z = *reinterpret_cast<const float4*>(
                g_ZR + (size_t)(m0 + r) * XGPITCH + b * CC + c4 * 4);
            v.x *= z.x; v.y *= z.y; v.z *= z.z; v.w *= z.w;
        }
        *reinterpret_cast<float4*>(&tile[r][c4 * 4]) = v;
    }
    __syncthreads();
    int c = tid >> 2, mg = (tid & 3) * 16;
    uint32_t hi[8];
    #pragma unroll
    for (int p = 0; p < 8; p++) {
        float v0 = tile[mg + 2 * p][c], v1 = tile[mg + 2 * p + 1][c];
        __half2 hp = __floats2half2_rn(v0, v1);
        hi[p] = *reinterpret_cast<uint32_t*>(&hp);
    }
    size_t o = (size_t)(b * 64 + c) * NN + m0 + mg;
    *reinterpret_cast<uint4*>(dhi + o)     = make_uint4(hi[0], hi[1], hi[2], hi[3]);
    *reinterpret_cast<uint4*>(dhi + o + 8) = make_uint4(hi[4], hi[5], hi[6], hi[7]);
}

// ================ big GEMM via mma.sync fp16, single term ========================
// C = S_hi @ B_hi^T. CTA 128x128, K-chunk 32 (64B rows), 3-stage, 2 CTAs/SM.
#define OFF_B   8192
#define STAGE_BYTES 16384
#define GEMM_SMEM (3 * STAGE_BYTES)  // 48 KB

__device__ __forceinline__ uint32_t swz64(int r, int c) {
    return (uint32_t)(r * 64 + ((c ^ (r & 3) ^ ((r >> 2) & 1)) << 4));
}
__device__ __forceinline__ uint32_t swz256(int r, int c) {
    return (uint32_t)(r * 256 + ((c ^ (r & 7)) << 4));
}
__device__ __forceinline__ uint32_t swz128(int r, int c) {
    return (uint32_t)(r * 128 + ((c ^ (r & 7)) << 4));
}

__device__ __forceinline__ void load_stage(uint32_t base, int kt, int tid,
        const __half* Ah, const __half* Bh) {
    int k0 = kt * 32;
    #pragma unroll
    for (int i = 0; i < 2; i++) {
        int id = i * 256 + tid;
        int r = id >> 2, c = id & 3;
        uint32_t off = swz64(r, c);
        size_t g = (size_t)r * NN + k0 + c * 8;
        cpa16(base + off,         Ah + g);
        cpa16(base + OFF_B + off, Bh + g);
    }
    CP_COMMIT();
}

__global__ __launch_bounds__(256, 2) void k_hgemm(
        const __half* __restrict__ Bhi0,
        int coff0,
        const __half* __restrict__ Bhi1,
        int split) {
    extern __shared__ char dsm[];
    uint32_t sb = smem_u32(dsm);
    int tid = threadIdx.x, lane = tid & 31, wid = tid >> 5;
    int bn = blockIdx.x, bm = blockIdx.y;

    const __half* Bhp;
    int coff;
    if (bn < split) { Bhp = Bhi0; coff = coff0; }
    else            { Bhp = Bhi1; coff = 64; bn -= split; }

    const __half* Ah = g_Shi + (size_t)(bm * 128) * NN;
    const __half* Bh = Bhp + (size_t)(bn * 128) * NN;

    int warp_m = (wid >> 2) * 64;
    int warp_n = (wid & 3) * 32;
    float acc[4][4][4] = {};

    load_stage(sb, 0, tid, Ah, Bh);
    load_stage(sb + STAGE_BYTES, 1, tid, Ah, Bh);

    const int NKT = NN / 32;
    int lrowA = lane & 15, lgrp = lane >> 4;

    for (int kt = 0; kt < NKT; kt++) {
        CP_WAIT1();
        __syncthreads();

        if (kt + 2 < NKT)
            load_stage(sb + ((kt + 2) % 3) * STAGE_BYTES, kt + 2, tid, Ah, Bh);
        else
            CP_COMMIT();

        uint32_t base = sb + (kt % 3) * STAGE_BYTES;
        #pragma unroll
        for (int s = 0; s < 2; s++) {
            int cb = s * 2 + lgrp;
            uint32_t bh[4][2];
            #pragma unroll
            for (int ng = 0; ng < 2; ng++) {
                int r = warp_n + ng * 16 + lrowA;
                uint32_t off = swz64(r, cb);
                uint32_t t0, t1, t2, t3;
                LDSM4(t0, t1, t2, t3, base + OFF_B + off);
                bh[ng * 2][0] = t0; bh[ng * 2][1] = t2;
                bh[ng * 2 + 1][0] = t1; bh[ng * 2 + 1][1] = t3;
            }
            #pragma unroll
            for (int mt = 0; mt < 4; mt++) {
                int r = warp_m + mt * 16 + lrowA;
                uint32_t off = swz64(r, cb);
                uint32_t ahi[4];
                LDSM4(ahi[0], ahi[1], ahi[2], ahi[3], base + off);
                #pragma unroll
                for (int nt = 0; nt < 4; nt++)
                    MMA_F16(acc[mt][nt], ahi, bh[nt]);
            }
        }
    }

    // epilogue: write XG as bf16 hi/lo pairs (unchanged downstream format)
    int row0 = bm * 128 + warp_m + (lane >> 2);
    #pragma unroll
    for (int mt = 0; mt < 4; mt++) {
        #pragma unroll
        for (int nt = 0; nt < 4; nt++) {
            int j = bn * 128 + warp_n + nt * 8 + (lane & 3) * 2;
            int b = j >> 6, c = j & 63;
            size_t p0 = (size_t)(row0 + mt * 16) * XGPITCH + b * CC + coff + c;
            size_t p1 = p0 + (size_t)8 * XGPITCH;
            float a0 = acc[mt][nt][0], a1 = acc[mt][nt][1];
            float a2 = acc[mt][nt][2], a3 = acc[mt][nt][3];
            __nv_bfloat162 h01, l01, h23, l23;
            h01.x = __float2bfloat16(a0); h01.y = __float2bfloat16(a1);
            l01.x = __float2bfloat16(a0 - __bfloat162float(h01.x));
            l01.y = __float2bfloat16(a1 - __bfloat162float(h01.y));
            h23.x = __float2bfloat16(a2); h23.y = __float2bfloat16(a3);
            l23.x = __float2bfloat16(a2 - __bfloat162float(h23.x));
            l23.y = __float2bfloat16(a3 - __bfloat162float(h23.y));
            *reinterpret_cast<__nv_bfloat162*>(g_XGhi + p0) = h01;
            *reinterpret_cast<__nv_bfloat162*>(g_XGlo + p0) = l01;
            *reinterpret_cast<__nv_bfloat162*>(g_XGhi + p1) = h23;
            *reinterpret_cast<__nv_bfloat162*>(g_XGlo + p1) = l23;
        }
    }
}

// ================ per-node gate GEMM (tensorized, 256 thr) + sigmoid =============
// 8 warps: 2(M) x 4(N), warptile 32x32. X(64x128) @ W_n(128x128). bf16 3-term.
#define NG_XHI 0
#define NG_XLO 16384
#define NG_WHI 32768
#define NG_WLO 65536
#define NG_BIAS 98304
#define NG_SMEM 98816

__global__ __launch_bounds__(256, 2) void k_ngate(const float* __restrict__ ne,
                                                  const float* __restrict__ gbp) {
    extern __shared__ char dsm[];
    uint32_t sb = smem_u32(dsm);
    int n = blockIdx.x, tid = threadIdx.x, lane = tid & 31, wid = tid >> 5;

    #pragma unroll
    for (int i = 0; i < 4; i++) {
        int id = i * 256 + tid;
        int r = id >> 4, c = id & 15;
        uint32_t off = swz256(r, c);
        size_t g = (size_t)n * XGPITCH + r * 128 + c * 8;
        cpa16(sb + NG_XHI + off, g_XGhi + g);
        cpa16(sb + NG_XLO + off, g_XGlo + g);
    }
    #pragma unroll
    for (int i = 0; i < 8; i++) {
        int id = i * 256 + tid;
        int r = id >> 4, c = id & 15;
        uint32_t off = swz256(r, c);
        size_t g = (size_t)n * (CC * CC) + r * 128 + c * 8;
        cpa16(sb + NG_WHI + off, g_Wghi + g);
        cpa16(sb + NG_WLO + off, g_Wglo + g);
    }
    CP_COMMIT();

    if (tid < CC) {
        float v = 0.0f;
        #pragma unroll
        for (int d = 0; d < EE; d++) v += ne[n * EE + d] * gbp[d * CC + tid];
        reinterpret_cast<float*>(dsm + NG_BIAS)[tid] = v;
    }
    CP_WAIT0();
    __syncthreads();

    int warp_m = (wid >> 2) * 32;
    int warp_n = (wid & 3) * 32;
    int lrow = lane & 15, lgrp = lane >> 4;
    float acc[2][4][4] = {};

    #pragma unroll
    for (int k16 = 0; k16 < 8; k16++) {
        uint32_t bh[4][2], bl[4][2];
        #pragma unroll
        for (int half = 0; half < 2; half++) {
            uint32_t off = swz256(k16 * 16 + lrow, (warp_n >> 3) + half * 2 + lgrp);
            uint32_t t0, t1, t2, t3;
            LDSM4T(t0, t1, t2, t3, sb + NG_WHI + off);
            bh[half * 2][0] = t0; bh[half * 2][1] = t1;
            bh[half * 2 + 1][0] = t2; bh[half * 2 + 1][1] = t3;
            LDSM4T(t0, t1, t2, t3, sb + NG_WLO + off);
            bl[half * 2][0] = t0; bl[half * 2][1] = t1;
            bl[half * 2 + 1][0] = t2; bl[half * 2 + 1][1] = t3;
        }
        #pragma unroll
        for (int mt = 0; mt < 2; mt++) {
            uint32_t off = swz256(warp_m + mt * 16 + lrow, k16 * 2 + lgrp);
            uint32_t ah[4], al[4];
            LDSM4(ah[0], ah[1], ah[2], ah[3], sb + NG_XHI + off);
            LDSM4(al[0], al[1], al[2], al[3], sb + NG_XLO + off);
            #pragma unroll
            for (int nb = 0; nb < 4; nb++) {
                MMA_BF16(acc[mt][nb], ah, bh[nb]);
                MMA_BF16(acc[mt][nb], ah, bl[nb]);
                MMA_BF16(acc[mt][nb], al, bh[nb]);
            }
        }
    }

    const float* biasp = reinterpret_cast<const float*>(dsm + NG_BIAS);
    #pragma unroll
    for (int mt = 0; mt < 2; mt++) {
        #pragma unroll
        for (int nb = 0; nb < 4; nb++) {
            int o = warp_n + nb * 8 + (lane & 3) * 2;
            int b = warp_m + mt * 16 + (lane >> 2);
            float b0 = biasp[o], b1 = biasp[o + 1];
            float y0 = 1.0f / (1.0f + __expf(-(acc[mt][nb][0] + b0)));
            float y1 = 1.0f / (1.0f + __expf(-(acc[mt][nb][1] + b1)));
            float y2 = 1.0f / (1.0f + __expf(-(acc[mt][nb][2] + b0)));
            float y3 = 1.0f / (1.0f + __expf(-(acc[mt][nb][3] + b1)));
            *reinterpret_cast<float2*>(g_ZR + (size_t)n * XGPITCH + b * CC + o) =
                make_float2(y0, y1);
            *reinterpret_cast<float2*>(g_ZR + (size_t)n * XGPITCH + (b + 8) * CC + o) =
                make_float2(y2, y3);
        }
    }
}

// ================ per-node update GEMM (256 thr) + tanh + GRU combine ============
#define NF_XHI 0
#define NF_XLO 16384
#define NF_WHI 32768
#define NF_WLO 49152
#define NF_BIAS 65536
#define NF_SMEM 65792

__global__ __launch_bounds__(256, 3) void k_nfinal(const float* __restrict__ ne,
                                                   const float* __restrict__ ubp,
                                                   const float* __restrict__ st,
                                                   float* __restrict__ out) {
    extern __shared__ char dsm[];
    uint32_t sb = smem_u32(dsm);
    int n = blockIdx.x, tid = threadIdx.x, lane = tid & 31, wid = tid >> 5;

    #pragma unroll
    for (int i = 0; i < 4; i++) {
        int id = i * 256 + tid;
        int r = id >> 4, c = id & 15;
        uint32_t off = swz256(r, c);
        size_t g = (size_t)n * XGPITCH + r * 128 + c * 8;
        cpa16(sb + NF_XHI + off, g_XGhi + g);
        cpa16(sb + NF_XLO + off, g_XGlo + g);
    }
    #pragma unroll
    for (int i = 0; i < 4; i++) {
        int id = i * 256 + tid;
        int r = id >> 3, c = id & 7;
        uint32_t off = swz128(r, c);
        size_t g = (size_t)n * (CC * DH) + r * 64 + c * 8;
        cpa16(sb + NF_WHI + off, g_Wuhi + g);
        cpa16(sb + NF_WLO + off, g_Wulo + g);
    }
    CP_COMMIT();

    if (tid < DH) {
        float v = 0.0f;
        #pragma unroll
        for (int d = 0; d < EE; d++) v += ne[n * EE + d] * ubp[d * DH + tid];
        reinterpret_cast<float*>(dsm + NF_BIAS)[tid] = v;
    }
    CP_WAIT0();
    __syncthreads();

    int warp_m = (wid >> 2) * 32;
    int warp_n = (wid & 3) * 16;
    int lrow = lane & 15, lgrp = lane >> 4;
    float acc[2][2][4] = {};

    #pragma unroll
    for (int k16 = 0; k16 < 8; k16++) {
        uint32_t bh[2][2], bl[2][2];
        {
            uint32_t off = swz128(k16 * 16 + lrow, (warp_n >> 3) + lgrp);
            uint32_t t0, t1, t2, t3;
            LDSM4T(t0, t1, t2, t3, sb + NF_WHI + off);
            bh[0][0] = t0; bh[0][1] = t1;
            bh[1][0] = t2; bh[1][1] = t3;
            LDSM4T(t0, t1, t2, t3, sb + NF_WLO + off);
            bl[0][0] = t0; bl[0][1] = t1;
            bl[1][0] = t2; bl[1][1] = t3;
        }
        #pragma unroll
        for (int mt = 0; mt < 2; mt++) {
            uint32_t off = swz256(warp_m + mt * 16 + lrow, k16 * 2 + lgrp);
            uint32_t ah[4], al[4];
            LDSM4(ah[0], ah[1], ah[2], ah[3], sb + NF_XHI + off);
            LDSM4(al[0], al[1], al[2], al[3], sb + NF_XLO + off);
            #pragma unroll
            for (int nb = 0; nb < 2; nb++) {
                MMA_BF16(acc[mt][nb], ah, bh[nb]);
                MMA_BF16(acc[mt][nb], ah, bl[nb]);
                MMA_BF16(acc[mt][nb], al, bh[nb]);
            }
        }
    }

    const float* biasp = reinterpret_cast<const float*>(dsm + NF_BIAS);
    #pragma unroll
    for (int mt = 0; mt < 2; mt++) {
        #pragma unroll
        for (int nb = 0; nb < 2; nb++) {
            int o = warp_n + nb * 8 + (lane & 3) * 2;
            float b0 = biasp[o], b1 = biasp[o + 1];
            #pragma unroll
            for (int h = 0; h < 2; h++) {
                int b = warp_m + mt * 16 + (lane >> 2) + h * 8;
                float hc0 = tanhf(acc[mt][nb][h * 2] + b0);
                float hc1 = tanhf(acc[mt][nb][h * 2 + 1] + b1);
                float2 rr = *reinterpret_cast<const float2*>(
                    g_ZR + (size_t)n * XGPITCH + b * CC + DH + o);
                float2 ss = *reinterpret_cast<const float2*>(
                    st + ((size_t)b * NN + n) * DH + o);
                float2 hv;
                hv.x = rr.x * ss.x + (1.0f - rr.x) * hc0;
                hv.y = rr.y * ss.y + (1.0f - rr.y) * hc1;
                *reinterpret_cast<float2*>(out + ((size_t)b * NN + n) * DH + o) = hv;
            }
        }
    }
}

// ================ launch (multi-stream fork/join, capture-legal) =================
extern "C" void kernel_launch(void* const* d_in, const int* in_sizes, int n_in,
                              void* d_out, int out_size) {
    const float* x   = (const float*)d_in[0];
    const float* st  = (const float*)d_in[1];
    const float* ne  = (const float*)d_in[2];
    const float* gwp = (const float*)d_in[3];
    const float* gbp = (const float*)d_in[4];
    const float* uwp = (const float*)d_in[5];
    const float* ubp = (const float*)d_in[6];
    float* out = (float*)d_out;

    static cudaStream_t s1 = nullptr, s2 = nullptr;
    static cudaEvent_t e_fork, e_mkw, e_trans;
    static int initialized = 0;
    if (!initialized) {
        cudaFuncSetAttribute(k_hgemm,  cudaFuncAttributeMaxDynamicSharedMemorySize, GEMM_SMEM);
        cudaFuncSetAttribute(k_ngate,  cudaFuncAttributeMaxDynamicSharedMemorySize, NG_SMEM);
        cudaFuncSetAttribute(k_nfinal, cudaFuncAttributeMaxDynamicSharedMemorySize, NF_SMEM);
        cudaStreamCreateWithFlags(&s1, cudaStreamNonBlocking);
        cudaStreamCreateWithFlags(&s2, cudaStreamNonBlocking);
        cudaEventCreateWithFlags(&e_fork,  cudaEventDisableTiming);
        cudaEventCreateWithFlags(&e_mkw,   cudaEventDisableTiming);
        cudaEventCreateWithFlags(&e_trans, cudaEventDisableTiming);
        initialized = 1;
    }

    __half *bxh, *bsh;
    __nv_bfloat16 *wgh, *wgl, *wuh, *wul;
    cudaGetSymbolAddress((void**)&bxh, g_BXhi);
    cudaGetSymbolAddress((void**)&bsh, g_BShi);
    cudaGetSymbolAddress((void**)&wgh, g_Wghi);
    cudaGetSymbolAddress((void**)&wgl, g_Wglo);
    cudaGetSymbolAddress((void**)&wuh, g_Wuhi);
    cudaGetSymbolAddress((void**)&wul, g_Wulo);

    // fork from default stream
    cudaEventRecord(e_fork, 0);
    cudaStreamWaitEvent(s1, e_fork, 0);
    cudaStreamWaitEvent(s2, e_fork, 0);

    // s1: per-node weight materialization (needed by k_ngate, much later)
    k_mkw<<<(CC * CC) / 256, 256, 0, s1>>>(ne, gwp, wgh, wgl, CC * CC);
    k_mkw<<<(CC * DH) / 256, 256, 0, s1>>>(ne, uwp, wuh, wul, CC * DH);
    cudaEventRecord(e_mkw, s1);

    // s2: input transposes (needed by hgemm1), concurrent with k_supports
    k_trans<<<dim3(NN / 64, BB), 256, 0, s2>>>(x, bxh, 0);
    k_trans<<<dim3(NN / 64, BB), 256, 0, s2>>>(st, bsh, 0);
    cudaEventRecord(e_trans, s2);

    // default: supports, then join transposes before the merged GEMM
    k_supports<<<NN, 256>>>(ne);
    cudaStreamWaitEvent(0, e_trans, 0);

    // merged S@x | S@state : 2048 CTAs (6.92 waves)
    k_hgemm<<<dim3(2 * NN / 128, NN / 128), 256, GEMM_SMEM>>>(
        bxh, 0, bsh, NN / 128);

    // join weights before per-node gate GEMM
    cudaStreamWaitEvent(0, e_mkw, 0);
    k_ngate<<<NN, 256, NG_SMEM>>>(ne, gbp);

    // update path
    k_trans<<<dim3(NN / 64, BB), 256>>>(st, bsh, 1);        // (z*state)^T
    k_hgemm<<<dim3(NN / 128, NN / 128), 256, GEMM_SMEM>>>(
        bsh, 64, bsh, NN / 128);
    k_nfinal<<<NN, 256, NF_SMEM>>>(ne, ubp, st, out);
}